// round 8
// baseline (speedup 1.0000x reference)
#include <cuda_runtime.h>
#include <cstdint>
#include <math.h>

typedef unsigned long long ull;

__device__ __forceinline__ ull pack2(float lo, float hi) {
    ull r; asm("mov.b64 %0, {%1, %2};" : "=l"(r) : "f"(lo), "f"(hi)); return r;
}
__device__ __forceinline__ void unpack2(ull v, float& lo, float& hi) {
    asm("mov.b64 {%0, %1}, %2;" : "=f"(lo), "=f"(hi) : "l"(v));
}
__device__ __forceinline__ ull ffma2(ull a, ull b, ull c) {
    ull d; asm("fma.rn.f32x2 %0, %1, %2, %3;" : "=l"(d) : "l"(a), "l"(b), "l"(c)); return d;
}

static constexpr int B = 8, C = 128, T = 128, F = 512, K = 64;
static constexpr int FC = 128;     // F columns per CTA in main kernel
static constexpr int PXF = 128;    // pitch (floats) for 128-wide smem tiles
static constexpr int PXK = 68;     // pitch (floats) for 64-wide smem tiles (bank-skewed)

// scratch for k/v projections of the latent path: [b*T+t][c][k]
__device__ float g_kbuf[(size_t)B * T * C * K];
__device__ float g_vbuf[(size_t)B * T * C * K];

__device__ __forceinline__ float silu_f(float g) {
    float e = __expf(-g);
    return __fdividef(g, 1.0f + e);
}

// ===========================================================================
// 256-thread GEMM core for the latent kernel (unchanged from R4).
// ===========================================================================
template <int RT, int NP, int PX, int CH>
__device__ __forceinline__ void gemm_core(
    const float* __restrict__ Wglob,
    const float* __restrict__ Xin,
    ull* __restrict__ Wts,
    ull acc[RT][NP], int tid)
{
    const int tx = tid & 15, ty = tid >> 4;
    constexpr int R   = RT * 16;
    constexpr int PW2 = 2 * CH + 2;
    constexpr int C4  = CH / 4;
    constexpr int PT  = (R * C4) / 256;
    static_assert((R * C4) % 256 == 0, "staging divisibility");

    const int wbase = (ty >> 1) * PW2 + (ty & 1);

    float4 pf[PT];
    #pragma unroll
    for (int p = 0; p < PT; ++p) {
        int idx = tid + p * 256;
        int r = idx / C4, q = idx % C4;
        pf[p] = *reinterpret_cast<const float4*>(Wglob + r * 128 + q * 4);
    }

    for (int c0 = 0; c0 < 128; c0 += CH) {
        __syncthreads();
        #pragma unroll
        for (int p = 0; p < PT; ++p) {
            int idx = tid + p * 256;
            int r = idx / C4, q = idx % C4;
            ull* d = Wts + (r >> 1) * PW2 + (r & 1) + 2 * (q * 4);
            d[0] = pack2(pf[p].x, pf[p].x);
            d[2] = pack2(pf[p].y, pf[p].y);
            d[4] = pack2(pf[p].z, pf[p].z);
            d[6] = pack2(pf[p].w, pf[p].w);
        }
        __syncthreads();
        if (c0 + CH < 128) {
            #pragma unroll
            for (int p = 0; p < PT; ++p) {
                int idx = tid + p * 256;
                int r = idx / C4, q = idx % C4;
                pf[p] = *reinterpret_cast<const float4*>(Wglob + r * 128 + (c0 + CH) + q * 4);
            }
        }
        #pragma unroll 4
        for (int cc = 0; cc < CH; ++cc) {
            const float* xrow = Xin + (c0 + cc) * PX;
            ull xp[NP];
            #pragma unroll
            for (int jp = 0; jp < NP; ++jp)
                xp[jp] = *reinterpret_cast<const ull*>(xrow + 2 * (tx + 16 * jp));
            #pragma unroll
            for (int i = 0; i < RT; ++i) {
                ull wp = Wts[wbase + i * (8 * PW2) + 2 * cc];
                #pragma unroll
                for (int jp = 0; jp < NP; ++jp)
                    acc[i][jp] = ffma2(wp, xp[jp], acc[i][jp]);
            }
        }
    }
}

// ---------------------------------------------------------------------------
// Kernel 1: latent path (unchanged). One CTA per (b,t) frame, 2 CTAs/SM.
// ---------------------------------------------------------------------------
static constexpr int K1_XL = 0;
static constexpr int K1_LH = 128 * PXK;
static constexpr int K1_WT = K1_LH + 128 * PXK;
static constexpr int K1_WT_ULL = 64 * 34;
static constexpr int K1_RS = K1_WT + 2 * K1_WT_ULL;
static constexpr int K1_SMEM_BYTES = (K1_RS + 64) * 4;

__global__ void __launch_bounds__(256, 2) latent_kernel(
    const float* __restrict__ latent, const float* __restrict__ lp_gamma,
    const float* __restrict__ lp_w,   const float* __restrict__ lp_b,
    const float* __restrict__ k_w,    const float* __restrict__ k_b,
    const float* __restrict__ v_w,    const float* __restrict__ v_b)
{
    extern __shared__ float sm[];
    float* Xl  = sm + K1_XL;
    float* Lh  = sm + K1_LH;
    ull*   Wts = reinterpret_cast<ull*>(sm + K1_WT);
    float* rstd = sm + K1_RS;
    const int tid = threadIdx.x;
    const int frame = blockIdx.x;
    const int b = frame / T, t = frame % T;
    const int tx = tid & 15, ty = tid >> 4;

    const float* src = latent + ((size_t)b * C * T + t) * K;
    #pragma unroll
    for (int idx = tid; idx < 128 * 16; idx += 256) {
        int r = idx >> 4, q = idx & 15;
        float4 v = *reinterpret_cast<const float4*>(src + (size_t)r * (T * K) + q * 4);
        *reinterpret_cast<float4*>(Xl + r * PXK + q * 4) = v;
    }
    __syncthreads();
    if (tid < 64) {
        float s0 = 0, s1 = 0, s2 = 0, s3 = 0;
        for (int c = 0; c < 128; c += 4) {
            float a = Xl[c * PXK + tid], bb = Xl[(c + 1) * PXK + tid];
            float cc = Xl[(c + 2) * PXK + tid], dd = Xl[(c + 3) * PXK + tid];
            s0 += a * a; s1 += bb * bb; s2 += cc * cc; s3 += dd * dd;
        }
        rstd[tid] = rsqrtf((s0 + s1 + s2 + s3) * (1.0f / 128.0f) + 1e-6f);
    }
    __syncthreads();
    #pragma unroll
    for (int idx = tid; idx < 128 * 16; idx += 256) {
        int r = idx >> 4, q = idx & 15;
        float g = lp_gamma[r];
        float* d = Xl + r * PXK + q * 4;
        d[0] *= rstd[q * 4 + 0] * g; d[1] *= rstd[q * 4 + 1] * g;
        d[2] *= rstd[q * 4 + 2] * g; d[3] *= rstd[q * 4 + 3] * g;
    }

    {
        ull acc[8][2] = {};
        gemm_core<8, 2, PXK, 16>(lp_w, Xl, Wts, acc, tid);
        #pragma unroll
        for (int i = 0; i < 8; ++i) {
            int r = ty + 16 * i;
            float bias = lp_b[r];
            #pragma unroll
            for (int jp = 0; jp < 2; ++jp) {
                float lo, hi; unpack2(acc[i][jp], lo, hi);
                int fl = 2 * (tx + 16 * jp);
                Lh[r * PXK + fl]     = silu_f(lo + bias);
                Lh[r * PXK + fl + 1] = silu_f(hi + bias);
            }
        }
    }
    {
        ull acc[8][2] = {};
        gemm_core<8, 2, PXK, 16>(k_w, Lh, Wts, acc, tid);
        float* dst = g_kbuf + (size_t)frame * (C * K);
        #pragma unroll
        for (int i = 0; i < 8; ++i) {
            int r = ty + 16 * i;
            float bias = k_b[r];
            #pragma unroll
            for (int jp = 0; jp < 2; ++jp) {
                float lo, hi; unpack2(acc[i][jp], lo, hi);
                int fl = 2 * (tx + 16 * jp);
                *reinterpret_cast<float2*>(dst + r * K + fl) = make_float2(lo + bias, hi + bias);
            }
        }
    }
    {
        ull acc[8][2] = {};
        gemm_core<8, 2, PXK, 16>(v_w, Lh, Wts, acc, tid);
        float* dst = g_vbuf + (size_t)frame * (C * K);
        #pragma unroll
        for (int i = 0; i < 8; ++i) {
            int r = ty + 16 * i;
            float bias = v_b[r];
            #pragma unroll
            for (int jp = 0; jp < 2; ++jp) {
                float lo, hi; unpack2(acc[i][jp], lo, hi);
                int fl = 2 * (tx + 16 * jp);
                *reinterpret_cast<float2*>(dst + r * K + fl) = make_float2(lo + bias, hi + bias);
            }
        }
    }
}

// ===========================================================================
// 512-thread GEMM core for the main kernel.
// tx = tid&15 owns float-quads [4tx .. 4tx+3] and [4tx+64 .. 4tx+67].
// ty = tid>>4 (0..31) owns rows r = ty + 32*i, i<4. Warp = ty pair {2w,2w+1}.
// Weights staged per-parity as duplicated (w,w) pairs; inner-loop w fetch is
// ONE LDS.128 giving (w_cc, w_cc+1), 2 distinct addrs/warp (different bank
// quads via +4-ull parity offset) = 1 wavefront. X fetch = LDS.128 float4s.
// Per warp per cc: 4 LDS instr / 6 wavefronts / 16 FFMA2.
// ===========================================================================
static constexpr int CH5 = 16;
static constexpr int WPAR = 64 * CH5 + 4;    // parity-array stride in ull

__device__ __forceinline__ void gemm512(
    const float* __restrict__ Wglob,   // [128][128] row-major
    const float* __restrict__ Xin,     // smem tile, pitch PXF
    ull* __restrict__ Wts,             // 2*WPAR ull
    ull acc[4][4], int tid)
{
    const int tx = tid & 15, ty = tid >> 4;
    const int wbase = (ty & 1) * WPAR + (ty >> 1) * (4 * CH5);

    // staging map: 512 threads, 128 rows x 4 float4
    const int sr = tid >> 2, sq = tid & 3;
    const int wslot = (sr & 1) * WPAR + (((sr & 31) >> 1) * 4 + (sr >> 5)) * CH5 + sq * 4;

    float4 pf = *reinterpret_cast<const float4*>(Wglob + sr * 128 + sq * 4);

    for (int c0 = 0; c0 < 128; c0 += CH5) {
        __syncthreads();
        {
            ulonglong2 w01, w23;
            w01.x = pack2(pf.x, pf.x); w01.y = pack2(pf.y, pf.y);
            w23.x = pack2(pf.z, pf.z); w23.y = pack2(pf.w, pf.w);
            *reinterpret_cast<ulonglong2*>(Wts + wslot)     = w01;
            *reinterpret_cast<ulonglong2*>(Wts + wslot + 2) = w23;
        }
        __syncthreads();
        if (c0 + CH5 < 128)
            pf = *reinterpret_cast<const float4*>(Wglob + sr * 128 + (c0 + CH5) + sq * 4);

        #pragma unroll 2
        for (int cc2 = 0; cc2 < CH5; cc2 += 2) {
            ulonglong2 wv[4];
            #pragma unroll
            for (int i = 0; i < 4; ++i)
                wv[i] = *reinterpret_cast<const ulonglong2*>(Wts + wbase + i * CH5 + cc2);
            #pragma unroll
            for (int h = 0; h < 2; ++h) {
                const float* xrow = Xin + (c0 + cc2 + h) * PXF + 4 * tx;
                ulonglong2 x0 = *reinterpret_cast<const ulonglong2*>(xrow);
                ulonglong2 x1 = *reinterpret_cast<const ulonglong2*>(xrow + 64);
                #pragma unroll
                for (int i = 0; i < 4; ++i) {
                    ull w = h ? wv[i].y : wv[i].x;
                    acc[i][0] = ffma2(w, x0.x, acc[i][0]);
                    acc[i][1] = ffma2(w, x0.y, acc[i][1]);
                    acc[i][2] = ffma2(w, x1.x, acc[i][2]);
                    acc[i][3] = ffma2(w, x1.y, acc[i][3]);
                }
            }
        }
    }
}

// ---------------------------------------------------------------------------
// Kernel 2: fused side path + attention + FFN. 512 threads, 1 CTA/SM.
// ---------------------------------------------------------------------------
static constexpr int K2_XS = 0;
static constexpr int K2_HS = 128 * PXF;                 // 16384
static constexpr int K2_KS = K2_HS + 128 * PXF;         // 32768
static constexpr int K2_VS = K2_KS + 128 * PXK;         // 41472
static constexpr int K2_WT = K2_VS + 128 * PXK;         // 50176 (16B aligned)
static constexpr int K2_RS = K2_WT + 2 * (2 * WPAR);    // + 4112 floats
static constexpr int K2_SMEM_BYTES = (K2_RS + 128) * 4; // 217,664 B

__global__ void __launch_bounds__(512, 1) main_kernel(
    const float* __restrict__ side,      const float* __restrict__ basis,
    const float* __restrict__ qn_gamma,
    const float* __restrict__ qmlp_in_w, const float* __restrict__ qmlp_in_b,
    const float* __restrict__ qmlp_out_w,const float* __restrict__ qmlp_out_b,
    const float* __restrict__ q_w,       const float* __restrict__ q_b,
    const float* __restrict__ o_w,       const float* __restrict__ o_b,
    const float* __restrict__ ffn_gamma,
    const float* __restrict__ ffn_in_w,  const float* __restrict__ ffn_in_b,
    const float* __restrict__ ffn_out_w, const float* __restrict__ ffn_out_b,
    const float* __restrict__ score_scale, const float* __restrict__ prior_scale,
    const float* __restrict__ query_skip_scale,
    float* __restrict__ out)
{
    extern __shared__ float sm[];
    float* Xs  = sm + K2_XS;
    float* Hs  = sm + K2_HS;
    float* Ks  = sm + K2_KS;
    float* Vs  = sm + K2_VS;
    ull*   Wts = reinterpret_cast<ull*>(sm + K2_WT);
    float* rstd = sm + K2_RS;

    const int tid = threadIdx.x;
    const int fc = blockIdx.x;      // 0..3
    const int t  = blockIdx.y;
    const int b  = blockIdx.z;
    const int f0 = fc * FC;
    const int tx = tid & 15, ty = tid >> 4;   // ty 0..31
    const int frame = b * T + t;

    // ---- load k/v frame into smem (pitch 64 -> 68) ----
    {
        const float* ksrc = g_kbuf + (size_t)frame * (C * K);
        const float* vsrc = g_vbuf + (size_t)frame * (C * K);
        #pragma unroll
        for (int idx = tid; idx < 128 * 16; idx += 512) {
            int r = idx >> 4, q = idx & 15;
            float4 kv = *reinterpret_cast<const float4*>(ksrc + r * K + q * 4);
            float4 vv = *reinterpret_cast<const float4*>(vsrc + r * K + q * 4);
            *reinterpret_cast<float4*>(Ks + r * PXK + q * 4) = kv;
            *reinterpret_cast<float4*>(Vs + r * PXK + q * 4) = vv;
        }
    }
    // ---- load side chunk [128][128] ----
    const float* sbase = side + ((size_t)b * C * T + t) * F + f0;
    #pragma unroll
    for (int idx = tid; idx < 128 * 32; idx += 512) {
        int r = idx >> 5, q = idx & 31;
        float4 v = *reinterpret_cast<const float4*>(sbase + (size_t)r * (T * F) + q * 4);
        *reinterpret_cast<float4*>(Xs + r * PXF + q * 4) = v;
    }
    __syncthreads();
    // ---- rmsnorm (axis C) ----
    if (tid < 128) {
        float s0 = 0, s1 = 0, s2 = 0, s3 = 0;
        for (int c = 0; c < 128; c += 4) {
            float a = Xs[c * PXF + tid], bb = Xs[(c + 1) * PXF + tid];
            float cc = Xs[(c + 2) * PXF + tid], dd = Xs[(c + 3) * PXF + tid];
            s0 += a * a; s1 += bb * bb; s2 += cc * cc; s3 += dd * dd;
        }
        rstd[tid] = rsqrtf((s0 + s1 + s2 + s3) * (1.0f / 128.0f) + 1e-6f);
    }
    __syncthreads();
    #pragma unroll
    for (int idx = tid; idx < 128 * 32; idx += 512) {
        int r = idx >> 5, q = idx & 31;
        float g = qn_gamma[r];
        float* d = Xs + r * PXF + q * 4;
        d[0] *= rstd[q * 4 + 0] * g; d[1] *= rstd[q * 4 + 1] * g;
        d[2] *= rstd[q * 4 + 2] * g; d[3] *= rstd[q * 4 + 3] * g;
    }

    // epilogue helper ---------------------------------------------------------
    auto acc_to_f4 = [](ull a0, ull a1, float bias) {
        float4 v;
        unpack2(a0, v.x, v.y); unpack2(a1, v.z, v.w);
        v.x += bias; v.y += bias; v.z += bias; v.w += bias;
        return v;
    };

    // ---- GEMM1: qmlp_in (gated, two 128-row passes) -> m in Hs ----
    {   // pass 1: gate rows -> silu(g) into Hs
        ull acc[4][4] = {};
        gemm512(qmlp_in_w + 128 * 128, Xs, Wts, acc, tid);
        #pragma unroll
        for (int i = 0; i < 4; ++i) {
            int r = ty + 32 * i;
            float bg = qmlp_in_b[r + 128];
            float4 va = acc_to_f4(acc[i][0], acc[i][1], bg);
            float4 vb = acc_to_f4(acc[i][2], acc[i][3], bg);
            va.x = silu_f(va.x); va.y = silu_f(va.y); va.z = silu_f(va.z); va.w = silu_f(va.w);
            vb.x = silu_f(vb.x); vb.y = silu_f(vb.y); vb.z = silu_f(vb.z); vb.w = silu_f(vb.w);
            *reinterpret_cast<float4*>(Hs + r * PXF + 4 * tx)      = va;
            *reinterpret_cast<float4*>(Hs + r * PXF + 4 * tx + 64) = vb;
        }
    }
    {   // pass 2: a rows; m = (a+b) * silu(g)
        ull acc[4][4] = {};
        gemm512(qmlp_in_w, Xs, Wts, acc, tid);
        #pragma unroll
        for (int i = 0; i < 4; ++i) {
            int r = ty + 32 * i;
            float ba = qmlp_in_b[r];
            float4 va = acc_to_f4(acc[i][0], acc[i][1], ba);
            float4 vb = acc_to_f4(acc[i][2], acc[i][3], ba);
            float4 g0 = *reinterpret_cast<float4*>(Hs + r * PXF + 4 * tx);
            float4 g1 = *reinterpret_cast<float4*>(Hs + r * PXF + 4 * tx + 64);
            g0.x *= va.x; g0.y *= va.y; g0.z *= va.z; g0.w *= va.w;
            g1.x *= vb.x; g1.y *= vb.y; g1.z *= vb.z; g1.w *= vb.w;
            *reinterpret_cast<float4*>(Hs + r * PXF + 4 * tx)      = g0;
            *reinterpret_cast<float4*>(Hs + r * PXF + 4 * tx + 64) = g1;
        }
    }
    // ---- GEMM2: qmlp_out -> query_h in Xs ----
    {
        ull acc[4][4] = {};
        gemm512(qmlp_out_w, Hs, Wts, acc, tid);
        #pragma unroll
        for (int i = 0; i < 4; ++i) {
            int r = ty + 32 * i;
            float bias = qmlp_out_b[r];
            *reinterpret_cast<float4*>(Xs + r * PXF + 4 * tx)      = acc_to_f4(acc[i][0], acc[i][1], bias);
            *reinterpret_cast<float4*>(Xs + r * PXF + 4 * tx + 64) = acc_to_f4(acc[i][2], acc[i][3], bias);
        }
    }
    // ---- GEMM3: q projection -> Hs ----
    {
        ull acc[4][4] = {};
        gemm512(q_w, Xs, Wts, acc, tid);
        #pragma unroll
        for (int i = 0; i < 4; ++i) {
            int r = ty + 32 * i;
            float bias = q_b[r];
            *reinterpret_cast<float4*>(Hs + r * PXF + 4 * tx)      = acc_to_f4(acc[i][0], acc[i][1], bias);
            *reinterpret_cast<float4*>(Hs + r * PXF + 4 * tx + 64) = acc_to_f4(acc[i][2], acc[i][3], bias);
        }
    }
    __syncthreads();   // q fully in Hs before scores

    // ---- scores [f][k] + softmax over k. 512 threads: 2 f x 8 k each ----
    const int kg = tid & 7, fg = tid >> 3;    // fg 0..63
    float wgt[2][8];
    {
        ull sacc[2][4] = {};
        #pragma unroll 4
        for (int c = 0; c < 128; ++c) {
            float2 qv = *reinterpret_cast<const float2*>(Hs + c * PXF + 2 * fg);
            const ulonglong2* kr = reinterpret_cast<const ulonglong2*>(Ks + c * PXK + kg * 8);
            ulonglong2 k0 = kr[0], k1 = kr[1];
            ull qp0 = pack2(qv.x, qv.x), qp1 = pack2(qv.y, qv.y);
            sacc[0][0] = ffma2(qp0, k0.x, sacc[0][0]);
            sacc[0][1] = ffma2(qp0, k0.y, sacc[0][1]);
            sacc[0][2] = ffma2(qp0, k1.x, sacc[0][2]);
            sacc[0][3] = ffma2(qp0, k1.y, sacc[0][3]);
            sacc[1][0] = ffma2(qp1, k0.x, sacc[1][0]);
            sacc[1][1] = ffma2(qp1, k0.y, sacc[1][1]);
            sacc[1][2] = ffma2(qp1, k1.x, sacc[1][2]);
            sacc[1][3] = ffma2(qp1, k1.y, sacc[1][3]);
        }
        const float ssc = *score_scale, psc = *prior_scale;
        #pragma unroll
        for (int i = 0; i < 2; ++i) {
            float s[8];
            #pragma unroll
            for (int jp = 0; jp < 4; ++jp) unpack2(sacc[i][jp], s[2 * jp], s[2 * jp + 1]);
            int fglob = f0 + 2 * fg + i;
            #pragma unroll
            for (int j = 0; j < 8; ++j)
                s[j] = s[j] * ssc + basis[(kg * 8 + j) * F + fglob] * psc;
            float m = s[0];
            #pragma unroll
            for (int j = 1; j < 8; ++j) m = fmaxf(m, s[j]);
            #pragma unroll
            for (int d = 1; d < 8; d <<= 1) m = fmaxf(m, __shfl_xor_sync(0xffffffffu, m, d));
            float sum = 0;
            #pragma unroll
            for (int j = 0; j < 8; ++j) { float e = __expf(s[j] - m); wgt[i][j] = e; sum += e; }
            #pragma unroll
            for (int d = 1; d < 8; d <<= 1) sum += __shfl_xor_sync(0xffffffffu, sum, d);
            float inv = __frcp_rn(sum);
            #pragma unroll
            for (int j = 0; j < 8; ++j) wgt[i][j] *= inv;
        }
    }
    __syncthreads();   // all reads of Ks + q reads of Hs done
    {   // store weights transposed into the dead Ks region: Ws[k][f], pitch PXF
        float* Ws = Ks;
        #pragma unroll
        for (int j = 0; j < 8; ++j)
            *reinterpret_cast<float2*>(Ws + (kg * 8 + j) * PXF + 2 * fg) =
                make_float2(wgt[0][j], wgt[1][j]);
    }
    __syncthreads();
    // ---- attended[c][f] = sum_k Ws[k][f] * Vs[c][k] -> Hs ----
    {
        ull acc[4][4] = {};
        const float* Ws = Ks;
        #pragma unroll 4
        for (int kk = 0; kk < 64; ++kk) {
            const float* wsrow = Ws + kk * PXF + 4 * tx;
            ulonglong2 x0 = *reinterpret_cast<const ulonglong2*>(wsrow);
            ulonglong2 x1 = *reinterpret_cast<const ulonglong2*>(wsrow + 64);
            #pragma unroll
            for (int i = 0; i < 4; ++i) {
                float v = Vs[(ty + 32 * i) * PXK + kk];
                ull vp = pack2(v, v);
                acc[i][0] = ffma2(vp, x0.x, acc[i][0]);
                acc[i][1] = ffma2(vp, x0.y, acc[i][1]);
                acc[i][2] = ffma2(vp, x1.x, acc[i][2]);
                acc[i][3] = ffma2(vp, x1.y, acc[i][3]);
            }
        }
        #pragma unroll
        for (int i = 0; i < 4; ++i) {
            int r = ty + 32 * i;
            *reinterpret_cast<float4*>(Hs + r * PXF + 4 * tx)      = acc_to_f4(acc[i][0], acc[i][1], 0.0f);
            *reinterpret_cast<float4*>(Hs + r * PXF + 4 * tx + 64) = acc_to_f4(acc[i][2], acc[i][3], 0.0f);
        }
    }
    // ---- GEMM4: hidden = o_w @ attended + o_b + qss*query_h -> Xs (in place) ----
    {
        ull acc[4][4] = {};
        gemm512(o_w, Hs, Wts, acc, tid);
        const float qs = *query_skip_scale;
        #pragma unroll
        for (int i = 0; i < 4; ++i) {
            int r = ty + 32 * i;
            float bias = o_b[r];
            float4 va = acc_to_f4(acc[i][0], acc[i][1], bias);
            float4 vb = acc_to_f4(acc[i][2], acc[i][3], bias);
            float4 qa = *reinterpret_cast<float4*>(Xs + r * PXF + 4 * tx);
            float4 qb = *reinterpret_cast<float4*>(Xs + r * PXF + 4 * tx + 64);
            va.x += qs * qa.x; va.y += qs * qa.y; va.z += qs * qa.z; va.w += qs * qa.w;
            vb.x += qs * qb.x; vb.y += qs * qb.y; vb.z += qs * qb.z; vb.w += qs * qb.w;
            *reinterpret_cast<float4*>(Xs + r * PXF + 4 * tx)      = va;
            *reinterpret_cast<float4*>(Xs + r * PXF + 4 * tx + 64) = vb;
        }
    }
    __syncthreads();
    // ---- FFN rmsnorm: Hs = rmsnorm(Xs)*ffn_gamma ----
    if (tid < 128) {
        float s0 = 0, s1 = 0, s2 = 0, s3 = 0;
        for (int c = 0; c < 128; c += 4) {
            float a = Xs[c * PXF + tid], bb = Xs[(c + 1) * PXF + tid];
            float cc = Xs[(c + 2) * PXF + tid], dd = Xs[(c + 3) * PXF + tid];
            s0 += a * a; s1 += bb * bb; s2 += cc * cc; s3 += dd * dd;
        }
        rstd[tid] = rsqrtf((s0 + s1 + s2 + s3) * (1.0f / 128.0f) + 1e-6f);
    }
    __syncthreads();
    #pragma unroll
    for (int idx = tid; idx < 128 * 32; idx += 512) {
        int r = idx >> 5, q = idx & 31;
        float g = ffn_gamma[r];
        const float* s = Xs + r * PXF + q * 4;
        float* d = Hs + r * PXF + q * 4;
        d[0] = s[0] * rstd[q * 4 + 0] * g; d[1] = s[1] * rstd[q * 4 + 1] * g;
        d[2] = s[2] * rstd[q * 4 + 2] * g; d[3] = s[3] * rstd[q * 4 + 3] * g;
    }
    // ---- GEMM5: ffn_in (gated, two passes), intermediate Gb = dead Ks+Vs ----
    float* Gb = Ks;
    {   // pass 1: gate rows -> silu into Gb
        ull acc[4][4] = {};
        gemm512(ffn_in_w + 128 * 128, Hs, Wts, acc, tid);
        #pragma unroll
        for (int i = 0; i < 4; ++i) {
            int r = ty + 32 * i;
            float bg = ffn_in_b[r + 128];
            float4 va = acc_to_f4(acc[i][0], acc[i][1], bg);
            float4 vb = acc_to_f4(acc[i][2], acc[i][3], bg);
            va.x = silu_f(va.x); va.y = silu_f(va.y); va.z = silu_f(va.z); va.w = silu_f(va.w);
            vb.x = silu_f(vb.x); vb.y = silu_f(vb.y); vb.z = silu_f(vb.z); vb.w = silu_f(vb.w);
            *reinterpret_cast<float4*>(Gb + r * PXF + 4 * tx)      = va;
            *reinterpret_cast<float4*>(Gb + r * PXF + 4 * tx + 64) = vb;
        }
    }
    {   // pass 2: a rows; m2 = (a+b)*silu(g) into Gb
        ull acc[4][4] = {};
        gemm512(ffn_in_w, Hs, Wts, acc, tid);
        #pragma unroll
        for (int i = 0; i < 4; ++i) {
            int r = ty + 32 * i;
            float ba = ffn_in_b[r];
            float4 va = acc_to_f4(acc[i][0], acc[i][1], ba);
            float4 vb = acc_to_f4(acc[i][2], acc[i][3], ba);
            float4 g0 = *reinterpret_cast<float4*>(Gb + r * PXF + 4 * tx);
            float4 g1 = *reinterpret_cast<float4*>(Gb + r * PXF + 4 * tx + 64);
            g0.x *= va.x; g0.y *= va.y; g0.z *= va.z; g0.w *= va.w;
            g1.x *= vb.x; g1.y *= vb.y; g1.z *= vb.z; g1.w *= vb.w;
            *reinterpret_cast<float4*>(Gb + r * PXF + 4 * tx)      = g0;
            *reinterpret_cast<float4*>(Gb + r * PXF + 4 * tx + 64) = g1;
        }
    }
    // ---- GEMM6: out = ffn_out @ m2 + ffn_out_b + hidden -> global ----
    {
        ull acc[4][4] = {};
        gemm512(ffn_out_w, Gb, Wts, acc, tid);
        float* obase = out + ((size_t)b * C * T + t) * F + f0;
        #pragma unroll
        for (int i = 0; i < 4; ++i) {
            int r = ty + 32 * i;
            float bias = ffn_out_b[r];
            float4 va = acc_to_f4(acc[i][0], acc[i][1], bias);
            float4 vb = acc_to_f4(acc[i][2], acc[i][3], bias);
            float4 ha = *reinterpret_cast<float4*>(Xs + r * PXF + 4 * tx);
            float4 hb = *reinterpret_cast<float4*>(Xs + r * PXF + 4 * tx + 64);
            va.x += ha.x; va.y += ha.y; va.z += ha.z; va.w += ha.w;
            vb.x += hb.x; vb.y += hb.y; vb.z += hb.z; vb.w += hb.w;
            *reinterpret_cast<float4*>(obase + (size_t)r * (T * F) + 4 * tx)      = va;
            *reinterpret_cast<float4*>(obase + (size_t)r * (T * F) + 4 * tx + 64) = vb;
        }
    }
}

// ---------------------------------------------------------------------------
extern "C" void kernel_launch(void* const* d_in, const int* in_sizes, int n_in,
                              void* d_out, int out_size)
{
    const float* latent      = (const float*)d_in[0];
    const float* side        = (const float*)d_in[1];
    const float* basis       = (const float*)d_in[2];
    const float* lp_gamma    = (const float*)d_in[3];
    const float* lp_w        = (const float*)d_in[4];
    const float* lp_b        = (const float*)d_in[5];
    const float* qn_gamma    = (const float*)d_in[6];
    const float* qmlp_in_w   = (const float*)d_in[7];
    const float* qmlp_in_b   = (const float*)d_in[8];
    const float* qmlp_out_w  = (const float*)d_in[9];
    const float* qmlp_out_b  = (const float*)d_in[10];
    const float* q_w         = (const float*)d_in[11];
    const float* q_b         = (const float*)d_in[12];
    const float* k_w         = (const float*)d_in[13];
    const float* k_b         = (const float*)d_in[14];
    const float* v_w         = (const float*)d_in[15];
    const float* v_b         = (const float*)d_in[16];
    const float* o_w         = (const float*)d_in[17];
    const float* o_b         = (const float*)d_in[18];
    const float* ffn_gamma   = (const float*)d_in[19];
    const float* ffn_in_w    = (const float*)d_in[20];
    const float* ffn_in_b    = (const float*)d_in[21];
    const float* ffn_out_w   = (const float*)d_in[22];
    const float* ffn_out_b   = (const float*)d_in[23];
    const float* score_scale = (const float*)d_in[24];
    const float* prior_scale = (const float*)d_in[25];
    const float* qss         = (const float*)d_in[26];
    float* out = (float*)d_out;

    cudaFuncSetAttribute(latent_kernel, cudaFuncAttributeMaxDynamicSharedMemorySize, K1_SMEM_BYTES);
    cudaFuncSetAttribute(main_kernel,   cudaFuncAttributeMaxDynamicSharedMemorySize, K2_SMEM_BYTES);

    latent_kernel<<<B * T, 256, K1_SMEM_BYTES>>>(
        latent, lp_gamma, lp_w, lp_b, k_w, k_b, v_w, v_b);

    main_kernel<<<dim3(F / FC, T, B), 512, K2_SMEM_BYTES>>>(
        side, basis, qn_gamma,
        qmlp_in_w, qmlp_in_b, qmlp_out_w, qmlp_out_b,
        q_w, q_b, o_w, o_b,
        ffn_gamma, ffn_in_w, ffn_in_b, ffn_out_w, ffn_out_b,
        score_scale, prior_scale, qss, out);
}

// round 10
// speedup vs baseline: 1.8695x; 1.8695x over previous
#include <cuda_runtime.h>
#include <cuda_bf16.h>
#include <cstdint>
#include <math.h>

typedef unsigned long long ull;

static constexpr int B = 8, C = 128, T = 128, F = 512, K = 64;
static constexpr int PXK = 68;

__device__ float g_kbuf[(size_t)B * T * C * K];   // [frame][kidx][c]  (transposed)
__device__ float g_vbuf[(size_t)B * T * C * K];   // [frame][c][kidx]

__device__ __forceinline__ float silu_f(float g) {
    float e = __expf(-g);
    return __fdividef(g, 1.0f + e);
}
__device__ __forceinline__ uint32_t smem_to_u32(const void* p) {
    uint32_t a;
    asm("{ .reg .u64 t; cvta.to.shared.u64 t, %1; cvt.u32.u64 %0, t; }" : "=r"(a) : "l"(p));
    return a;
}
__device__ __forceinline__ void ldsm4(uint32_t* r, uint32_t addr) {
    asm volatile("ldmatrix.sync.aligned.m8n8.x4.shared.b16 {%0,%1,%2,%3}, [%4];"
        : "=r"(r[0]), "=r"(r[1]), "=r"(r[2]), "=r"(r[3]) : "r"(addr));
}
__device__ __forceinline__ void mma16816(float* d, const uint32_t* a, const uint32_t* b) {
    asm volatile("mma.sync.aligned.m16n8k16.row.col.f32.bf16.bf16.f32 "
        "{%0,%1,%2,%3},{%4,%5,%6,%7},{%8,%9},{%0,%1,%2,%3};"
        : "+f"(d[0]), "+f"(d[1]), "+f"(d[2]), "+f"(d[3])
        : "r"(a[0]), "r"(a[1]), "r"(a[2]), "r"(a[3]), "r"(b[0]), "r"(b[1]));
}
__device__ __forceinline__ float bfh_f(float x) { return __bfloat162float(__float2bfloat16(x)); }
__device__ __forceinline__ uint32_t bf2(float lo, float hi) {
    uint32_t r;
    asm("cvt.rn.satfinite.bf16x2.f32 %0, %1, %2;" : "=r"(r) : "f"(hi), "f"(lo));
    return r;
}

// pitches (bytes)
static constexpr int PA = 272;   // 136 bf16
static constexpr int PV = 144;   // 72 bf16
// smem layout (bytes)
static constexpr int SRED = 0;        // 2048
static constexpr int SA_H = 2048;
static constexpr int SA_L = SA_H + 34816;     // 36864
static constexpr int SW_H = SA_L + 34816;     // 71680
static constexpr int SW_L = SW_H + 34816;     // 106496
static constexpr int SK_H = SW_L + 34816;     // 141312
static constexpr int SK_L = SK_H + 17408;     // 158720
static constexpr int SV_H = SK_L + 17408;     // 176128
static constexpr int SV_L = SV_H + 18432;     // 194560
static constexpr int K2_SMEM_BYTES = SV_L + 18432;   // 212992
static constexpr int SPARK = SK_H;   // fp32 [128][132] overlay (K/V dead by then)

// stage fp32 [nrows][128] -> bf16 hi/lo, pitch 272B
__device__ __forceinline__ void stageW(const float* __restrict__ src, char* wh, char* wl,
                                       int tid, int nrows) {
    for (int i = tid; i < nrows * 32; i += 256) {
        int r = i >> 5, c4 = (i & 31) << 2;
        float4 w = *reinterpret_cast<const float4*>(src + r * 128 + c4);
        float h0 = bfh_f(w.x), h1 = bfh_f(w.y), h2 = bfh_f(w.z), h3 = bfh_f(w.w);
        uint2 ph = make_uint2(bf2(h0, h1), bf2(h2, h3));
        uint2 pl = make_uint2(bf2(w.x - h0, w.y - h1), bf2(w.z - h2, w.w - h3));
        *reinterpret_cast<uint2*>(wh + r * PA + c4 * 2) = ph;
        *reinterpret_cast<uint2*>(wl + r * PA + c4 * 2) = pl;
    }
}
// stage fp32 [128][64] -> bf16 hi/lo, pitch 144B
__device__ __forceinline__ void stageV(const float* __restrict__ src, char* vh, char* vl, int tid) {
    for (int i = tid; i < 128 * 16; i += 256) {
        int r = i >> 4, c4 = (i & 15) << 2;
        float4 w = *reinterpret_cast<const float4*>(src + r * 64 + c4);
        float h0 = bfh_f(w.x), h1 = bfh_f(w.y), h2 = bfh_f(w.z), h3 = bfh_f(w.w);
        *reinterpret_cast<uint2*>(vh + r * PV + c4 * 2) = make_uint2(bf2(h0, h1), bf2(h2, h3));
        *reinterpret_cast<uint2*>(vl + r * PV + c4 * 2) =
            make_uint2(bf2(w.x - h0, w.y - h1), bf2(w.z - h2, w.w - h3));
    }
}
// write activation pair (r, c),(r, c+1) to A hi/lo
__device__ __forceinline__ void stA(char* aHp, char* aLp, int r, int c, float x0, float x1) {
    float h0 = bfh_f(x0), h1 = bfh_f(x1);
    *reinterpret_cast<uint32_t*>(aHp + r * PA + c * 2) = bf2(h0, h1);
    *reinterpret_cast<uint32_t*>(aLp + r * PA + c * 2) = bf2(x0 - h0, x1 - h1);
}

// generic smem-A x smem-B bf16-split gemm (3 passes), acc fp32
template <int MT, int NT>
__device__ __forceinline__ void gemm_sm(uint32_t aH, uint32_t aL, uint32_t bH, uint32_t bL,
                                        int mbase, int nbase, int pitchB,
                                        float (*acc)[4], int lane) {
    #pragma unroll
    for (int kt = 0; kt < 8; ++kt) {
        uint32_t ah[MT][4], al[MT][4];
        int q = lane >> 3;
        #pragma unroll
        for (int mt = 0; mt < MT; ++mt) {
            int row = mbase + mt * 16 + ((q & 1) << 3) + (lane & 7);
            uint32_t ad = (uint32_t)(row * PA + kt * 32 + ((q >> 1) << 4));
            ldsm4(ah[mt], aH + ad);
            ldsm4(al[mt], aL + ad);
        }
        uint32_t bh[NT / 2][4], bl[NT / 2][4];
        #pragma unroll
        for (int p = 0; p < NT / 2; ++p) {
            int row = nbase + p * 16 + ((lane >> 4) << 3) + (lane & 7);
            uint32_t bd = (uint32_t)(row * pitchB + kt * 32 + (((lane >> 3) & 1) << 4));
            ldsm4(bh[p], bH + bd);
            ldsm4(bl[p], bL + bd);
        }
        #pragma unroll
        for (int mt = 0; mt < MT; ++mt)
            #pragma unroll
            for (int nt = 0; nt < NT; ++nt) {
                float* d = acc[mt * NT + nt];
                uint32_t fh[2] = { bh[nt >> 1][(nt & 1) * 2], bh[nt >> 1][(nt & 1) * 2 + 1] };
                uint32_t fl[2] = { bl[nt >> 1][(nt & 1) * 2], bl[nt >> 1][(nt & 1) * 2 + 1] };
                mma16816(d, ah[mt], fh);
                mma16816(d, ah[mt], fl);
                mma16816(d, al[mt], fh);
            }
    }
}

// attended: A (P) fragments in registers, B = V tile (pitch 144), k=64, n=128
__device__ __forceinline__ void gemm_att(const uint32_t aPh[4][4], const uint32_t aPl[4][4],
                                         uint32_t bH, uint32_t bL, float (*acc)[4], int lane) {
    #pragma unroll
    for (int kt = 0; kt < 4; ++kt) {
        #pragma unroll
        for (int nh = 0; nh < 2; ++nh) {
            uint32_t bh[4][4], bl[4][4];
            #pragma unroll
            for (int p = 0; p < 4; ++p) {
                int row = nh * 64 + p * 16 + ((lane >> 4) << 3) + (lane & 7);
                uint32_t bd = (uint32_t)(row * PV + kt * 32 + (((lane >> 3) & 1) << 4));
                ldsm4(bh[p], bH + bd);
                ldsm4(bl[p], bL + bd);
            }
            #pragma unroll
            for (int nt2 = 0; nt2 < 8; ++nt2) {
                float* d = acc[nh * 8 + nt2];
                uint32_t fh[2] = { bh[nt2 >> 1][(nt2 & 1) * 2], bh[nt2 >> 1][(nt2 & 1) * 2 + 1] };
                uint32_t fl[2] = { bl[nt2 >> 1][(nt2 & 1) * 2], bl[nt2 >> 1][(nt2 & 1) * 2 + 1] };
                mma16816(d, aPh[kt], fh);
                mma16816(d, aPh[kt], fl);
                mma16816(d, aPl[kt], fh);
            }
        }
    }
}

// ===========================================================================
// Latent kernel (SIMT fp32, unchanged R4 core; k stored transposed [kidx][c])
// ===========================================================================
__device__ __forceinline__ ull pack2(float lo, float hi) {
    ull r; asm("mov.b64 %0, {%1, %2};" : "=l"(r) : "f"(lo), "f"(hi)); return r;
}
__device__ __forceinline__ void unpack2(ull v, float& lo, float& hi) {
    asm("mov.b64 {%0, %1}, %2;" : "=f"(lo), "=f"(hi) : "l"(v));
}
__device__ __forceinline__ ull ffma2(ull a, ull b, ull c) {
    ull d; asm("fma.rn.f32x2 %0, %1, %2, %3;" : "=l"(d) : "l"(a), "l"(b), "l"(c)); return d;
}

template <int RT, int NP, int PX, int CH>
__device__ __forceinline__ void gemm_core(const float* __restrict__ Wglob,
                                          const float* __restrict__ Xin,
                                          ull* __restrict__ Wts, ull acc[RT][NP], int tid) {
    const int tx = tid & 15, ty = tid >> 4;
    constexpr int R = RT * 16, PW2 = 2 * CH + 2, C4 = CH / 4, PT = (R * C4) / 256;
    const int wbase = (ty >> 1) * PW2 + (ty & 1);
    float4 pf[PT];
    #pragma unroll
    for (int p = 0; p < PT; ++p) {
        int idx = tid + p * 256, r = idx / C4, q = idx % C4;
        pf[p] = *reinterpret_cast<const float4*>(Wglob + r * 128 + q * 4);
    }
    for (int c0 = 0; c0 < 128; c0 += CH) {
        __syncthreads();
        #pragma unroll
        for (int p = 0; p < PT; ++p) {
            int idx = tid + p * 256, r = idx / C4, q = idx % C4;
            ull* d = Wts + (r >> 1) * PW2 + (r & 1) + 2 * (q * 4);
            d[0] = pack2(pf[p].x, pf[p].x); d[2] = pack2(pf[p].y, pf[p].y);
            d[4] = pack2(pf[p].z, pf[p].z); d[6] = pack2(pf[p].w, pf[p].w);
        }
        __syncthreads();
        if (c0 + CH < 128) {
            #pragma unroll
            for (int p = 0; p < PT; ++p) {
                int idx = tid + p * 256, r = idx / C4, q = idx % C4;
                pf[p] = *reinterpret_cast<const float4*>(Wglob + r * 128 + (c0 + CH) + q * 4);
            }
        }
        #pragma unroll 4
        for (int cc = 0; cc < CH; ++cc) {
            const float* xrow = Xin + (c0 + cc) * PX;
            ull xp[NP];
            #pragma unroll
            for (int jp = 0; jp < NP; ++jp)
                xp[jp] = *reinterpret_cast<const ull*>(xrow + 2 * (tx + 16 * jp));
            #pragma unroll
            for (int i = 0; i < RT; ++i) {
                ull wp = Wts[wbase + i * (8 * PW2) + 2 * cc];
                #pragma unroll
                for (int jp = 0; jp < NP; ++jp)
                    acc[i][jp] = ffma2(wp, xp[jp], acc[i][jp]);
            }
        }
    }
}

static constexpr int K1_XL = 0;
static constexpr int K1_LH = 128 * PXK;
static constexpr int K1_WT = K1_LH + 128 * PXK;
static constexpr int K1_WT_ULL = 64 * 34;
static constexpr int K1_RS = K1_WT + 2 * K1_WT_ULL;
static constexpr int K1_SMEM_BYTES = (K1_RS + 64) * 4;

__global__ void __launch_bounds__(256, 2) latent_kernel(
    const float* __restrict__ latent, const float* __restrict__ lp_gamma,
    const float* __restrict__ lp_w,   const float* __restrict__ lp_b,
    const float* __restrict__ k_w,    const float* __restrict__ k_b,
    const float* __restrict__ v_w,    const float* __restrict__ v_b)
{
    extern __shared__ float sm[];
    float* Xl = sm + K1_XL;
    float* Lh = sm + K1_LH;
    ull*   Wts = reinterpret_cast<ull*>(sm + K1_WT);
    float* rstd = sm + K1_RS;
    const int tid = threadIdx.x;
    const int frame = blockIdx.x;
    const int b = frame / T, t = frame % T;
    const int tx = tid & 15, ty = tid >> 4;

    const float* src = latent + ((size_t)b * C * T + t) * K;
    #pragma unroll
    for (int idx = tid; idx < 128 * 16; idx += 256) {
        int r = idx >> 4, q = idx & 15;
        float4 v = *reinterpret_cast<const float4*>(src + (size_t)r * (T * K) + q * 4);
        *reinterpret_cast<float4*>(Xl + r * PXK + q * 4) = v;
    }
    __syncthreads();
    if (tid < 64) {
        float s0 = 0, s1 = 0, s2 = 0, s3 = 0;
        for (int c = 0; c < 128; c += 4) {
            float a = Xl[c * PXK + tid], bb = Xl[(c + 1) * PXK + tid];
            float cc = Xl[(c + 2) * PXK + tid], dd = Xl[(c + 3) * PXK + tid];
            s0 += a * a; s1 += bb * bb; s2 += cc * cc; s3 += dd * dd;
        }
        rstd[tid] = rsqrtf((s0 + s1 + s2 + s3) * (1.0f / 128.0f) + 1e-6f);
    }
    __syncthreads();
    #pragma unroll
    for (int idx = tid; idx < 128 * 16; idx += 256) {
        int r = idx >> 4, q = idx & 15;
        float g = lp_gamma[r];
        float* d = Xl + r * PXK + q * 4;
        d[0] *= rstd[q * 4 + 0] * g; d[1] *= rstd[q * 4 + 1] * g;
        d[2] *= rstd[q * 4 + 2] * g; d[3] *= rstd[q * 4 + 3] * g;
    }
    {
        ull acc[8][2] = {};
        gemm_core<8, 2, PXK, 16>(lp_w, Xl, Wts, acc, tid);
        #pragma unroll
        for (int i = 0; i < 8; ++i) {
            int r = ty + 16 * i;
            float bias = lp_b[r];
            #pragma unroll
            for (int jp = 0; jp < 2; ++jp) {
                float lo, hi; unpack2(acc[i][jp], lo, hi);
                int fl = 2 * (tx + 16 * jp);
                Lh[r * PXK + fl]     = silu_f(lo + bias);
                Lh[r * PXK + fl + 1] = silu_f(hi + bias);
            }
        }
    }
    {   // k projection -> TRANSPOSED g_kbuf [kidx][c]
        ull acc[8][2] = {};
        gemm_core<8, 2, PXK, 16>(k_w, Lh, Wts, acc, tid);
        float* dst = g_kbuf + (size_t)frame * (C * K);
        #pragma unroll
        for (int i = 0; i < 8; ++i) {
            int r = ty + 16 * i;
            float bias = k_b[r];
            #pragma unroll
            for (int jp = 0; jp < 2; ++jp) {
                float lo, hi; unpack2(acc[i][jp], lo, hi);
                int fl = 2 * (tx + 16 * jp);
                dst[(size_t)(fl + 0) * C + r] = lo + bias;
                dst[(size_t)(fl + 1) * C + r] = hi + bias;
            }
        }
    }
    {
        ull acc[8][2] = {};
        gemm_core<8, 2, PXK, 16>(v_w, Lh, Wts, acc, tid);
        float* dst = g_vbuf + (size_t)frame * (C * K);
        #pragma unroll
        for (int i = 0; i < 8; ++i) {
            int r = ty + 16 * i;
            float bias = v_b[r];
            #pragma unroll
            for (int jp = 0; jp < 2; ++jp) {
                float lo, hi; unpack2(acc[i][jp], lo, hi);
                int fl = 2 * (tx + 16 * jp);
                *reinterpret_cast<float2*>(dst + r * K + fl) = make_float2(lo + bias, hi + bias);
            }
        }
    }
}

// ===========================================================================
// Main kernel — HMMA bf16-split. 256 threads, 1 CTA/SM.
// ===========================================================================
__global__ void __launch_bounds__(256, 1) main_kernel(
    const float* __restrict__ side,      const float* __restrict__ basis,
    const float* __restrict__ qn_gamma,
    const float* __restrict__ qmlp_in_w, const float* __restrict__ qmlp_in_b,
    const float* __restrict__ qmlp_out_w,const float* __restrict__ qmlp_out_b,
    const float* __restrict__ q_w,       const float* __restrict__ q_b,
    const float* __restrict__ o_w,       const float* __restrict__ o_b,
    const float* __restrict__ ffn_gamma,
    const float* __restrict__ ffn_in_w,  const float* __restrict__ ffn_in_b,
    const float* __restrict__ ffn_out_w, const float* __restrict__ ffn_out_b,
    const float* __restrict__ score_scale, const float* __restrict__ prior_scale,
    const float* __restrict__ query_skip_scale,
    float* __restrict__ out)
{
    extern __shared__ char smc[];
    float* red = reinterpret_cast<float*>(smc + SRED);
    char *aHp = smc + SA_H, *aLp = smc + SA_L, *wHp = smc + SW_H, *wLp = smc + SW_L;
    char *kHp = smc + SK_H, *kLp = smc + SK_L, *vHp = smc + SV_H, *vLp = smc + SV_L;
    float* park = reinterpret_cast<float*>(smc + SPARK);
    const uint32_t aH = smem_to_u32(aHp), aL = smem_to_u32(aLp);
    const uint32_t wH = smem_to_u32(wHp), wL = smem_to_u32(wLp);
    const uint32_t kH = smem_to_u32(kHp), kL = smem_to_u32(kLp);
    const uint32_t vH = smem_to_u32(vHp), vL = smem_to_u32(vLp);

    const int tid = threadIdx.x, wid = tid >> 5, lane = tid & 31;
    const int wm = wid & 1, wn = wid >> 1;
    const int qr = lane >> 2, qc = (lane & 3) << 1;
    const int fc = blockIdx.x, t = blockIdx.y, b = blockIdx.z;
    const int f0 = fc * 128;
    const int frame = b * T + t;

    // stage K, V, first W
    stageW(g_kbuf + (size_t)frame * (C * K), kHp, kLp, tid, 64);
    stageV(g_vbuf + (size_t)frame * (C * K), vHp, vLp, tid);
    stageW(qmlp_in_w + 128 * 128, wHp, wLp, tid, 128);

    // initial A: side chunk rmsnorm
    {
        const int wg = tid >> 7, f = tid & 127, cb = wg * 64;
        float x[64];
        const float* sp = side + ((size_t)b * C * T + t) * F + f0 + f;
        #pragma unroll 8
        for (int j = 0; j < 64; ++j) x[j] = sp[(size_t)(cb + j) * (T * F)];
        float ss = 0;
        #pragma unroll
        for (int j = 0; j < 64; ++j) ss += x[j] * x[j];
        red[wg * 128 + f] = ss;
        __syncthreads();
        float rs = rsqrtf((red[f] + red[128 + f]) * (1.0f / 128.0f) + 1e-6f);
        __syncthreads();
        #pragma unroll
        for (int j = 0; j < 64; j += 2)
            stA(aHp, aLp, f, cb + j, x[j] * rs * qn_gamma[cb + j],
                x[j + 1] * rs * qn_gamma[cb + j + 1]);
    }
    __syncthreads();

    float query[16][4], hidden[16][4];
    float acc[16][4];
    #define ZACC() do { _Pragma("unroll") for (int _i = 0; _i < 16; ++_i) { acc[_i][0]=0;acc[_i][1]=0;acc[_i][2]=0;acc[_i][3]=0; } } while(0)

    // ---- G1: qmlp gate ----
    ZACC();
    gemm_sm<4, 4>(aH, aL, wH, wL, wm * 64, wn * 32, PA, acc, lane);
    __syncthreads();
    stageW(qmlp_in_w, wHp, wLp, tid, 128);
    float g1[16][4];
    #pragma unroll
    for (int mt = 0; mt < 4; ++mt)
        #pragma unroll
        for (int nt = 0; nt < 4; ++nt) {
            int c = wn * 32 + nt * 8 + qc;
            float b0 = qmlp_in_b[128 + c], b1 = qmlp_in_b[129 + c];
            float* d = acc[mt * 4 + nt]; float* g = g1[mt * 4 + nt];
            g[0] = silu_f(d[0] + b0); g[1] = silu_f(d[1] + b1);
            g[2] = silu_f(d[2] + b0); g[3] = silu_f(d[3] + b1);
        }
    __syncthreads();

    // ---- G2: qmlp a; m -> A ----
    ZACC();
    gemm_sm<4, 4>(aH, aL, wH, wL, wm * 64, wn * 32, PA, acc, lane);
    __syncthreads();
    stageW(qmlp_out_w, wHp, wLp, tid, 128);
    #pragma unroll
    for (int mt = 0; mt < 4; ++mt)
        #pragma unroll
        for (int nt = 0; nt < 4; ++nt) {
            int r = wm * 64 + mt * 16 + qr, c = wn * 32 + nt * 8 + qc;
            float b0 = qmlp_in_b[c], b1 = qmlp_in_b[c + 1];
            float* d = acc[mt * 4 + nt]; float* g = g1[mt * 4 + nt];
            stA(aHp, aLp, r, c, (d[0] + b0) * g[0], (d[1] + b1) * g[1]);
            stA(aHp, aLp, r + 8, c, (d[2] + b0) * g[2], (d[3] + b1) * g[3]);
        }
    __syncthreads();

    // ---- G3: qmlp_out -> query_h (regs + A) ----
    ZACC();
    gemm_sm<4, 4>(aH, aL, wH, wL, wm * 64, wn * 32, PA, acc, lane);
    __syncthreads();
    stageW(q_w, wHp, wLp, tid, 128);
    #pragma unroll
    for (int mt = 0; mt < 4; ++mt)
        #pragma unroll
        for (int nt = 0; nt < 4; ++nt) {
            int r = wm * 64 + mt * 16 + qr, c = wn * 32 + nt * 8 + qc;
            float b0 = qmlp_out_b[c], b1 = qmlp_out_b[c + 1];
            float* d = acc[mt * 4 + nt]; float* qv = query[mt * 4 + nt];
            qv[0] = d[0] + b0; qv[1] = d[1] + b1; qv[2] = d[2] + b0; qv[3] = d[3] + b1;
            stA(aHp, aLp, r, c, qv[0], qv[1]);
            stA(aHp, aLp, r + 8, c, qv[2], qv[3]);
        }
    __syncthreads();

    // ---- G4: q projection -> A ----
    ZACC();
    gemm_sm<4, 4>(aH, aL, wH, wL, wm * 64, wn * 32, PA, acc, lane);
    __syncthreads();
    stageW(o_w, wHp, wLp, tid, 128);
    #pragma unroll
    for (int mt = 0; mt < 4; ++mt)
        #pragma unroll
        for (int nt = 0; nt < 4; ++nt) {
            int r = wm * 64 + mt * 16 + qr, c = wn * 32 + nt * 8 + qc;
            float b0 = q_b[c], b1 = q_b[c + 1];
            float* d = acc[mt * 4 + nt];
            stA(aHp, aLp, r, c, d[0] + b0, d[1] + b1);
            stA(aHp, aLp, r + 8, c, d[2] + b0, d[3] + b1);
        }
    __syncthreads();

    // ---- G5: scores (per-warp m16, N=64) + softmax -> P frags ----
    uint32_t aPh[4][4], aPl[4][4];
    {
        float sacc[8][4];
        #pragma unroll
        for (int i = 0; i < 8; ++i) { sacc[i][0]=0;sacc[i][1]=0;sacc[i][2]=0;sacc[i][3]=0; }
        gemm_sm<1, 8>(aH, aL, kH, kL, wid * 16, 0, PA, sacc, lane);
        const float ssc = *score_scale, psc = *prior_scale;
        const int fgA = f0 + wid * 16 + qr, fgB = fgA + 8;
        float p0[16], p1[16];
        #pragma unroll
        for (int nt = 0; nt < 8; ++nt) {
            int k0 = nt * 8 + qc;
            p0[nt * 2 + 0] = sacc[nt][0] * ssc + basis[(size_t)k0 * F + fgA] * psc;
            p0[nt * 2 + 1] = sacc[nt][1] * ssc + basis[(size_t)(k0 + 1) * F + fgA] * psc;
            p1[nt * 2 + 0] = sacc[nt][2] * ssc + basis[(size_t)k0 * F + fgB] * psc;
            p1[nt * 2 + 1] = sacc[nt][3] * ssc + basis[(size_t)(k0 + 1) * F + fgB] * psc;
        }
        float m0 = p0[0], m1 = p1[0];
        #pragma unroll
        for (int i = 1; i < 16; ++i) { m0 = fmaxf(m0, p0[i]); m1 = fmaxf(m1, p1[i]); }
        m0 = fmaxf(m0, __shfl_xor_sync(0xffffffffu, m0, 1));
        m0 = fmaxf(m0, __shfl_xor_sync(0xffffffffu, m0, 2));
        m1 = fmaxf(m1, __shfl_xor_sync(0xffffffffu, m1, 1));
        m1 = fmaxf(m1, __shfl_xor_sync(0xffffffffu, m1, 2));
        float s0 = 0, s1 = 0;
        #pragma unroll
        for (int i = 0; i < 16; ++i) {
            p0[i] = __expf(p0[i] - m0); s0 += p0[i];
            p1[i] = __expf(p1[i] - m1); s1 += p1[i];
        }
        s0 += __shfl_xor_sync(0xffffffffu, s0, 1); s0 += __shfl_xor_sync(0xffffffffu, s0, 2);
        s1 += __shfl_xor_sync(0xffffffffu, s1, 1); s1 += __shfl_xor_sync(0xffffffffu, s1, 2);
        float i0 = __frcp_rn(s0), i1 = __frcp_rn(s1);
        #pragma unroll
        for (int i = 0; i < 16; ++i) { p0[i] *= i0; p1[i] *= i1; }
        #pragma unroll
        for (int kt = 0; kt < 4; ++kt) {
            int iA = (2 * kt) * 2, iB = (2 * kt + 1) * 2;
            float x0, x1, h0, h1;
            x0 = p0[iA]; x1 = p0[iA + 1]; h0 = bfh_f(x0); h1 = bfh_f(x1);
            aPh[kt][0] = bf2(h0, h1); aPl[kt][0] = bf2(x0 - h0, x1 - h1);
            x0 = p1[iA]; x1 = p1[iA + 1]; h0 = bfh_f(x0); h1 = bfh_f(x1);
            aPh[kt][1] = bf2(h0, h1); aPl[kt][1] = bf2(x0 - h0, x1 - h1);
            x0 = p0[iB]; x1 = p0[iB + 1]; h0 = bfh_f(x0); h1 = bfh_f(x1);
            aPh[kt][2] = bf2(h0, h1); aPl[kt][2] = bf2(x0 - h0, x1 - h1);
            x0 = p1[iB]; x1 = p1[iB + 1]; h0 = bfh_f(x0); h1 = bfh_f(x1);
            aPh[kt][3] = bf2(h0, h1); aPl[kt][3] = bf2(x0 - h0, x1 - h1);
        }
    }
    // ---- G6: attended -> A (rows 16*wid, disjoint per warp) ----
    ZACC();
    gemm_att(aPh, aPl, vH, vL, acc, lane);
    #pragma unroll
    for (int nt = 0; nt < 16; ++nt) {
        int r = wid * 16 + qr, c = nt * 8 + qc;
        float* d = acc[nt];
        stA(aHp, aLp, r, c, d[0], d[1]);
        stA(aHp, aLp, r + 8, c, d[2], d[3]);
    }
    __syncthreads();

    // ---- G7: o_w; hidden = d + o_b + qss*query; rmsnorm -> A ----
    ZACC();
    gemm_sm<4, 4>(aH, aL, wH, wL, wm * 64, wn * 32, PA, acc, lane);
    __syncthreads();
    stageW(ffn_in_w + 128 * 128, wHp, wLp, tid, 128);
    {
        const float qs = *query_skip_scale;
        float ss[4][2] = {};
        #pragma unroll
        for (int mt = 0; mt < 4; ++mt)
            #pragma unroll
            for (int nt = 0; nt < 4; ++nt) {
                int c = wn * 32 + nt * 8 + qc;
                float b0 = o_b[c], b1 = o_b[c + 1];
                float* d = acc[mt * 4 + nt]; float* h = hidden[mt * 4 + nt];
                float* qv = query[mt * 4 + nt];
                h[0] = d[0] + b0 + qs * qv[0]; h[1] = d[1] + b1 + qs * qv[1];
                h[2] = d[2] + b0 + qs * qv[2]; h[3] = d[3] + b1 + qs * qv[3];
                ss[mt][0] += h[0] * h[0] + h[1] * h[1];
                ss[mt][1] += h[2] * h[2] + h[3] * h[3];
            }
        #pragma unroll
        for (int mt = 0; mt < 4; ++mt)
            #pragma unroll
            for (int rw = 0; rw < 2; ++rw) {
                float v = ss[mt][rw];
                v += __shfl_xor_sync(0xffffffffu, v, 1);
                v += __shfl_xor_sync(0xffffffffu, v, 2);
                if ((lane & 3) == 0)
                    red[(wm * 64 + mt * 16 + qr + rw * 8) * 4 + wn] = v;
            }
        __syncthreads();
        float rs_[4][2];
        #pragma unroll
        for (int mt = 0; mt < 4; ++mt)
            #pragma unroll
            for (int rw = 0; rw < 2; ++rw) {
                int r = wm * 64 + mt * 16 + qr + rw * 8;
                float s = red[r * 4] + red[r * 4 + 1] + red[r * 4 + 2] + red[r * 4 + 3];
                rs_[mt][rw] = rsqrtf(s * (1.0f / 128.0f) + 1e-6f);
            }
        #pragma unroll
        for (int mt = 0; mt < 4; ++mt)
            #pragma unroll
            for (int nt = 0; nt < 4; ++nt) {
                int r = wm * 64 + mt * 16 + qr, c = wn * 32 + nt * 8 + qc;
                float g0 = ffn_gamma[c], g1 = ffn_gamma[c + 1];
                float* h = hidden[mt * 4 + nt];
                stA(aHp, aLp, r, c, h[0] * rs_[mt][0] * g0, h[1] * rs_[mt][0] * g1);
                stA(aHp, aLp, r + 8, c, h[2] * rs_[mt][1] * g0, h[3] * rs_[mt][1] * g1);
            }
    }
    __syncthreads();

    // ---- G8: ffn gate -> park (overlay on dead K/V) ----
    ZACC();
    gemm_sm<4, 4>(aH, aL, wH, wL, wm * 64, wn * 32, PA, acc, lane);
    __syncthreads();
    stageW(ffn_in_w, wHp, wLp, tid, 128);
    #pragma unroll
    for (int mt = 0; mt < 4; ++mt)
        #pragma unroll
        for (int nt = 0; nt < 4; ++nt) {
            int r = wm * 64 + mt * 16 + qr, c = wn * 32 + nt * 8 + qc;
            float b0 = ffn_in_b[128 + c], b1 = ffn_in_b[129 + c];
            float* d = acc[mt * 4 + nt];
            *reinterpret_cast<float2*>(park + r * 132 + c) =
                make_float2(silu_f(d[0] + b0), silu_f(d[1] + b1));
            *reinterpret_cast<float2*>(park + (r + 8) * 132 + c) =
                make_float2(silu_f(d[2] + b0), silu_f(d[3] + b1));
        }
    __syncthreads();

    // ---- G9: ffn a; m2 = (a+b)*g -> A ----
    ZACC();
    gemm_sm<4, 4>(aH, aL, wH, wL, wm * 64, wn * 32, PA, acc, lane);
    __syncthreads();
    stageW(ffn_out_w, wHp, wLp, tid, 128);
    #pragma unroll
    for (int mt = 0; mt < 4; ++mt)
        #pragma unroll
        for (int nt = 0; nt < 4; ++nt) {
            int r = wm * 64 + mt * 16 + qr, c = wn * 32 + nt * 8 + qc;
            float b0 = ffn_in_b[c], b1 = ffn_in_b[c + 1];
            float* d = acc[mt * 4 + nt];
            float2 ga = *reinterpret_cast<float2*>(park + r * 132 + c);
            float2 gb = *reinterpret_cast<float2*>(park + (r + 8) * 132 + c);
            stA(aHp, aLp, r, c, (d[0] + b0) * ga.x, (d[1] + b1) * ga.y);
            stA(aHp, aLp, r + 8, c, (d[2] + b0) * gb.x, (d[3] + b1) * gb.y);
        }
    __syncthreads();

    // ---- G10: ffn_out; out = d + b + hidden -> global ----
    ZACC();
    gemm_sm<4, 4>(aH, aL, wH, wL, wm * 64, wn * 32, PA, acc, lane);
    {
        float* ob = out + ((size_t)b * C * T + t) * F + f0;
        #pragma unroll
        for (int mt = 0; mt < 4; ++mt)
            #pragma unroll
            for (int nt = 0; nt < 4; ++nt) {
                int r = wm * 64 + mt * 16 + qr, c = wn * 32 + nt * 8 + qc;
                float b0 = ffn_out_b[c], b1 = ffn_out_b[c + 1];
                float* d = acc[mt * 4 + nt]; float* h = hidden[mt * 4 + nt];
                ob[(size_t)c * (T * F) + r]           = d[0] + b0 + h[0];
                ob[(size_t)(c + 1) * (T * F) + r]     = d[1] + b1 + h[1];
                ob[(size_t)c * (T * F) + r + 8]       = d[2] + b0 + h[2];
                ob[(size_t)(c + 1) * (T * F) + r + 8] = d[3] + b1 + h[3];
            }
    }
    #undef ZACC
}

// ---------------------------------------------------------------------------
extern "C" void kernel_launch(void* const* d_in, const int* in_sizes, int n_in,
                              void* d_out, int out_size)
{
    const float* latent      = (const float*)d_in[0];
    const float* side        = (const float*)d_in[1];
    const float* basis       = (const float*)d_in[2];
    const float* lp_gamma    = (const float*)d_in[3];
    const float* lp_w        = (const float*)d_in[4];
    const float* lp_b        = (const float*)d_in[5];
    const float* qn_gamma    = (const float*)d_in[6];
    const float* qmlp_in_w   = (const float*)d_in[7];
    const float* qmlp_in_b   = (const float*)d_in[8];
    const float* qmlp_out_w  = (const float*)d_in[9];
    const float* qmlp_out_b  = (const float*)d_in[10];
    const float* q_w         = (const float*)d_in[11];
    const float* q_b         = (const float*)d_in[12];
    const float* k_w         = (const float*)d_in[13];
    const float* k_b         = (const float*)d_in[14];
    const float* v_w         = (const float*)d_in[15];
    const float* v_b         = (const float*)d_in[16];
    const float* o_w         = (const float*)d_in[17];
    const float* o_b         = (const float*)d_in[18];
    const float* ffn_gamma   = (const float*)d_in[19];
    const float* ffn_in_w    = (const float*)d_in[20];
    const float* ffn_in_b    = (const float*)d_in[21];
    const float* ffn_out_w   = (const float*)d_in[22];
    const float* ffn_out_b   = (const float*)d_in[23];
    const float* score_scale = (const float*)d_in[24];
    const float* prior_scale = (const float*)d_in[25];
    const float* qss         = (const float*)d_in[26];
    float* out = (float*)d_out;

    cudaFuncSetAttribute(latent_kernel, cudaFuncAttributeMaxDynamicSharedMemorySize, K1_SMEM_BYTES);
    cudaFuncSetAttribute(main_kernel,   cudaFuncAttributeMaxDynamicSharedMemorySize, K2_SMEM_BYTES);

    latent_kernel<<<B * T, 256, K1_SMEM_BYTES>>>(
        latent, lp_gamma, lp_w, lp_b, k_w, k_b, v_w, v_b);

    main_kernel<<<dim3(F / 128, T, B), 256, K2_SMEM_BYTES>>>(
        side, basis, qn_gamma,
        qmlp_in_w, qmlp_in_b, qmlp_out_w, qmlp_out_b,
        q_w, q_b, o_w, o_b,
        ffn_gamma, ffn_in_w, ffn_in_b, ffn_out_w, ffn_out_b,
        score_scale, prior_scale, qss, out);
}

// round 11
// speedup vs baseline: 2.5310x; 1.3538x over previous
#include <cuda_runtime.h>
#include <cuda_bf16.h>
#include <cstdint>
#include <math.h>

typedef unsigned long long ull;

static constexpr int B = 8, C = 128, T = 128, F = 512, K = 64;
static constexpr int PXK = 68;

__device__ float g_kbuf[(size_t)B * T * C * K];   // [frame][kidx][c]  (transposed)
__device__ float g_vbuf[(size_t)B * T * C * K];   // [frame][c][kidx]

__device__ __forceinline__ float silu_f(float g) {
    float e = __expf(-g);
    return __fdividef(g, 1.0f + e);
}
__device__ __forceinline__ uint32_t smem_to_u32(const void* p) {
    uint32_t a;
    asm("{ .reg .u64 t; cvta.to.shared.u64 t, %1; cvt.u32.u64 %0, t; }" : "=r"(a) : "l"(p));
    return a;
}
__device__ __forceinline__ void ldsm4(uint32_t* r, uint32_t addr) {
    asm volatile("ldmatrix.sync.aligned.m8n8.x4.shared.b16 {%0,%1,%2,%3}, [%4];"
        : "=r"(r[0]), "=r"(r[1]), "=r"(r[2]), "=r"(r[3]) : "r"(addr));
}
__device__ __forceinline__ void mma16816(float* d, const uint32_t* a, const uint32_t* b) {
    asm volatile("mma.sync.aligned.m16n8k16.row.col.f32.bf16.bf16.f32 "
        "{%0,%1,%2,%3},{%4,%5,%6,%7},{%8,%9},{%0,%1,%2,%3};"
        : "+f"(d[0]), "+f"(d[1]), "+f"(d[2]), "+f"(d[3])
        : "r"(a[0]), "r"(a[1]), "r"(a[2]), "r"(a[3]), "r"(b[0]), "r"(b[1]));
}
__device__ __forceinline__ float bfh_f(float x) { return __bfloat162float(__float2bfloat16(x)); }
__device__ __forceinline__ uint32_t bf2(float lo, float hi) {
    uint32_t r;
    asm("cvt.rn.satfinite.bf16x2.f32 %0, %1, %2;" : "=r"(r) : "f"(hi), "f"(lo));
    return r;
}

static constexpr int PA = 272;   // bytes, 136 bf16
static constexpr int PV = 144;   // bytes, 72 bf16
static constexpr int SRED = 0;                 // 2048 B
static constexpr int SA_H = 2048;
static constexpr int SA_L = SA_H + 34816;
static constexpr int SW_H = SA_L + 34816;
static constexpr int SW_L = SW_H + 34816;
static constexpr int SK_H = SW_L + 34816;
static constexpr int SK_L = SK_H + 17408;
static constexpr int SV_H = SK_L + 17408;
static constexpr int SV_L = SV_H + 18432;
static constexpr int K2_SMEM_BYTES = SV_L + 18432;   // 212992
static constexpr int SPARK = SK_H;   // fp32 [128][132] overlay (K/V dead)

__device__ __forceinline__ void stageW(const float* __restrict__ src, char* wh, char* wl,
                                       int start, int stride, int nrows) {
    for (int i = start; i < nrows * 32; i += stride) {
        int r = i >> 5, c4 = (i & 31) << 2;
        float4 w = *reinterpret_cast<const float4*>(src + r * 128 + c4);
        float h0 = bfh_f(w.x), h1 = bfh_f(w.y), h2 = bfh_f(w.z), h3 = bfh_f(w.w);
        *reinterpret_cast<uint2*>(wh + r * PA + c4 * 2) = make_uint2(bf2(h0, h1), bf2(h2, h3));
        *reinterpret_cast<uint2*>(wl + r * PA + c4 * 2) =
            make_uint2(bf2(w.x - h0, w.y - h1), bf2(w.z - h2, w.w - h3));
    }
}
__device__ __forceinline__ void stageV(const float* __restrict__ src, char* vh, char* vl,
                                       int start, int stride) {
    for (int i = start; i < 128 * 16; i += stride) {
        int r = i >> 4, c4 = (i & 15) << 2;
        float4 w = *reinterpret_cast<const float4*>(src + r * 64 + c4);
        float h0 = bfh_f(w.x), h1 = bfh_f(w.y), h2 = bfh_f(w.z), h3 = bfh_f(w.w);
        *reinterpret_cast<uint2*>(vh + r * PV + c4 * 2) = make_uint2(bf2(h0, h1), bf2(h2, h3));
        *reinterpret_cast<uint2*>(vl + r * PV + c4 * 2) =
            make_uint2(bf2(w.x - h0, w.y - h1), bf2(w.z - h2, w.w - h3));
    }
}
__device__ __forceinline__ void stA(char* aHp, char* aLp, int r, int c, float x0, float x1) {
    float h0 = bfh_f(x0), h1 = bfh_f(x1);
    *reinterpret_cast<uint32_t*>(aHp + r * PA + c * 2) = bf2(h0, h1);
    *reinterpret_cast<uint32_t*>(aLp + r * PA + c * 2) = bf2(x0 - h0, x1 - h1);
}

// smem-A x smem-B bf16-split GEMM (3 passes), row.col, acc fp32
template <int MT, int NT, int KT>
__device__ __forceinline__ void gemm_sm(uint32_t aH, uint32_t aL, uint32_t bH, uint32_t bL,
                                        int mbase, int nbase, int pitchB,
                                        float (*acc)[4], int lane) {
    #pragma unroll
    for (int kt = 0; kt < KT; ++kt) {
        uint32_t ah[MT][4], al[MT][4];
        int q = lane >> 3;
        #pragma unroll
        for (int mt = 0; mt < MT; ++mt) {
            int row = mbase + mt * 16 + ((q & 1) << 3) + (lane & 7);
            uint32_t ad = (uint32_t)(row * PA + kt * 32 + ((q >> 1) << 4));
            ldsm4(ah[mt], aH + ad);
            ldsm4(al[mt], aL + ad);
        }
        uint32_t bh[NT / 2][4], bl[NT / 2][4];
        #pragma unroll
        for (int p = 0; p < NT / 2; ++p) {
            int row = nbase + p * 16 + ((lane >> 4) << 3) + (lane & 7);
            uint32_t bd = (uint32_t)(row * pitchB + kt * 32 + (((lane >> 3) & 1) << 4));
            ldsm4(bh[p], bH + bd);
            ldsm4(bl[p], bL + bd);
        }
        #pragma unroll
        for (int mt = 0; mt < MT; ++mt)
            #pragma unroll
            for (int nt = 0; nt < NT; ++nt) {
                float* d = acc[mt * NT + nt];
                uint32_t fh[2] = { bh[nt >> 1][(nt & 1) * 2], bh[nt >> 1][(nt & 1) * 2 + 1] };
                uint32_t fl[2] = { bl[nt >> 1][(nt & 1) * 2], bl[nt >> 1][(nt & 1) * 2 + 1] };
                mma16816(d, ah[mt], fh);
                mma16816(d, ah[mt], fl);
                mma16816(d, al[mt], fh);
            }
    }
}

// ===========================================================================
// Latent kernel (SIMT fp32, unchanged; k stored transposed [kidx][c])
// ===========================================================================
__device__ __forceinline__ ull pack2(float lo, float hi) {
    ull r; asm("mov.b64 %0, {%1, %2};" : "=l"(r) : "f"(lo), "f"(hi)); return r;
}
__device__ __forceinline__ void unpack2(ull v, float& lo, float& hi) {
    asm("mov.b64 {%0, %1}, %2;" : "=f"(lo), "=f"(hi) : "l"(v));
}
__device__ __forceinline__ ull ffma2(ull a, ull b, ull c) {
    ull d; asm("fma.rn.f32x2 %0, %1, %2, %3;" : "=l"(d) : "l"(a), "l"(b), "l"(c)); return d;
}

template <int RT, int NP, int PX, int CH>
__device__ __forceinline__ void gemm_core(const float* __restrict__ Wglob,
                                          const float* __restrict__ Xin,
                                          ull* __restrict__ Wts, ull acc[RT][NP], int tid) {
    const int tx = tid & 15, ty = tid >> 4;
    constexpr int R = RT * 16, PW2 = 2 * CH + 2, C4 = CH / 4, PT = (R * C4) / 256;
    const int wbase = (ty >> 1) * PW2 + (ty & 1);
    float4 pf[PT];
    #pragma unroll
    for (int p = 0; p < PT; ++p) {
        int idx = tid + p * 256, r = idx / C4, q = idx % C4;
        pf[p] = *reinterpret_cast<const float4*>(Wglob + r * 128 + q * 4);
    }
    for (int c0 = 0; c0 < 128; c0 += CH) {
        __syncthreads();
        #pragma unroll
        for (int p = 0; p < PT; ++p) {
            int idx = tid + p * 256, r = idx / C4, q = idx % C4;
            ull* d = Wts + (r >> 1) * PW2 + (r & 1) + 2 * (q * 4);
            d[0] = pack2(pf[p].x, pf[p].x); d[2] = pack2(pf[p].y, pf[p].y);
            d[4] = pack2(pf[p].z, pf[p].z); d[6] = pack2(pf[p].w, pf[p].w);
        }
        __syncthreads();
        if (c0 + CH < 128) {
            #pragma unroll
            for (int p = 0; p < PT; ++p) {
                int idx = tid + p * 256, r = idx / C4, q = idx % C4;
                pf[p] = *reinterpret_cast<const float4*>(Wglob + r * 128 + (c0 + CH) + q * 4);
            }
        }
        #pragma unroll 4
        for (int cc = 0; cc < CH; ++cc) {
            const float* xrow = Xin + (c0 + cc) * PX;
            ull xp[NP];
            #pragma unroll
            for (int jp = 0; jp < NP; ++jp)
                xp[jp] = *reinterpret_cast<const ull*>(xrow + 2 * (tx + 16 * jp));
            #pragma unroll
            for (int i = 0; i < RT; ++i) {
                ull wp = Wts[wbase + i * (8 * PW2) + 2 * cc];
                #pragma unroll
                for (int jp = 0; jp < NP; ++jp)
                    acc[i][jp] = ffma2(wp, xp[jp], acc[i][jp]);
            }
        }
    }
}

static constexpr int K1_XL = 0;
static constexpr int K1_LH = 128 * PXK;
static constexpr int K1_WT = K1_LH + 128 * PXK;
static constexpr int K1_WT_ULL = 64 * 34;
static constexpr int K1_RS = K1_WT + 2 * K1_WT_ULL;
static constexpr int K1_SMEM_BYTES = (K1_RS + 64) * 4;

__global__ void __launch_bounds__(256, 2) latent_kernel(
    const float* __restrict__ latent, const float* __restrict__ lp_gamma,
    const float* __restrict__ lp_w,   const float* __restrict__ lp_b,
    const float* __restrict__ k_w,    const float* __restrict__ k_b,
    const float* __restrict__ v_w,    const float* __restrict__ v_b)
{
    extern __shared__ float sm[];
    float* Xl = sm + K1_XL;
    float* Lh = sm + K1_LH;
    ull*   Wts = reinterpret_cast<ull*>(sm + K1_WT);
    float* rstd = sm + K1_RS;
    const int tid = threadIdx.x;
    const int frame = blockIdx.x;
    const int b = frame / T, t = frame % T;
    const int tx = tid & 15, ty = tid >> 4;

    const float* src = latent + ((size_t)b * C * T + t) * K;
    #pragma unroll
    for (int idx = tid; idx < 128 * 16; idx += 256) {
        int r = idx >> 4, q = idx & 15;
        float4 v = *reinterpret_cast<const float4*>(src + (size_t)r * (T * K) + q * 4);
        *reinterpret_cast<float4*>(Xl + r * PXK + q * 4) = v;
    }
    __syncthreads();
    if (tid < 64) {
        float s0 = 0, s1 = 0, s2 = 0, s3 = 0;
        for (int c = 0; c < 128; c += 4) {
            float a = Xl[c * PXK + tid], bb = Xl[(c + 1) * PXK + tid];
            float cc = Xl[(c + 2) * PXK + tid], dd = Xl[(c + 3) * PXK + tid];
            s0 += a * a; s1 += bb * bb; s2 += cc * cc; s3 += dd * dd;
        }
        rstd[tid] = rsqrtf((s0 + s1 + s2 + s3) * (1.0f / 128.0f) + 1e-6f);
    }
    __syncthreads();
    #pragma unroll
    for (int idx = tid; idx < 128 * 16; idx += 256) {
        int r = idx >> 4, q = idx & 15;
        float g = lp_gamma[r];
        float* d = Xl + r * PXK + q * 4;
        d[0] *= rstd[q * 4 + 0] * g; d[1] *= rstd[q * 4 + 1] * g;
        d[2] *= rstd[q * 4 + 2] * g; d[3] *= rstd[q * 4 + 3] * g;
    }
    {
        ull acc[8][2] = {};
        gemm_core<8, 2, PXK, 16>(lp_w, Xl, Wts, acc, tid);
        #pragma unroll
        for (int i = 0; i < 8; ++i) {
            int r = ty + 16 * i;
            float bias = lp_b[r];
            #pragma unroll
            for (int jp = 0; jp < 2; ++jp) {
                float lo, hi; unpack2(acc[i][jp], lo, hi);
                int fl = 2 * (tx + 16 * jp);
                Lh[r * PXK + fl]     = silu_f(lo + bias);
                Lh[r * PXK + fl + 1] = silu_f(hi + bias);
            }
        }
    }
    {
        ull acc[8][2] = {};
        gemm_core<8, 2, PXK, 16>(k_w, Lh, Wts, acc, tid);
        float* dst = g_kbuf + (size_t)frame * (C * K);
        #pragma unroll
        for (int i = 0; i < 8; ++i) {
            int r = ty + 16 * i;
            float bias = k_b[r];
            #pragma unroll
            for (int jp = 0; jp < 2; ++jp) {
                float lo, hi; unpack2(acc[i][jp], lo, hi);
                int fl = 2 * (tx + 16 * jp);
                dst[(size_t)(fl + 0) * C + r] = lo + bias;
                dst[(size_t)(fl + 1) * C + r] = hi + bias;
            }
        }
    }
    {
        ull acc[8][2] = {};
        gemm_core<8, 2, PXK, 16>(v_w, Lh, Wts, acc, tid);
        float* dst = g_vbuf + (size_t)frame * (C * K);
        #pragma unroll
        for (int i = 0; i < 8; ++i) {
            int r = ty + 16 * i;
            float bias = v_b[r];
            #pragma unroll
            for (int jp = 0; jp < 2; ++jp) {
                float lo, hi; unpack2(acc[i][jp], lo, hi);
                int fl = 2 * (tx + 16 * jp);
                *reinterpret_cast<float2*>(dst + r * K + fl) = make_float2(lo + bias, hi + bias);
            }
        }
    }
}

// ===========================================================================
// Main kernel — HMMA bf16-split, 512 threads (16 warps), 1 CTA/SM.
// Main GEMMs: warp (wm=wid&3, wn=wid>>2) owns 32 rows x 32 cols (MT=2, NT=4).
// ===========================================================================
__global__ void __launch_bounds__(512, 1) main_kernel(
    const float* __restrict__ side,      const float* __restrict__ basis,
    const float* __restrict__ qn_gamma,
    const float* __restrict__ qmlp_in_w, const float* __restrict__ qmlp_in_b,
    const float* __restrict__ qmlp_out_w,const float* __restrict__ qmlp_out_b,
    const float* __restrict__ q_w,       const float* __restrict__ q_b,
    const float* __restrict__ o_w,       const float* __restrict__ o_b,
    const float* __restrict__ ffn_gamma,
    const float* __restrict__ ffn_in_w,  const float* __restrict__ ffn_in_b,
    const float* __restrict__ ffn_out_w, const float* __restrict__ ffn_out_b,
    const float* __restrict__ score_scale, const float* __restrict__ prior_scale,
    const float* __restrict__ query_skip_scale,
    float* __restrict__ out)
{
    extern __shared__ char smc[];
    float* red = reinterpret_cast<float*>(smc + SRED);
    char *aHp = smc + SA_H, *aLp = smc + SA_L, *wHp = smc + SW_H, *wLp = smc + SW_L;
    char *kHp = smc + SK_H, *kLp = smc + SK_L, *vHp = smc + SV_H, *vLp = smc + SV_L;
    float* park = reinterpret_cast<float*>(smc + SPARK);
    const uint32_t aH = smem_to_u32(aHp), aL = smem_to_u32(aLp);
    const uint32_t wH = smem_to_u32(wHp), wL = smem_to_u32(wLp);
    const uint32_t kH = smem_to_u32(kHp), kL = smem_to_u32(kLp);
    const uint32_t vH = smem_to_u32(vHp), vL = smem_to_u32(vLp);

    const int tid = threadIdx.x, wid = tid >> 5, lane = tid & 31;
    const int wm = wid & 3, wn = wid >> 2;          // 4 x 4 warp grid
    const int qr = lane >> 2, qc = (lane & 3) << 1;
    const int fc = blockIdx.x, t = blockIdx.y, b = blockIdx.z;
    const int f0 = fc * 128;
    const int frame = b * T + t;

    // stage K, V, first W (all 512 threads)
    stageW(g_kbuf + (size_t)frame * (C * K), kHp, kLp, tid, 512, 64);
    stageV(g_vbuf + (size_t)frame * (C * K), vHp, vLp, tid, 512);
    stageW(qmlp_in_w + 128 * 128, wHp, wLp, tid, 512, 128);

    // initial A: side chunk rmsnorm (4 groups x 128 f-lanes, 32 c each)
    {
        const int wg = tid >> 7, f = tid & 127, cb = wg * 32;
        float x[32];
        const float* sp = side + ((size_t)b * C * T + t) * F + f0 + f;
        #pragma unroll 8
        for (int j = 0; j < 32; ++j) x[j] = sp[(size_t)(cb + j) * (T * F)];
        float ss = 0;
        #pragma unroll
        for (int j = 0; j < 32; ++j) ss += x[j] * x[j];
        red[wg * 128 + f] = ss;
        __syncthreads();
        float rs = rsqrtf((red[f] + red[128 + f] + red[256 + f] + red[384 + f]) * (1.0f / 128.0f) + 1e-6f);
        __syncthreads();
        #pragma unroll
        for (int j = 0; j < 32; j += 2)
            stA(aHp, aLp, f, cb + j, x[j] * rs * qn_gamma[cb + j],
                x[j + 1] * rs * qn_gamma[cb + j + 1]);
    }
    __syncthreads();

    float query[8][4], hidden[8][4];
    float acc[8][4];
    #define ZACC() do { _Pragma("unroll") for (int _i = 0; _i < 8; ++_i) { acc[_i][0]=0;acc[_i][1]=0;acc[_i][2]=0;acc[_i][3]=0; } } while(0)

    // ---- G1: qmlp gate ----
    ZACC();
    gemm_sm<2, 4, 8>(aH, aL, wH, wL, wm * 32, wn * 32, PA, acc, lane);
    __syncthreads();
    stageW(qmlp_in_w, wHp, wLp, tid, 512, 128);
    float g1[8][4];
    #pragma unroll
    for (int mt = 0; mt < 2; ++mt)
        #pragma unroll
        for (int nt = 0; nt < 4; ++nt) {
            int c = wn * 32 + nt * 8 + qc;
            float b0 = qmlp_in_b[128 + c], b1 = qmlp_in_b[129 + c];
            float* d = acc[mt * 4 + nt]; float* g = g1[mt * 4 + nt];
            g[0] = silu_f(d[0] + b0); g[1] = silu_f(d[1] + b1);
            g[2] = silu_f(d[2] + b0); g[3] = silu_f(d[3] + b1);
        }
    __syncthreads();

    // ---- G2: qmlp a; m -> A ----
    ZACC();
    gemm_sm<2, 4, 8>(aH, aL, wH, wL, wm * 32, wn * 32, PA, acc, lane);
    __syncthreads();
    stageW(qmlp_out_w, wHp, wLp, tid, 512, 128);
    #pragma unroll
    for (int mt = 0; mt < 2; ++mt)
        #pragma unroll
        for (int nt = 0; nt < 4; ++nt) {
            int r = wm * 32 + mt * 16 + qr, c = wn * 32 + nt * 8 + qc;
            float b0 = qmlp_in_b[c], b1 = qmlp_in_b[c + 1];
            float* d = acc[mt * 4 + nt]; float* g = g1[mt * 4 + nt];
            stA(aHp, aLp, r, c, (d[0] + b0) * g[0], (d[1] + b1) * g[1]);
            stA(aHp, aLp, r + 8, c, (d[2] + b0) * g[2], (d[3] + b1) * g[3]);
        }
    __syncthreads();

    // ---- G3: qmlp_out -> query_h (regs + A) ----
    ZACC();
    gemm_sm<2, 4, 8>(aH, aL, wH, wL, wm * 32, wn * 32, PA, acc, lane);
    __syncthreads();
    stageW(q_w, wHp, wLp, tid, 512, 128);
    #pragma unroll
    for (int mt = 0; mt < 2; ++mt)
        #pragma unroll
        for (int nt = 0; nt < 4; ++nt) {
            int r = wm * 32 + mt * 16 + qr, c = wn * 32 + nt * 8 + qc;
            float b0 = qmlp_out_b[c], b1 = qmlp_out_b[c + 1];
            float* d = acc[mt * 4 + nt]; float* qv = query[mt * 4 + nt];
            qv[0] = d[0] + b0; qv[1] = d[1] + b1; qv[2] = d[2] + b0; qv[3] = d[3] + b1;
            stA(aHp, aLp, r, c, qv[0], qv[1]);
            stA(aHp, aLp, r + 8, c, qv[2], qv[3]);
        }
    __syncthreads();

    // ---- G4: q projection -> A ----
    ZACC();
    gemm_sm<2, 4, 8>(aH, aL, wH, wL, wm * 32, wn * 32, PA, acc, lane);
    __syncthreads();
    #pragma unroll
    for (int mt = 0; mt < 2; ++mt)
        #pragma unroll
        for (int nt = 0; nt < 4; ++nt) {
            int r = wm * 32 + mt * 16 + qr, c = wn * 32 + nt * 8 + qc;
            float b0 = q_b[c], b1 = q_b[c + 1];
            float* d = acc[mt * 4 + nt];
            stA(aHp, aLp, r, c, d[0] + b0, d[1] + b1);
            stA(aHp, aLp, r + 8, c, d[2] + b0, d[3] + b1);
        }
    __syncthreads();

    // ---- G5: scores + softmax (warps 0-7) || stage o_w (warps 8-15) ----
    if (wid < 8) {
        float sacc[8][4];
        #pragma unroll
        for (int i = 0; i < 8; ++i) { sacc[i][0]=0;sacc[i][1]=0;sacc[i][2]=0;sacc[i][3]=0; }
        gemm_sm<1, 8, 8>(aH, aL, kH, kL, wid * 16, 0, PA, sacc, lane);
        const float ssc = *score_scale, psc = *prior_scale;
        const int fgA = f0 + wid * 16 + qr, fgB = fgA + 8;
        float p0[16], p1[16];
        #pragma unroll
        for (int nt = 0; nt < 8; ++nt) {
            int k0 = nt * 8 + qc;
            p0[nt * 2 + 0] = sacc[nt][0] * ssc + basis[(size_t)k0 * F + fgA] * psc;
            p0[nt * 2 + 1] = sacc[nt][1] * ssc + basis[(size_t)(k0 + 1) * F + fgA] * psc;
            p1[nt * 2 + 0] = sacc[nt][2] * ssc + basis[(size_t)k0 * F + fgB] * psc;
            p1[nt * 2 + 1] = sacc[nt][3] * ssc + basis[(size_t)(k0 + 1) * F + fgB] * psc;
        }
        float m0 = p0[0], m1 = p1[0];
        #pragma unroll
        for (int i = 1; i < 16; ++i) { m0 = fmaxf(m0, p0[i]); m1 = fmaxf(m1, p1[i]); }
        m0 = fmaxf(m0, __shfl_xor_sync(0xffffffffu, m0, 1));
        m0 = fmaxf(m0, __shfl_xor_sync(0xffffffffu, m0, 2));
        m1 = fmaxf(m1, __shfl_xor_sync(0xffffffffu, m1, 1));
        m1 = fmaxf(m1, __shfl_xor_sync(0xffffffffu, m1, 2));
        float s0 = 0, s1 = 0;
        #pragma unroll
        for (int i = 0; i < 16; ++i) {
            p0[i] = __expf(p0[i] - m0); s0 += p0[i];
            p1[i] = __expf(p1[i] - m1); s1 += p1[i];
        }
        s0 += __shfl_xor_sync(0xffffffffu, s0, 1); s0 += __shfl_xor_sync(0xffffffffu, s0, 2);
        s1 += __shfl_xor_sync(0xffffffffu, s1, 1); s1 += __shfl_xor_sync(0xffffffffu, s1, 2);
        float i0 = __frcp_rn(s0), i1 = __frcp_rn(s1);
        // write P (softmax weights) as new A rows (own 16-row block, cols 0..63)
        #pragma unroll
        for (int nt = 0; nt < 8; ++nt) {
            int c = nt * 8 + qc;
            stA(aHp, aLp, wid * 16 + qr, c, p0[2 * nt] * i0, p0[2 * nt + 1] * i0);
            stA(aHp, aLp, wid * 16 + qr + 8, c, p1[2 * nt] * i1, p1[2 * nt + 1] * i1);
        }
    } else {
        stageW(o_w, wHp, wLp, tid - 256, 256, 128);
    }
    __syncthreads();

    // ---- G6: attended = P @ V (all 16 warps; A = P in smem, k=64) ----
    ZACC();
    gemm_sm<2, 4, 4>(aH, aL, vH, vL, wm * 32, wn * 32, PV, acc, lane);
    __syncthreads();
    #pragma unroll
    for (int mt = 0; mt < 2; ++mt)
        #pragma unroll
        for (int nt = 0; nt < 4; ++nt) {
            int r = wm * 32 + mt * 16 + qr, c = wn * 32 + nt * 8 + qc;
            float* d = acc[mt * 4 + nt];
            stA(aHp, aLp, r, c, d[0], d[1]);
            stA(aHp, aLp, r + 8, c, d[2], d[3]);
        }
    __syncthreads();

    // ---- G7: o_w; hidden = d + o_b + qss*query; rmsnorm -> A ----
    ZACC();
    gemm_sm<2, 4, 8>(aH, aL, wH, wL, wm * 32, wn * 32, PA, acc, lane);
    __syncthreads();
    stageW(ffn_in_w + 128 * 128, wHp, wLp, tid, 512, 128);
    {
        const float qs = *query_skip_scale;
        float ss[2][2] = {};
        #pragma unroll
        for (int mt = 0; mt < 2; ++mt)
            #pragma unroll
            for (int nt = 0; nt < 4; ++nt) {
                int c = wn * 32 + nt * 8 + qc;
                float b0 = o_b[c], b1 = o_b[c + 1];
                float* d = acc[mt * 4 + nt]; float* h = hidden[mt * 4 + nt];
                float* qv = query[mt * 4 + nt];
                h[0] = d[0] + b0 + qs * qv[0]; h[1] = d[1] + b1 + qs * qv[1];
                h[2] = d[2] + b0 + qs * qv[2]; h[3] = d[3] + b1 + qs * qv[3];
                ss[mt][0] += h[0] * h[0] + h[1] * h[1];
                ss[mt][1] += h[2] * h[2] + h[3] * h[3];
            }
        #pragma unroll
        for (int mt = 0; mt < 2; ++mt)
            #pragma unroll
            for (int rw = 0; rw < 2; ++rw) {
                float v = ss[mt][rw];
                v += __shfl_xor_sync(0xffffffffu, v, 1);
                v += __shfl_xor_sync(0xffffffffu, v, 2);
                if ((lane & 3) == 0)
                    red[(wm * 32 + mt * 16 + qr + rw * 8) * 4 + wn] = v;
            }
        __syncthreads();
        float rs_[2][2];
        #pragma unroll
        for (int mt = 0; mt < 2; ++mt)
            #pragma unroll
            for (int rw = 0; rw < 2; ++rw) {
                int r = wm * 32 + mt * 16 + qr + rw * 8;
                float s = red[r * 4] + red[r * 4 + 1] + red[r * 4 + 2] + red[r * 4 + 3];
                rs_[mt][rw] = rsqrtf(s * (1.0f / 128.0f) + 1e-6f);
            }
        #pragma unroll
        for (int mt = 0; mt < 2; ++mt)
            #pragma unroll
            for (int nt = 0; nt < 4; ++nt) {
                int r = wm * 32 + mt * 16 + qr, c = wn * 32 + nt * 8 + qc;
                float g0 = ffn_gamma[c], g1 = ffn_gamma[c + 1];
                float* h = hidden[mt * 4 + nt];
                stA(aHp, aLp, r, c, h[0] * rs_[mt][0] * g0, h[1] * rs_[mt][0] * g1);
                stA(aHp, aLp, r + 8, c, h[2] * rs_[mt][1] * g0, h[3] * rs_[mt][1] * g1);
            }
    }
    __syncthreads();

    // ---- G8: ffn gate -> park ----
    ZACC();
    gemm_sm<2, 4, 8>(aH, aL, wH, wL, wm * 32, wn * 32, PA, acc, lane);
    __syncthreads();
    stageW(ffn_in_w, wHp, wLp, tid, 512, 128);
    #pragma unroll
    for (int mt = 0; mt < 2; ++mt)
        #pragma unroll
        for (int nt = 0; nt < 4; ++nt) {
            int r = wm * 32 + mt * 16 + qr, c = wn * 32 + nt * 8 + qc;
            float b0 = ffn_in_b[128 + c], b1 = ffn_in_b[129 + c];
            float* d = acc[mt * 4 + nt];
            *reinterpret_cast<float2*>(park + r * 132 + c) =
                make_float2(silu_f(d[0] + b0), silu_f(d[1] + b1));
            *reinterpret_cast<float2*>(park + (r + 8) * 132 + c) =
                make_float2(silu_f(d[2] + b0), silu_f(d[3] + b1));
        }
    __syncthreads();

    // ---- G9: ffn a; m2 = (a+b)*g -> A ----
    ZACC();
    gemm_sm<2, 4, 8>(aH, aL, wH, wL, wm * 32, wn * 32, PA, acc, lane);
    __syncthreads();
    stageW(ffn_out_w, wHp, wLp, tid, 512, 128);
    #pragma unroll
    for (int mt = 0; mt < 2; ++mt)
        #pragma unroll
        for (int nt = 0; nt < 4; ++nt) {
            int r = wm * 32 + mt * 16 + qr, c = wn * 32 + nt * 8 + qc;
            float b0 = ffn_in_b[c], b1 = ffn_in_b[c + 1];
            float* d = acc[mt * 4 + nt];
            float2 ga = *reinterpret_cast<float2*>(park + r * 132 + c);
            float2 gb = *reinterpret_cast<float2*>(park + (r + 8) * 132 + c);
            stA(aHp, aLp, r, c, (d[0] + b0) * ga.x, (d[1] + b1) * ga.y);
            stA(aHp, aLp, r + 8, c, (d[2] + b0) * gb.x, (d[3] + b1) * gb.y);
        }
    __syncthreads();

    // ---- G10: ffn_out; out = d + b + hidden -> global ----
    ZACC();
    gemm_sm<2, 4, 8>(aH, aL, wH, wL, wm * 32, wn * 32, PA, acc, lane);
    {
        float* ob = out + ((size_t)b * C * T + t) * F + f0;
        #pragma unroll
        for (int mt = 0; mt < 2; ++mt)
            #pragma unroll
            for (int nt = 0; nt < 4; ++nt) {
                int r = wm * 32 + mt * 16 + qr, c = wn * 32 + nt * 8 + qc;
                float b0 = ffn_out_b[c], b1 = ffn_out_b[c + 1];
                float* d = acc[mt * 4 + nt]; float* h = hidden[mt * 4 + nt];
                ob[(size_t)c * (T * F) + r]           = d[0] + b0 + h[0];
                ob[(size_t)(c + 1) * (T * F) + r]     = d[1] + b1 + h[1];
                ob[(size_t)c * (T * F) + r + 8]       = d[2] + b0 + h[2];
                ob[(size_t)(c + 1) * (T * F) + r + 8] = d[3] + b1 + h[3];
            }
    }
    #undef ZACC
}

// ---------------------------------------------------------------------------
extern "C" void kernel_launch(void* const* d_in, const int* in_sizes, int n_in,
                              void* d_out, int out_size)
{
    const float* latent      = (const float*)d_in[0];
    const float* side        = (const float*)d_in[1];
    const float* basis       = (const float*)d_in[2];
    const float* lp_gamma    = (const float*)d_in[3];
    const float* lp_w        = (const float*)d_in[4];
    const float* lp_b        = (const float*)d_in[5];
    const float* qn_gamma    = (const float*)d_in[6];
    const float* qmlp_in_w   = (const float*)d_in[7];
    const float* qmlp_in_b   = (const float*)d_in[8];
    const float* qmlp_out_w  = (const float*)d_in[9];
    const float* qmlp_out_b  = (const float*)d_in[10];
    const float* q_w         = (const float*)d_in[11];
    const float* q_b         = (const float*)d_in[12];
    const float* k_w         = (const float*)d_in[13];
    const float* k_b         = (const float*)d_in[14];
    const float* v_w         = (const float*)d_in[15];
    const float* v_b         = (const float*)d_in[16];
    const float* o_w         = (const float*)d_in[17];
    const float* o_b         = (const float*)d_in[18];
    const float* ffn_gamma   = (const float*)d_in[19];
    const float* ffn_in_w    = (const float*)d_in[20];
    const float* ffn_in_b    = (const float*)d_in[21];
    const float* ffn_out_w   = (const float*)d_in[22];
    const float* ffn_out_b   = (const float*)d_in[23];
    const float* score_scale = (const float*)d_in[24];
    const float* prior_scale = (const float*)d_in[25];
    const float* qss         = (const float*)d_in[26];
    float* out = (float*)d_out;

    cudaFuncSetAttribute(latent_kernel, cudaFuncAttributeMaxDynamicSharedMemorySize, K1_SMEM_BYTES);
    cudaFuncSetAttribute(main_kernel,   cudaFuncAttributeMaxDynamicSharedMemorySize, K2_SMEM_BYTES);

    latent_kernel<<<B * T, 256, K1_SMEM_BYTES>>>(
        latent, lp_gamma, lp_w, lp_b, k_w, k_b, v_w, v_b);

    main_kernel<<<dim3(F / 128, T, B), 512, K2_SMEM_BYTES>>>(
        side, basis, qn_gamma,
        qmlp_in_w, qmlp_in_b, qmlp_out_w, qmlp_out_b,
        q_w, q_b, o_w, o_b,
        ffn_gamma, ffn_in_w, ffn_in_b, ffn_out_w, ffn_out_b,
        score_scale, prior_scale, qss, out);
}

// round 12
// speedup vs baseline: 3.0661x; 1.2114x over previous
#include <cuda_runtime.h>
#include <cuda_bf16.h>
#include <cstdint>
#include <math.h>

typedef unsigned long long ull;

static constexpr int B = 8, C = 128, T = 128, F = 512, K = 64;
static constexpr int PXK = 68;

// pre-converted bf16 hi/lo tiles (smem-identical layout)
// weights: 8 tiles x [hi 128x136][lo 128x136]
__device__ uint4 g_wt4[8 * 69632 / 16];
// K tiles: per frame [hi 64x136][lo 64x136] (rows = kidx, cols = c)
__device__ uint4 g_kt4[(size_t)1024 * 2176];
// V tiles: per frame [hi 128x72][lo 128x72] (rows = c, cols = kidx)
__device__ uint4 g_vt4[(size_t)1024 * 2304];

__device__ __forceinline__ float silu_f(float g) {
    float e = __expf(-g);
    return __fdividef(g, 1.0f + e);
}
__device__ __forceinline__ uint32_t smem_to_u32(const void* p) {
    uint32_t a;
    asm("{ .reg .u64 t; cvta.to.shared.u64 t, %1; cvt.u32.u64 %0, t; }" : "=r"(a) : "l"(p));
    return a;
}
__device__ __forceinline__ void ldsm4(uint32_t* r, uint32_t addr) {
    asm volatile("ldmatrix.sync.aligned.m8n8.x4.shared.b16 {%0,%1,%2,%3}, [%4];"
        : "=r"(r[0]), "=r"(r[1]), "=r"(r[2]), "=r"(r[3]) : "r"(addr));
}
__device__ __forceinline__ void mma16816(float* d, const uint32_t* a, const uint32_t* b) {
    asm volatile("mma.sync.aligned.m16n8k16.row.col.f32.bf16.bf16.f32 "
        "{%0,%1,%2,%3},{%4,%5,%6,%7},{%8,%9},{%0,%1,%2,%3};"
        : "+f"(d[0]), "+f"(d[1]), "+f"(d[2]), "+f"(d[3])
        : "r"(a[0]), "r"(a[1]), "r"(a[2]), "r"(a[3]), "r"(b[0]), "r"(b[1]));
}
__device__ __forceinline__ float bfh_f(float x) { return __bfloat162float(__float2bfloat16(x)); }
__device__ __forceinline__ uint32_t bf2(float lo, float hi) {
    uint32_t r;
    asm("cvt.rn.satfinite.bf16x2.f32 %0, %1, %2;" : "=r"(r) : "f"(hi), "f"(lo));
    return r;
}
// cp.async: issue nchunks 16B copies, one commit group per call
__device__ __forceinline__ void cpa(uint32_t sdst, const void* gsrc, int nchunks, int tid) {
    const char* gp = (const char*)gsrc;
    for (int i = tid; i < nchunks; i += 512)
        asm volatile("cp.async.cg.shared.global [%0], [%1], 16;"
                     :: "r"(sdst + 16u * i), "l"(gp + 16 * i));
    asm volatile("cp.async.commit_group;" ::: "memory");
}
#define CP_WAIT() asm volatile("cp.async.wait_group 0;" ::: "memory")

static constexpr int PA = 272;   // bytes, 136 bf16
static constexpr int PV = 144;   // bytes, 72 bf16
static constexpr int SRED = 0;                 // 2048 B
static constexpr int SA_H = 2048;
static constexpr int SA_L = SA_H + 34816;
static constexpr int SW_H = SA_L + 34816;
static constexpr int SW_L = SW_H + 34816;
static constexpr int SK_H = SW_L + 34816;      // K hi (17408) then K lo (17408)
static constexpr int SV_H = SK_H + 34816;      // V hi (18432) then V lo (18432)
static constexpr int K2_SMEM_BYTES = SV_H + 36864;   // 212992
static constexpr int SPARK = SK_H;   // fp32 [128][132] overlay (K/V dead after G6)

__device__ __forceinline__ void stA(char* aHp, char* aLp, int r, int c, float x0, float x1) {
    float h0 = bfh_f(x0), h1 = bfh_f(x1);
    *reinterpret_cast<uint32_t*>(aHp + r * PA + c * 2) = bf2(h0, h1);
    *reinterpret_cast<uint32_t*>(aLp + r * PA + c * 2) = bf2(x0 - h0, x1 - h1);
}

// smem-A x smem-B bf16-split GEMM (3 passes), row.col, acc fp32
template <int MT, int NT, int KT>
__device__ __forceinline__ void gemm_sm(uint32_t aH, uint32_t aL, uint32_t bH, uint32_t bL,
                                        int mbase, int nbase, int pitchB,
                                        float (*acc)[4], int lane) {
    #pragma unroll
    for (int kt = 0; kt < KT; ++kt) {
        uint32_t ah[MT][4], al[MT][4];
        int q = lane >> 3;
        #pragma unroll
        for (int mt = 0; mt < MT; ++mt) {
            int row = mbase + mt * 16 + ((q & 1) << 3) + (lane & 7);
            uint32_t ad = (uint32_t)(row * PA + kt * 32 + ((q >> 1) << 4));
            ldsm4(ah[mt], aH + ad);
            ldsm4(al[mt], aL + ad);
        }
        uint32_t bh[NT / 2][4], bl[NT / 2][4];
        #pragma unroll
        for (int p = 0; p < NT / 2; ++p) {
            int row = nbase + p * 16 + ((lane >> 4) << 3) + (lane & 7);
            uint32_t bd = (uint32_t)(row * pitchB + kt * 32 + (((lane >> 3) & 1) << 4));
            ldsm4(bh[p], bH + bd);
            ldsm4(bl[p], bL + bd);
        }
        #pragma unroll
        for (int mt = 0; mt < MT; ++mt)
            #pragma unroll
            for (int nt = 0; nt < NT; ++nt) {
                float* d = acc[mt * NT + nt];
                uint32_t fh[2] = { bh[nt >> 1][(nt & 1) * 2], bh[nt >> 1][(nt & 1) * 2 + 1] };
                uint32_t fl[2] = { bl[nt >> 1][(nt & 1) * 2], bl[nt >> 1][(nt & 1) * 2 + 1] };
                mma16816(d, ah[mt], fh);
                mma16816(d, ah[mt], fl);
                mma16816(d, al[mt], fh);
            }
    }
}

// ===========================================================================
// Prep kernel — convert 8 weight tiles to bf16 hi/lo tile layout (once)
// ===========================================================================
__global__ void prep_kernel(
    const float* __restrict__ qmlp_in_w, const float* __restrict__ qmlp_out_w,
    const float* __restrict__ q_w,       const float* __restrict__ o_w,
    const float* __restrict__ ffn_in_w,  const float* __restrict__ ffn_out_w)
{
    const int bid = blockIdx.x, tid = threadIdx.x;
    const float* src;
    switch (bid) {
        case 0: src = qmlp_in_w + 16384; break;
        case 1: src = qmlp_in_w; break;
        case 2: src = qmlp_out_w; break;
        case 3: src = q_w; break;
        case 4: src = o_w; break;
        case 5: src = ffn_in_w + 16384; break;
        case 6: src = ffn_in_w; break;
        default: src = ffn_out_w; break;
    }
    __nv_bfloat16* dh = reinterpret_cast<__nv_bfloat16*>(g_wt4) + (size_t)bid * 34816;
    __nv_bfloat16* dl = dh + 17408;
    for (int i = tid; i < 128 * 32; i += 256) {
        int r = i >> 5, c4 = (i & 31) << 2;
        float4 w = *reinterpret_cast<const float4*>(src + r * 128 + c4);
        float h0 = bfh_f(w.x), h1 = bfh_f(w.y), h2 = bfh_f(w.z), h3 = bfh_f(w.w);
        *reinterpret_cast<uint32_t*>(dh + r * 136 + c4)     = bf2(h0, h1);
        *reinterpret_cast<uint32_t*>(dh + r * 136 + c4 + 2) = bf2(h2, h3);
        *reinterpret_cast<uint32_t*>(dl + r * 136 + c4)     = bf2(w.x - h0, w.y - h1);
        *reinterpret_cast<uint32_t*>(dl + r * 136 + c4 + 2) = bf2(w.z - h2, w.w - h3);
    }
}

// ===========================================================================
// Latent kernel (SIMT fp32); writes K/V as bf16 hi/lo tiles in global
// ===========================================================================
__device__ __forceinline__ ull pack2(float lo, float hi) {
    ull r; asm("mov.b64 %0, {%1, %2};" : "=l"(r) : "f"(lo), "f"(hi)); return r;
}
__device__ __forceinline__ void unpack2(ull v, float& lo, float& hi) {
    asm("mov.b64 {%0, %1}, %2;" : "=f"(lo), "=f"(hi) : "l"(v));
}
__device__ __forceinline__ ull ffma2(ull a, ull b, ull c) {
    ull d; asm("fma.rn.f32x2 %0, %1, %2, %3;" : "=l"(d) : "l"(a), "l"(b), "l"(c)); return d;
}

template <int RT, int NP, int PX, int CH>
__device__ __forceinline__ void gemm_core(const float* __restrict__ Wglob,
                                          const float* __restrict__ Xin,
                                          ull* __restrict__ Wts, ull acc[RT][NP], int tid) {
    const int tx = tid & 15, ty = tid >> 4;
    constexpr int R = RT * 16, PW2 = 2 * CH + 2, C4 = CH / 4, PT = (R * C4) / 256;
    const int wbase = (ty >> 1) * PW2 + (ty & 1);
    float4 pf[PT];
    #pragma unroll
    for (int p = 0; p < PT; ++p) {
        int idx = tid + p * 256, r = idx / C4, q = idx % C4;
        pf[p] = *reinterpret_cast<const float4*>(Wglob + r * 128 + q * 4);
    }
    for (int c0 = 0; c0 < 128; c0 += CH) {
        __syncthreads();
        #pragma unroll
        for (int p = 0; p < PT; ++p) {
            int idx = tid + p * 256, r = idx / C4, q = idx % C4;
            ull* d = Wts + (r >> 1) * PW2 + (r & 1) + 2 * (q * 4);
            d[0] = pack2(pf[p].x, pf[p].x); d[2] = pack2(pf[p].y, pf[p].y);
            d[4] = pack2(pf[p].z, pf[p].z); d[6] = pack2(pf[p].w, pf[p].w);
        }
        __syncthreads();
        if (c0 + CH < 128) {
            #pragma unroll
            for (int p = 0; p < PT; ++p) {
                int idx = tid + p * 256, r = idx / C4, q = idx % C4;
                pf[p] = *reinterpret_cast<const float4*>(Wglob + r * 128 + (c0 + CH) + q * 4);
            }
        }
        #pragma unroll 4
        for (int cc = 0; cc < CH; ++cc) {
            const float* xrow = Xin + (c0 + cc) * PX;
            ull xp[NP];
            #pragma unroll
            for (int jp = 0; jp < NP; ++jp)
                xp[jp] = *reinterpret_cast<const ull*>(xrow + 2 * (tx + 16 * jp));
            #pragma unroll
            for (int i = 0; i < RT; ++i) {
                ull wp = Wts[wbase + i * (8 * PW2) + 2 * cc];
                #pragma unroll
                for (int jp = 0; jp < NP; ++jp)
                    acc[i][jp] = ffma2(wp, xp[jp], acc[i][jp]);
            }
        }
    }
}

static constexpr int K1_XL = 0;
static constexpr int K1_LH = 128 * PXK;
static constexpr int K1_WT = K1_LH + 128 * PXK;
static constexpr int K1_WT_ULL = 64 * 34;
static constexpr int K1_RS = K1_WT + 2 * K1_WT_ULL;
static constexpr int K1_SMEM_BYTES = (K1_RS + 64) * 4;

__global__ void __launch_bounds__(256, 2) latent_kernel(
    const float* __restrict__ latent, const float* __restrict__ lp_gamma,
    const float* __restrict__ lp_w,   const float* __restrict__ lp_b,
    const float* __restrict__ k_w,    const float* __restrict__ k_b,
    const float* __restrict__ v_w,    const float* __restrict__ v_b)
{
    extern __shared__ float sm[];
    float* Xl = sm + K1_XL;
    float* Lh = sm + K1_LH;
    ull*   Wts = reinterpret_cast<ull*>(sm + K1_WT);
    float* rstd = sm + K1_RS;
    const int tid = threadIdx.x;
    const int frame = blockIdx.x;
    const int b = frame / T, t = frame % T;
    const int tx = tid & 15, ty = tid >> 4;

    const float* src = latent + ((size_t)b * C * T + t) * K;
    #pragma unroll
    for (int idx = tid; idx < 128 * 16; idx += 256) {
        int r = idx >> 4, q = idx & 15;
        float4 v = *reinterpret_cast<const float4*>(src + (size_t)r * (T * K) + q * 4);
        *reinterpret_cast<float4*>(Xl + r * PXK + q * 4) = v;
    }
    __syncthreads();
    if (tid < 64) {
        float s0 = 0, s1 = 0, s2 = 0, s3 = 0;
        for (int c = 0; c < 128; c += 4) {
            float a = Xl[c * PXK + tid], bb = Xl[(c + 1) * PXK + tid];
            float cc = Xl[(c + 2) * PXK + tid], dd = Xl[(c + 3) * PXK + tid];
            s0 += a * a; s1 += bb * bb; s2 += cc * cc; s3 += dd * dd;
        }
        rstd[tid] = rsqrtf((s0 + s1 + s2 + s3) * (1.0f / 128.0f) + 1e-6f);
    }
    __syncthreads();
    #pragma unroll
    for (int idx = tid; idx < 128 * 16; idx += 256) {
        int r = idx >> 4, q = idx & 15;
        float g = lp_gamma[r];
        float* d = Xl + r * PXK + q * 4;
        d[0] *= rstd[q * 4 + 0] * g; d[1] *= rstd[q * 4 + 1] * g;
        d[2] *= rstd[q * 4 + 2] * g; d[3] *= rstd[q * 4 + 3] * g;
    }
    {
        ull acc[8][2] = {};
        gemm_core<8, 2, PXK, 16>(lp_w, Xl, Wts, acc, tid);
        #pragma unroll
        for (int i = 0; i < 8; ++i) {
            int r = ty + 16 * i;
            float bias = lp_b[r];
            #pragma unroll
            for (int jp = 0; jp < 2; ++jp) {
                float lo, hi; unpack2(acc[i][jp], lo, hi);
                int fl = 2 * (tx + 16 * jp);
                Lh[r * PXK + fl]     = silu_f(lo + bias);
                Lh[r * PXK + fl + 1] = silu_f(hi + bias);
            }
        }
    }
    {   // k projection -> bf16 hi/lo K tile [kidx rows][c cols], pitch 136
        ull acc[8][2] = {};
        gemm_core<8, 2, PXK, 16>(k_w, Lh, Wts, acc, tid);
        __nv_bfloat16* kt = reinterpret_cast<__nv_bfloat16*>(g_kt4) + (size_t)frame * 17408;
        #pragma unroll
        for (int i = 0; i < 8; ++i) {
            int r = ty + 16 * i;
            float bias = k_b[r];
            #pragma unroll
            for (int jp = 0; jp < 2; ++jp) {
                float v0, v1; unpack2(acc[i][jp], v0, v1);
                v0 += bias; v1 += bias;
                int fl = 2 * (tx + 16 * jp);
                __nv_bfloat16 h0 = __float2bfloat16(v0);
                __nv_bfloat16 h1 = __float2bfloat16(v1);
                kt[(size_t)fl * 136 + r] = h0;
                kt[(size_t)(fl + 1) * 136 + r] = h1;
                kt[8704 + (size_t)fl * 136 + r] = __float2bfloat16(v0 - __bfloat162float(h0));
                kt[8704 + (size_t)(fl + 1) * 136 + r] = __float2bfloat16(v1 - __bfloat162float(h1));
            }
        }
    }
    {   // v projection -> bf16 hi/lo V tile [c rows][kidx cols], pitch 72
        ull acc[8][2] = {};
        gemm_core<8, 2, PXK, 16>(v_w, Lh, Wts, acc, tid);
        __nv_bfloat16* vt = reinterpret_cast<__nv_bfloat16*>(g_vt4) + (size_t)frame * 18432;
        #pragma unroll
        for (int i = 0; i < 8; ++i) {
            int r = ty + 16 * i;
            float bias = v_b[r];
            #pragma unroll
            for (int jp = 0; jp < 2; ++jp) {
                float v0, v1; unpack2(acc[i][jp], v0, v1);
                v0 += bias; v1 += bias;
                int fl = 2 * (tx + 16 * jp);
                float h0 = bfh_f(v0), h1 = bfh_f(v1);
                *reinterpret_cast<uint32_t*>(vt + (size_t)r * 72 + fl) = bf2(h0, h1);
                *reinterpret_cast<uint32_t*>(vt + 9216 + (size_t)r * 72 + fl) = bf2(v0 - h0, v1 - h1);
            }
        }
    }
}

// ===========================================================================
// Main kernel — HMMA bf16-split, 512 threads, cp.async staging of tiles.
// ===========================================================================
__global__ void __launch_bounds__(512, 1) main_kernel(
    const float* __restrict__ side,      const float* __restrict__ basis,
    const float* __restrict__ qn_gamma,
    const float* __restrict__ qmlp_in_b, const float* __restrict__ qmlp_out_b,
    const float* __restrict__ q_b,       const float* __restrict__ o_b,
    const float* __restrict__ ffn_gamma, const float* __restrict__ ffn_in_b,
    const float* __restrict__ ffn_out_b,
    const float* __restrict__ score_scale, const float* __restrict__ prior_scale,
    const float* __restrict__ query_skip_scale,
    float* __restrict__ out)
{
    extern __shared__ char smc[];
    float* red = reinterpret_cast<float*>(smc + SRED);
    char *aHp = smc + SA_H, *aLp = smc + SA_L, *wHp = smc + SW_H;
    char *kHp = smc + SK_H, *vHp = smc + SV_H;
    float* park = reinterpret_cast<float*>(smc + SPARK);
    const uint32_t aH = smem_to_u32(aHp), aL = smem_to_u32(aLp);
    const uint32_t wH = smem_to_u32(wHp), wL = wH + 34816;
    const uint32_t kH = smem_to_u32(kHp), kL = kH + 17408;
    const uint32_t vH = smem_to_u32(vHp), vL = vH + 18432;

    const int tid = threadIdx.x, wid = tid >> 5, lane = tid & 31;
    const int wm = wid & 3, wn = wid >> 2;
    const int qr = lane >> 2, qc = (lane & 3) << 1;
    const int fc = blockIdx.x, t = blockIdx.y, b = blockIdx.z;
    const int f0 = fc * 128;
    const int frame = b * T + t;
    const char* wt = reinterpret_cast<const char*>(g_wt4);

    // async-stage K, V, W0
    cpa(kH, reinterpret_cast<const char*>(g_kt4) + (size_t)frame * 34816, 2176, tid);
    cpa(vH, reinterpret_cast<const char*>(g_vt4) + (size_t)frame * 36864, 2304, tid);
    cpa(wH, wt, 4352, tid);

    // initial A: side chunk rmsnorm
    {
        const int wg = tid >> 7, f = tid & 127, cb = wg * 32;
        float x[32];
        const float* sp = side + ((size_t)b * C * T + t) * F + f0 + f;
        #pragma unroll 8
        for (int j = 0; j < 32; ++j) x[j] = sp[(size_t)(cb + j) * (T * F)];
        float ss = 0;
        #pragma unroll
        for (int j = 0; j < 32; ++j) ss += x[j] * x[j];
        red[wg * 128 + f] = ss;
        __syncthreads();
        float rs = rsqrtf((red[f] + red[128 + f] + red[256 + f] + red[384 + f]) * (1.0f / 128.0f) + 1e-6f);
        __syncthreads();
        #pragma unroll
        for (int j = 0; j < 32; j += 2)
            stA(aHp, aLp, f, cb + j, x[j] * rs * qn_gamma[cb + j],
                x[j + 1] * rs * qn_gamma[cb + j + 1]);
    }
    CP_WAIT();
    __syncthreads();

    float query[8][4], hidden[8][4];
    float acc[8][4];
    #define ZACC() do { _Pragma("unroll") for (int _i = 0; _i < 8; ++_i) { acc[_i][0]=0;acc[_i][1]=0;acc[_i][2]=0;acc[_i][3]=0; } } while(0)

    // ---- G1: qmlp gate ----
    ZACC();
    gemm_sm<2, 4, 8>(aH, aL, wH, wL, wm * 32, wn * 32, PA, acc, lane);
    __syncthreads();
    cpa(wH, wt + 1 * 69632, 4352, tid);
    float g1[8][4];
    #pragma unroll
    for (int mt = 0; mt < 2; ++mt)
        #pragma unroll
        for (int nt = 0; nt < 4; ++nt) {
            int c = wn * 32 + nt * 8 + qc;
            float b0 = qmlp_in_b[128 + c], b1 = qmlp_in_b[129 + c];
            float* d = acc[mt * 4 + nt]; float* g = g1[mt * 4 + nt];
            g[0] = silu_f(d[0] + b0); g[1] = silu_f(d[1] + b1);
            g[2] = silu_f(d[2] + b0); g[3] = silu_f(d[3] + b1);
        }
    CP_WAIT();
    __syncthreads();

    // ---- G2: qmlp a; m -> A ----
    ZACC();
    gemm_sm<2, 4, 8>(aH, aL, wH, wL, wm * 32, wn * 32, PA, acc, lane);
    __syncthreads();
    cpa(wH, wt + 2 * 69632, 4352, tid);
    #pragma unroll
    for (int mt = 0; mt < 2; ++mt)
        #pragma unroll
        for (int nt = 0; nt < 4; ++nt) {
            int r = wm * 32 + mt * 16 + qr, c = wn * 32 + nt * 8 + qc;
            float b0 = qmlp_in_b[c], b1 = qmlp_in_b[c + 1];
            float* d = acc[mt * 4 + nt]; float* g = g1[mt * 4 + nt];
            stA(aHp, aLp, r, c, (d[0] + b0) * g[0], (d[1] + b1) * g[1]);
            stA(aHp, aLp, r + 8, c, (d[2] + b0) * g[2], (d[3] + b1) * g[3]);
        }
    CP_WAIT();
    __syncthreads();

    // ---- G3: qmlp_out -> query_h (regs + A) ----
    ZACC();
    gemm_sm<2, 4, 8>(aH, aL, wH, wL, wm * 32, wn * 32, PA, acc, lane);
    __syncthreads();
    cpa(wH, wt + 3 * 69632, 4352, tid);
    #pragma unroll
    for (int mt = 0; mt < 2; ++mt)
        #pragma unroll
        for (int nt = 0; nt < 4; ++nt) {
            int r = wm * 32 + mt * 16 + qr, c = wn * 32 + nt * 8 + qc;
            float b0 = qmlp_out_b[c], b1 = qmlp_out_b[c + 1];
            float* d = acc[mt * 4 + nt]; float* qv = query[mt * 4 + nt];
            qv[0] = d[0] + b0; qv[1] = d[1] + b1; qv[2] = d[2] + b0; qv[3] = d[3] + b1;
            stA(aHp, aLp, r, c, qv[0], qv[1]);
            stA(aHp, aLp, r + 8, c, qv[2], qv[3]);
        }
    CP_WAIT();
    __syncthreads();

    // ---- G4: q projection -> A ----
    ZACC();
    gemm_sm<2, 4, 8>(aH, aL, wH, wL, wm * 32, wn * 32, PA, acc, lane);
    __syncthreads();
    cpa(wH, wt + 4 * 69632, 4352, tid);   // o_w, awaited after G6
    #pragma unroll
    for (int mt = 0; mt < 2; ++mt)
        #pragma unroll
        for (int nt = 0; nt < 4; ++nt) {
            int r = wm * 32 + mt * 16 + qr, c = wn * 32 + nt * 8 + qc;
            float b0 = q_b[c], b1 = q_b[c + 1];
            float* d = acc[mt * 4 + nt];
            stA(aHp, aLp, r, c, d[0] + b0, d[1] + b1);
            stA(aHp, aLp, r + 8, c, d[2] + b0, d[3] + b1);
        }
    __syncthreads();

    // ---- G5: scores + softmax (warps 0-7; each owns its 16 A rows) ----
    if (wid < 8) {
        float sacc[8][4];
        #pragma unroll
        for (int i = 0; i < 8; ++i) { sacc[i][0]=0;sacc[i][1]=0;sacc[i][2]=0;sacc[i][3]=0; }
        gemm_sm<1, 8, 8>(aH, aL, kH, kL, wid * 16, 0, PA, sacc, lane);
        const float ssc = *score_scale, psc = *prior_scale;
        const int fgA = f0 + wid * 16 + qr, fgB = fgA + 8;
        float p0[16], p1[16];
        #pragma unroll
        for (int nt = 0; nt < 8; ++nt) {
            int k0 = nt * 8 + qc;
            p0[nt * 2 + 0] = sacc[nt][0] * ssc + basis[(size_t)k0 * F + fgA] * psc;
            p0[nt * 2 + 1] = sacc[nt][1] * ssc + basis[(size_t)(k0 + 1) * F + fgA] * psc;
            p1[nt * 2 + 0] = sacc[nt][2] * ssc + basis[(size_t)k0 * F + fgB] * psc;
            p1[nt * 2 + 1] = sacc[nt][3] * ssc + basis[(size_t)(k0 + 1) * F + fgB] * psc;
        }
        float m0 = p0[0], m1 = p1[0];
        #pragma unroll
        for (int i = 1; i < 16; ++i) { m0 = fmaxf(m0, p0[i]); m1 = fmaxf(m1, p1[i]); }
        m0 = fmaxf(m0, __shfl_xor_sync(0xffffffffu, m0, 1));
        m0 = fmaxf(m0, __shfl_xor_sync(0xffffffffu, m0, 2));
        m1 = fmaxf(m1, __shfl_xor_sync(0xffffffffu, m1, 1));
        m1 = fmaxf(m1, __shfl_xor_sync(0xffffffffu, m1, 2));
        float s0 = 0, s1 = 0;
        #pragma unroll
        for (int i = 0; i < 16; ++i) {
            p0[i] = __expf(p0[i] - m0); s0 += p0[i];
            p1[i] = __expf(p1[i] - m1); s1 += p1[i];
        }
        s0 += __shfl_xor_sync(0xffffffffu, s0, 1); s0 += __shfl_xor_sync(0xffffffffu, s0, 2);
        s1 += __shfl_xor_sync(0xffffffffu, s1, 1); s1 += __shfl_xor_sync(0xffffffffu, s1, 2);
        float i0 = __frcp_rn(s0), i1 = __frcp_rn(s1);
        #pragma unroll
        for (int nt = 0; nt < 8; ++nt) {
            int c = nt * 8 + qc;
            stA(aHp, aLp, wid * 16 + qr, c, p0[2 * nt] * i0, p0[2 * nt + 1] * i0);
            stA(aHp, aLp, wid * 16 + qr + 8, c, p1[2 * nt] * i1, p1[2 * nt + 1] * i1);
        }
    }
    __syncthreads();

    // ---- G6: attended = P @ V ----
    ZACC();
    gemm_sm<2, 4, 4>(aH, aL, vH, vL, wm * 32, wn * 32, PV, acc, lane);
    __syncthreads();
    #pragma unroll
    for (int mt = 0; mt < 2; ++mt)
        #pragma unroll
        for (int nt = 0; nt < 4; ++nt) {
            int r = wm * 32 + mt * 16 + qr, c = wn * 32 + nt * 8 + qc;
            float* d = acc[mt * 4 + nt];
            stA(aHp, aLp, r, c, d[0], d[1]);
            stA(aHp, aLp, r + 8, c, d[2], d[3]);
        }
    CP_WAIT();   // o_w landed
    __syncthreads();

    // ---- G7: o_w; hidden = d + o_b + qss*query; rmsnorm -> A ----
    ZACC();
    gemm_sm<2, 4, 8>(aH, aL, wH, wL, wm * 32, wn * 32, PA, acc, lane);
    __syncthreads();
    cpa(wH, wt + 5 * 69632, 4352, tid);
    {
        const float qs = *query_skip_scale;
        float ss[2][2] = {};
        #pragma unroll
        for (int mt = 0; mt < 2; ++mt)
            #pragma unroll
            for (int nt = 0; nt < 4; ++nt) {
                int c = wn * 32 + nt * 8 + qc;
                float b0 = o_b[c], b1 = o_b[c + 1];
                float* d = acc[mt * 4 + nt]; float* h = hidden[mt * 4 + nt];
                float* qv = query[mt * 4 + nt];
                h[0] = d[0] + b0 + qs * qv[0]; h[1] = d[1] + b1 + qs * qv[1];
                h[2] = d[2] + b0 + qs * qv[2]; h[3] = d[3] + b1 + qs * qv[3];
                ss[mt][0] += h[0] * h[0] + h[1] * h[1];
                ss[mt][1] += h[2] * h[2] + h[3] * h[3];
            }
        #pragma unroll
        for (int mt = 0; mt < 2; ++mt)
            #pragma unroll
            for (int rw = 0; rw < 2; ++rw) {
                float v = ss[mt][rw];
                v += __shfl_xor_sync(0xffffffffu, v, 1);
                v += __shfl_xor_sync(0xffffffffu, v, 2);
                if ((lane & 3) == 0)
                    red[(wm * 32 + mt * 16 + qr + rw * 8) * 4 + wn] = v;
            }
        __syncthreads();
        float rs_[2][2];
        #pragma unroll
        for (int mt = 0; mt < 2; ++mt)
            #pragma unroll
            for (int rw = 0; rw < 2; ++rw) {
                int r = wm * 32 + mt * 16 + qr + rw * 8;
                float s = red[r * 4] + red[r * 4 + 1] + red[r * 4 + 2] + red[r * 4 + 3];
                rs_[mt][rw] = rsqrtf(s * (1.0f / 128.0f) + 1e-6f);
            }
        #pragma unroll
        for (int mt = 0; mt < 2; ++mt)
            #pragma unroll
            for (int nt = 0; nt < 4; ++nt) {
                int r = wm * 32 + mt * 16 + qr, c = wn * 32 + nt * 8 + qc;
                float g0 = ffn_gamma[c], g1 = ffn_gamma[c + 1];
                float* h = hidden[mt * 4 + nt];
                stA(aHp, aLp, r, c, h[0] * rs_[mt][0] * g0, h[1] * rs_[mt][0] * g1);
                stA(aHp, aLp, r + 8, c, h[2] * rs_[mt][1] * g0, h[3] * rs_[mt][1] * g1);
            }
    }
    CP_WAIT();
    __syncthreads();

    // ---- G8: ffn gate -> park (K/V region dead) ----
    ZACC();
    gemm_sm<2, 4, 8>(aH, aL, wH, wL, wm * 32, wn * 32, PA, acc, lane);
    __syncthreads();
    cpa(wH, wt + 6 * 69632, 4352, tid);
    #pragma unroll
    for (int mt = 0; mt < 2; ++mt)
        #pragma unroll
        for (int nt = 0; nt < 4; ++nt) {
            int r = wm * 32 + mt * 16 + qr, c = wn * 32 + nt * 8 + qc;
            float b0 = ffn_in_b[128 + c], b1 = ffn_in_b[129 + c];
            float* d = acc[mt * 4 + nt];
            *reinterpret_cast<float2*>(park + r * 132 + c) =
                make_float2(silu_f(d[0] + b0), silu_f(d[1] + b1));
            *reinterpret_cast<float2*>(park + (r + 8) * 132 + c) =
                make_float2(silu_f(d[2] + b0), silu_f(d[3] + b1));
        }
    CP_WAIT();
    __syncthreads();

    // ---- G9: ffn a; m2 = (a+b)*g -> A ----
    ZACC();
    gemm_sm<2, 4, 8>(aH, aL, wH, wL, wm * 32, wn * 32, PA, acc, lane);
    __syncthreads();
    cpa(wH, wt + 7 * 69632, 4352, tid);
    #pragma unroll
    for (int mt = 0; mt < 2; ++mt)
        #pragma unroll
        for (int nt = 0; nt < 4; ++nt) {
            int r = wm * 32 + mt * 16 + qr, c = wn * 32 + nt * 8 + qc;
            float b0 = ffn_in_b[c], b1 = ffn_in_b[c + 1];
            float* d = acc[mt * 4 + nt];
            float2 ga = *reinterpret_cast<float2*>(park + r * 132 + c);
            float2 gb = *reinterpret_cast<float2*>(park + (r + 8) * 132 + c);
            stA(aHp, aLp, r, c, (d[0] + b0) * ga.x, (d[1] + b1) * ga.y);
            stA(aHp, aLp, r + 8, c, (d[2] + b0) * gb.x, (d[3] + b1) * gb.y);
        }
    CP_WAIT();
    __syncthreads();

    // ---- G10: ffn_out; out = d + b + hidden -> global ----
    ZACC();
    gemm_sm<2, 4, 8>(aH, aL, wH, wL, wm * 32, wn * 32, PA, acc, lane);
    {
        float* ob = out + ((size_t)b * C * T + t) * F + f0;
        #pragma unroll
        for (int mt = 0; mt < 2; ++mt)
            #pragma unroll
            for (int nt = 0; nt < 4; ++nt) {
                int r = wm * 32 + mt * 16 + qr, c = wn * 32 + nt * 8 + qc;
                float b0 = ffn_out_b[c], b1 = ffn_out_b[c + 1];
                float* d = acc[mt * 4 + nt]; float* h = hidden[mt * 4 + nt];
                ob[(size_t)c * (T * F) + r]           = d[0] + b0 + h[0];
                ob[(size_t)(c + 1) * (T * F) + r]     = d[1] + b1 + h[1];
                ob[(size_t)c * (T * F) + r + 8]       = d[2] + b0 + h[2];
                ob[(size_t)(c + 1) * (T * F) + r + 8] = d[3] + b1 + h[3];
            }
    }
    #undef ZACC
}

// ---------------------------------------------------------------------------
extern "C" void kernel_launch(void* const* d_in, const int* in_sizes, int n_in,
                              void* d_out, int out_size)
{
    const float* latent      = (const float*)d_in[0];
    const float* side        = (const float*)d_in[1];
    const float* basis       = (const float*)d_in[2];
    const float* lp_gamma    = (const float*)d_in[3];
    const float* lp_w        = (const float*)d_in[4];
    const float* lp_b        = (const float*)d_in[5];
    const float* qn_gamma    = (const float*)d_in[6];
    const float* qmlp_in_w   = (const float*)d_in[7];
    const float* qmlp_in_b   = (const float*)d_in[8];
    const float* qmlp_out_w  = (const float*)d_in[9];
    const float* qmlp_out_b  = (const float*)d_in[10];
    const float* q_w         = (const float*)d_in[11];
    const float* q_b         = (const float*)d_in[12];
    const float* k_w         = (const float*)d_in[13];
    const float* k_b         = (const float*)d_in[14];
    const float* v_w         = (const float*)d_in[15];
    const float* v_b         = (const float*)d_in[16];
    const float* o_w         = (const float*)d_in[17];
    const float* o_b         = (const float*)d_in[18];
    const float* ffn_gamma   = (const float*)d_in[19];
    const float* ffn_in_w    = (const float*)d_in[20];
    const float* ffn_in_b    = (const float*)d_in[21];
    const float* ffn_out_w   = (const float*)d_in[22];
    const float* ffn_out_b   = (const float*)d_in[23];
    const float* score_scale = (const float*)d_in[24];
    const float* prior_scale = (const float*)d_in[25];
    const float* qss         = (const float*)d_in[26];
    float* out = (float*)d_out;

    cudaFuncSetAttribute(latent_kernel, cudaFuncAttributeMaxDynamicSharedMemorySize, K1_SMEM_BYTES);
    cudaFuncSetAttribute(main_kernel,   cudaFuncAttributeMaxDynamicSharedMemorySize, K2_SMEM_BYTES);

    prep_kernel<<<8, 256>>>(qmlp_in_w, qmlp_out_w, q_w, o_w, ffn_in_w, ffn_out_w);

    latent_kernel<<<B * T, 256, K1_SMEM_BYTES>>>(
        latent, lp_gamma, lp_w, lp_b, k_w, k_b, v_w, v_b);

    main_kernel<<<dim3(F / 128, T, B), 512, K2_SMEM_BYTES>>>(
        side, basis, qn_gamma,
        qmlp_in_b, qmlp_out_b, q_b, o_b,
        ffn_gamma, ffn_in_b, ffn_out_b,
        score_scale, prior_scale, qss, out);
}

// round 13
// speedup vs baseline: 3.4303x; 1.1188x over previous
#include <cuda_runtime.h>
#include <cuda_bf16.h>
#include <cstdint>
#include <math.h>

typedef unsigned long long ull;

static constexpr int B = 8, C = 128, T = 128, F = 512, K = 64;

// pre-converted bf16 hi/lo tiles (smem-identical layout)
// weights: 11 tiles x [hi 128x136][lo 128x136]
__device__ uint4 g_wt4[11 * 69632 / 16];
// K tiles: per frame [hi 64x136][lo 64x136] (rows = kidx, cols = c)
__device__ uint4 g_kt4[(size_t)1024 * 2176];
// V tiles: per frame [hi 128x72][lo 128x72] (rows = c, cols = kidx)
__device__ uint4 g_vt4[(size_t)1024 * 2304];

__device__ __forceinline__ float silu_f(float g) {
    float e = __expf(-g);
    return __fdividef(g, 1.0f + e);
}
__device__ __forceinline__ uint32_t smem_to_u32(const void* p) {
    uint32_t a;
    asm("{ .reg .u64 t; cvta.to.shared.u64 t, %1; cvt.u32.u64 %0, t; }" : "=r"(a) : "l"(p));
    return a;
}
__device__ __forceinline__ void ldsm4(uint32_t* r, uint32_t addr) {
    asm volatile("ldmatrix.sync.aligned.m8n8.x4.shared.b16 {%0,%1,%2,%3}, [%4];"
        : "=r"(r[0]), "=r"(r[1]), "=r"(r[2]), "=r"(r[3]) : "r"(addr));
}
__device__ __forceinline__ void mma16816(float* d, const uint32_t* a, const uint32_t* b) {
    asm volatile("mma.sync.aligned.m16n8k16.row.col.f32.bf16.bf16.f32 "
        "{%0,%1,%2,%3},{%4,%5,%6,%7},{%8,%9},{%0,%1,%2,%3};"
        : "+f"(d[0]), "+f"(d[1]), "+f"(d[2]), "+f"(d[3])
        : "r"(a[0]), "r"(a[1]), "r"(a[2]), "r"(a[3]), "r"(b[0]), "r"(b[1]));
}
__device__ __forceinline__ float bfh_f(float x) { return __bfloat162float(__float2bfloat16(x)); }
__device__ __forceinline__ uint32_t bf2(float lo, float hi) {
    uint32_t r;
    asm("cvt.rn.satfinite.bf16x2.f32 %0, %1, %2;" : "=r"(r) : "f"(hi), "f"(lo));
    return r;
}
// cp.async: nchunks 16B copies from global to smem, one commit group
__device__ __forceinline__ void cpa(uint32_t sdst, const void* gsrc, int nchunks,
                                    int start, int stride) {
    const char* gp = (const char*)gsrc;
    for (int i = start; i < nchunks; i += stride)
        asm volatile("cp.async.cg.shared.global [%0], [%1], 16;"
                     :: "r"(sdst + 16u * i), "l"(gp + 16 * i));
    asm volatile("cp.async.commit_group;" ::: "memory");
}
#define CP_WAIT() asm volatile("cp.async.wait_group 0;" ::: "memory")

static constexpr int PA = 272;   // bytes, 136 bf16
static constexpr int PV = 144;   // bytes, 72 bf16

__device__ __forceinline__ void stA(char* aHp, char* aLp, int r, int c, float x0, float x1) {
    float h0 = bfh_f(x0), h1 = bfh_f(x1);
    *reinterpret_cast<uint32_t*>(aHp + r * PA + c * 2) = bf2(h0, h1);
    *reinterpret_cast<uint32_t*>(aLp + r * PA + c * 2) = bf2(x0 - h0, x1 - h1);
}

// smem-A x smem-B bf16-split GEMM (3 passes), row.col, acc fp32
template <int MT, int NT, int KT>
__device__ __forceinline__ void gemm_sm(uint32_t aH, uint32_t aL, uint32_t bH, uint32_t bL,
                                        int mbase, int nbase, int pitchB,
                                        float (*acc)[4], int lane) {
    #pragma unroll
    for (int kt = 0; kt < KT; ++kt) {
        uint32_t ah[MT][4], al[MT][4];
        int q = lane >> 3;
        #pragma unroll
        for (int mt = 0; mt < MT; ++mt) {
            int row = mbase + mt * 16 + ((q & 1) << 3) + (lane & 7);
            uint32_t ad = (uint32_t)(row * PA + kt * 32 + ((q >> 1) << 4));
            ldsm4(ah[mt], aH + ad);
            ldsm4(al[mt], aL + ad);
        }
        uint32_t bh[NT / 2][4], bl[NT / 2][4];
        #pragma unroll
        for (int p = 0; p < NT / 2; ++p) {
            int row = nbase + p * 16 + ((lane >> 4) << 3) + (lane & 7);
            uint32_t bd = (uint32_t)(row * pitchB + kt * 32 + (((lane >> 3) & 1) << 4));
            ldsm4(bh[p], bH + bd);
            ldsm4(bl[p], bL + bd);
        }
        #pragma unroll
        for (int mt = 0; mt < MT; ++mt)
            #pragma unroll
            for (int nt = 0; nt < NT; ++nt) {
                float* d = acc[mt * NT + nt];
                uint32_t fh[2] = { bh[nt >> 1][(nt & 1) * 2], bh[nt >> 1][(nt & 1) * 2 + 1] };
                uint32_t fl[2] = { bl[nt >> 1][(nt & 1) * 2], bl[nt >> 1][(nt & 1) * 2 + 1] };
                mma16816(d, ah[mt], fh);
                mma16816(d, ah[mt], fl);
                mma16816(d, al[mt], fh);
            }
    }
}

// ===========================================================================
// Prep kernel — convert 11 weight tiles to bf16 hi/lo tile layout (once)
// ===========================================================================
__global__ void prep_kernel(
    const float* __restrict__ qmlp_in_w, const float* __restrict__ qmlp_out_w,
    const float* __restrict__ q_w,       const float* __restrict__ o_w,
    const float* __restrict__ ffn_in_w,  const float* __restrict__ ffn_out_w,
    const float* __restrict__ lp_w,      const float* __restrict__ k_w,
    const float* __restrict__ v_w)
{
    const int bid = blockIdx.x, tid = threadIdx.x;
    const float* src;
    switch (bid) {
        case 0: src = qmlp_in_w + 16384; break;
        case 1: src = qmlp_in_w; break;
        case 2: src = qmlp_out_w; break;
        case 3: src = q_w; break;
        case 4: src = o_w; break;
        case 5: src = ffn_in_w + 16384; break;
        case 6: src = ffn_in_w; break;
        case 7: src = ffn_out_w; break;
        case 8: src = lp_w; break;
        case 9: src = k_w; break;
        default: src = v_w; break;
    }
    __nv_bfloat16* dh = reinterpret_cast<__nv_bfloat16*>(g_wt4) + (size_t)bid * 34816;
    __nv_bfloat16* dl = dh + 17408;
    for (int i = tid; i < 128 * 32; i += 256) {
        int r = i >> 5, c4 = (i & 31) << 2;
        float4 w = *reinterpret_cast<const float4*>(src + r * 128 + c4);
        float h0 = bfh_f(w.x), h1 = bfh_f(w.y), h2 = bfh_f(w.z), h3 = bfh_f(w.w);
        *reinterpret_cast<uint32_t*>(dh + r * 136 + c4)     = bf2(h0, h1);
        *reinterpret_cast<uint32_t*>(dh + r * 136 + c4 + 2) = bf2(h2, h3);
        *reinterpret_cast<uint32_t*>(dl + r * 136 + c4)     = bf2(w.x - h0, w.y - h1);
        *reinterpret_cast<uint32_t*>(dl + r * 136 + c4 + 2) = bf2(w.z - h2, w.w - h3);
    }
}

// ===========================================================================
// Latent kernel — HMMA bf16-split, 256 threads (8 warps), 2 CTAs/SM.
// A = latent^T [kpos=64 rows][c=128 cols]; warp (wm=wid&3, wn=wid>>2):
// rows 16*wm, cols 64*wn (MT=1, NT=8).
// ===========================================================================
static constexpr int L_RED = 0;               // 1024 B
static constexpr int L_AH = 1024;
static constexpr int L_AL = L_AH + 17408;     // 18432
static constexpr int L_WH = L_AL + 17408;     // 35840
static constexpr int K1_SMEM_BYTES = L_WH + 69632;   // 105472

__global__ void __launch_bounds__(256, 2) latent_kernel(
    const float* __restrict__ latent, const float* __restrict__ lp_gamma,
    const float* __restrict__ lp_b,   const float* __restrict__ k_b,
    const float* __restrict__ v_b)
{
    extern __shared__ char smc[];
    float* red = reinterpret_cast<float*>(smc + L_RED);
    char *aHp = smc + L_AH, *aLp = smc + L_AL, *wHp = smc + L_WH;
    const uint32_t aH = smem_to_u32(aHp), aL = smem_to_u32(aLp);
    const uint32_t wH = smem_to_u32(wHp), wL = wH + 34816;

    const int tid = threadIdx.x, wid = tid >> 5, lane = tid & 31;
    const int wm = wid & 3, wn = wid >> 2;
    const int qr = lane >> 2, qc = (lane & 3) << 1;
    const int frame = blockIdx.x;
    const int b = frame / T, t = frame % T;
    const char* wt = reinterpret_cast<const char*>(g_wt4);

    cpa(wH, wt + 8 * 69632, 4352, tid, 256);   // lp_w

    // stage A = rmsnorm(latent)^T : row kp (0..63), cols c
    {
        const int kp = tid & 63, grp = tid >> 6, cb = grp * 32;
        float x[32];
        const float* sp = latent + ((size_t)(b * C + cb) * T + t) * K + kp;
        #pragma unroll 8
        for (int j = 0; j < 32; ++j) x[j] = sp[(size_t)j * (T * K)];
        float ss = 0;
        #pragma unroll
        for (int j = 0; j < 32; ++j) ss += x[j] * x[j];
        red[grp * 64 + kp] = ss;
        __syncthreads();
        float rs = rsqrtf((red[kp] + red[64 + kp] + red[128 + kp] + red[192 + kp]) * (1.0f / 128.0f) + 1e-6f);
        __syncthreads();
        #pragma unroll
        for (int j = 0; j < 32; j += 2)
            stA(aHp, aLp, kp, cb + j, x[j] * rs * lp_gamma[cb + j],
                x[j + 1] * rs * lp_gamma[cb + j + 1]);
    }
    CP_WAIT();
    __syncthreads();

    float acc[8][4];
    #define ZAC() do { _Pragma("unroll") for (int _i = 0; _i < 8; ++_i) { acc[_i][0]=0;acc[_i][1]=0;acc[_i][2]=0;acc[_i][3]=0; } } while(0)

    // G_lp: latent_h^T = silu(Xn^T @ lp_w^T) -> A (in place)
    ZAC();
    gemm_sm<1, 8, 8>(aH, aL, wH, wL, wm * 16, wn * 64, PA, acc, lane);
    __syncthreads();
    cpa(wH, wt + 9 * 69632, 4352, tid, 256);   // k_w
    #pragma unroll
    for (int nt = 0; nt < 8; ++nt) {
        int r = wm * 16 + qr, c = wn * 64 + nt * 8 + qc;
        float b0 = lp_b[c], b1 = lp_b[c + 1];
        float* d = acc[nt];
        stA(aHp, aLp, r, c, silu_f(d[0] + b0), silu_f(d[1] + b1));
        stA(aHp, aLp, r + 8, c, silu_f(d[2] + b0), silu_f(d[3] + b1));
    }
    CP_WAIT();
    __syncthreads();

    // G_k: k^T [kpos][c_out] -> global K tile (hi/lo, pitch 136)
    ZAC();
    gemm_sm<1, 8, 8>(aH, aL, wH, wL, wm * 16, wn * 64, PA, acc, lane);
    __syncthreads();
    cpa(wH, wt + 10 * 69632, 4352, tid, 256);  // v_w
    {
        __nv_bfloat16* ktg = reinterpret_cast<__nv_bfloat16*>(g_kt4) + (size_t)frame * 17408;
        #pragma unroll
        for (int nt = 0; nt < 8; ++nt) {
            int c = wn * 64 + nt * 8 + qc;
            float b0 = k_b[c], b1 = k_b[c + 1];
            float* d = acc[nt];
            #pragma unroll
            for (int rw = 0; rw < 2; ++rw) {
                int r = wm * 16 + qr + rw * 8;
                float v0 = d[2 * rw] + b0, v1 = d[2 * rw + 1] + b1;
                float h0 = bfh_f(v0), h1 = bfh_f(v1);
                *reinterpret_cast<uint32_t*>(ktg + (size_t)r * 136 + c) = bf2(h0, h1);
                *reinterpret_cast<uint32_t*>(ktg + 8704 + (size_t)r * 136 + c) = bf2(v0 - h0, v1 - h1);
            }
        }
    }
    CP_WAIT();
    __syncthreads();

    // G_v: v^T [kpos][c_out] -> global V tile TRANSPOSED [c][kidx] (pitch 72)
    ZAC();
    gemm_sm<1, 8, 8>(aH, aL, wH, wL, wm * 16, wn * 64, PA, acc, lane);
    {
        __nv_bfloat16* vtg = reinterpret_cast<__nv_bfloat16*>(g_vt4) + (size_t)frame * 18432;
        #pragma unroll
        for (int nt = 0; nt < 8; ++nt) {
            int c = wn * 64 + nt * 8 + qc;
            float b0 = v_b[c], b1 = v_b[c + 1];
            float* d = acc[nt];
            #pragma unroll
            for (int rw = 0; rw < 2; ++rw) {
                int r = wm * 16 + qr + rw * 8;
                float v0 = d[2 * rw] + b0, v1 = d[2 * rw + 1] + b1;
                float h0 = bfh_f(v0), h1 = bfh_f(v1);
                vtg[(size_t)c * 72 + r]       = __float2bfloat16(h0);
                vtg[(size_t)(c + 1) * 72 + r] = __float2bfloat16(h1);
                vtg[9216 + (size_t)c * 72 + r]       = __float2bfloat16(v0 - h0);
                vtg[9216 + (size_t)(c + 1) * 72 + r] = __float2bfloat16(v1 - h1);
            }
        }
    }
    #undef ZAC
}

// ===========================================================================
// Main kernel — HMMA bf16-split, 512 threads, cp.async staging (unchanged R12).
// ===========================================================================
static constexpr int SRED = 0;                 // 2048 B
static constexpr int SA_H = 2048;
static constexpr int SA_L = SA_H + 34816;
static constexpr int SW_H = SA_L + 34816;
static constexpr int SK_H = SW_H + 69632;      // K hi then lo
static constexpr int SV_H = SK_H + 34816;      // V hi then lo
static constexpr int K2_SMEM_BYTES = SV_H + 36864;   // 212992
static constexpr int SPARK = SK_H;             // fp32 [128][132] overlay

__global__ void __launch_bounds__(512, 1) main_kernel(
    const float* __restrict__ side,      const float* __restrict__ basis,
    const float* __restrict__ qn_gamma,
    const float* __restrict__ qmlp_in_b, const float* __restrict__ qmlp_out_b,
    const float* __restrict__ q_b,       const float* __restrict__ o_b,
    const float* __restrict__ ffn_gamma, const float* __restrict__ ffn_in_b,
    const float* __restrict__ ffn_out_b,
    const float* __restrict__ score_scale, const float* __restrict__ prior_scale,
    const float* __restrict__ query_skip_scale,
    float* __restrict__ out)
{
    extern __shared__ char smc[];
    float* red = reinterpret_cast<float*>(smc + SRED);
    char *aHp = smc + SA_H, *aLp = smc + SA_L, *wHp = smc + SW_H;
    char *kHp = smc + SK_H, *vHp = smc + SV_H;
    float* park = reinterpret_cast<float*>(smc + SPARK);
    const uint32_t aH = smem_to_u32(aHp), aL = smem_to_u32(aLp);
    const uint32_t wH = smem_to_u32(wHp), wL = wH + 34816;
    const uint32_t kH = smem_to_u32(kHp), kL = kH + 17408;
    const uint32_t vH = smem_to_u32(vHp), vL = vH + 18432;

    const int tid = threadIdx.x, wid = tid >> 5, lane = tid & 31;
    const int wm = wid & 3, wn = wid >> 2;
    const int qr = lane >> 2, qc = (lane & 3) << 1;
    const int fc = blockIdx.x, t = blockIdx.y, b = blockIdx.z;
    const int f0 = fc * 128;
    const int frame = b * T + t;
    const char* wt = reinterpret_cast<const char*>(g_wt4);

    cpa(kH, reinterpret_cast<const char*>(g_kt4) + (size_t)frame * 34816, 2176, tid, 512);
    cpa(vH, reinterpret_cast<const char*>(g_vt4) + (size_t)frame * 36864, 2304, tid, 512);
    cpa(wH, wt, 4352, tid, 512);

    // initial A: side chunk rmsnorm
    {
        const int wg = tid >> 7, f = tid & 127, cb = wg * 32;
        float x[32];
        const float* sp = side + ((size_t)b * C * T + t) * F + f0 + f;
        #pragma unroll 8
        for (int j = 0; j < 32; ++j) x[j] = sp[(size_t)(cb + j) * (T * F)];
        float ss = 0;
        #pragma unroll
        for (int j = 0; j < 32; ++j) ss += x[j] * x[j];
        red[wg * 128 + f] = ss;
        __syncthreads();
        float rs = rsqrtf((red[f] + red[128 + f] + red[256 + f] + red[384 + f]) * (1.0f / 128.0f) + 1e-6f);
        __syncthreads();
        #pragma unroll
        for (int j = 0; j < 32; j += 2)
            stA(aHp, aLp, f, cb + j, x[j] * rs * qn_gamma[cb + j],
                x[j + 1] * rs * qn_gamma[cb + j + 1]);
    }
    CP_WAIT();
    __syncthreads();

    float query[8][4], hidden[8][4];
    float acc[8][4];
    #define ZACC() do { _Pragma("unroll") for (int _i = 0; _i < 8; ++_i) { acc[_i][0]=0;acc[_i][1]=0;acc[_i][2]=0;acc[_i][3]=0; } } while(0)

    // ---- G1: qmlp gate ----
    ZACC();
    gemm_sm<2, 4, 8>(aH, aL, wH, wL, wm * 32, wn * 32, PA, acc, lane);
    __syncthreads();
    cpa(wH, wt + 1 * 69632, 4352, tid, 512);
    float g1[8][4];
    #pragma unroll
    for (int mt = 0; mt < 2; ++mt)
        #pragma unroll
        for (int nt = 0; nt < 4; ++nt) {
            int c = wn * 32 + nt * 8 + qc;
            float b0 = qmlp_in_b[128 + c], b1 = qmlp_in_b[129 + c];
            float* d = acc[mt * 4 + nt]; float* g = g1[mt * 4 + nt];
            g[0] = silu_f(d[0] + b0); g[1] = silu_f(d[1] + b1);
            g[2] = silu_f(d[2] + b0); g[3] = silu_f(d[3] + b1);
        }
    CP_WAIT();
    __syncthreads();

    // ---- G2: qmlp a; m -> A ----
    ZACC();
    gemm_sm<2, 4, 8>(aH, aL, wH, wL, wm * 32, wn * 32, PA, acc, lane);
    __syncthreads();
    cpa(wH, wt + 2 * 69632, 4352, tid, 512);
    #pragma unroll
    for (int mt = 0; mt < 2; ++mt)
        #pragma unroll
        for (int nt = 0; nt < 4; ++nt) {
            int r = wm * 32 + mt * 16 + qr, c = wn * 32 + nt * 8 + qc;
            float b0 = qmlp_in_b[c], b1 = qmlp_in_b[c + 1];
            float* d = acc[mt * 4 + nt]; float* g = g1[mt * 4 + nt];
            stA(aHp, aLp, r, c, (d[0] + b0) * g[0], (d[1] + b1) * g[1]);
            stA(aHp, aLp, r + 8, c, (d[2] + b0) * g[2], (d[3] + b1) * g[3]);
        }
    CP_WAIT();
    __syncthreads();

    // ---- G3: qmlp_out -> query_h (regs + A) ----
    ZACC();
    gemm_sm<2, 4, 8>(aH, aL, wH, wL, wm * 32, wn * 32, PA, acc, lane);
    __syncthreads();
    cpa(wH, wt + 3 * 69632, 4352, tid, 512);
    #pragma unroll
    for (int mt = 0; mt < 2; ++mt)
        #pragma unroll
        for (int nt = 0; nt < 4; ++nt) {
            int r = wm * 32 + mt * 16 + qr, c = wn * 32 + nt * 8 + qc;
            float b0 = qmlp_out_b[c], b1 = qmlp_out_b[c + 1];
            float* d = acc[mt * 4 + nt]; float* qv = query[mt * 4 + nt];
            qv[0] = d[0] + b0; qv[1] = d[1] + b1; qv[2] = d[2] + b0; qv[3] = d[3] + b1;
            stA(aHp, aLp, r, c, qv[0], qv[1]);
            stA(aHp, aLp, r + 8, c, qv[2], qv[3]);
        }
    CP_WAIT();
    __syncthreads();

    // ---- G4: q projection -> A ----
    ZACC();
    gemm_sm<2, 4, 8>(aH, aL, wH, wL, wm * 32, wn * 32, PA, acc, lane);
    __syncthreads();
    cpa(wH, wt + 4 * 69632, 4352, tid, 512);   // o_w, awaited after G6
    #pragma unroll
    for (int mt = 0; mt < 2; ++mt)
        #pragma unroll
        for (int nt = 0; nt < 4; ++nt) {
            int r = wm * 32 + mt * 16 + qr, c = wn * 32 + nt * 8 + qc;
            float b0 = q_b[c], b1 = q_b[c + 1];
            float* d = acc[mt * 4 + nt];
            stA(aHp, aLp, r, c, d[0] + b0, d[1] + b1);
            stA(aHp, aLp, r + 8, c, d[2] + b0, d[3] + b1);
        }
    __syncthreads();

    // ---- G5: scores + softmax (warps 0-7; each owns its 16 A rows) ----
    if (wid < 8) {
        float sacc[8][4];
        #pragma unroll
        for (int i = 0; i < 8; ++i) { sacc[i][0]=0;sacc[i][1]=0;sacc[i][2]=0;sacc[i][3]=0; }
        gemm_sm<1, 8, 8>(aH, aL, kH, kL, wid * 16, 0, PA, sacc, lane);
        const float ssc = *score_scale, psc = *prior_scale;
        const int fgA = f0 + wid * 16 + qr, fgB = fgA + 8;
        float p0[16], p1[16];
        #pragma unroll
        for (int nt = 0; nt < 8; ++nt) {
            int k0 = nt * 8 + qc;
            p0[nt * 2 + 0] = sacc[nt][0] * ssc + basis[(size_t)k0 * F + fgA] * psc;
            p0[nt * 2 + 1] = sacc[nt][1] * ssc + basis[(size_t)(k0 + 1) * F + fgA] * psc;
            p1[nt * 2 + 0] = sacc[nt][2] * ssc + basis[(size_t)k0 * F + fgB] * psc;
            p1[nt * 2 + 1] = sacc[nt][3] * ssc + basis[(size_t)(k0 + 1) * F + fgB] * psc;
        }
        float m0 = p0[0], m1 = p1[0];
        #pragma unroll
        for (int i = 1; i < 16; ++i) { m0 = fmaxf(m0, p0[i]); m1 = fmaxf(m1, p1[i]); }
        m0 = fmaxf(m0, __shfl_xor_sync(0xffffffffu, m0, 1));
        m0 = fmaxf(m0, __shfl_xor_sync(0xffffffffu, m0, 2));
        m1 = fmaxf(m1, __shfl_xor_sync(0xffffffffu, m1, 1));
        m1 = fmaxf(m1, __shfl_xor_sync(0xffffffffu, m1, 2));
        float s0 = 0, s1 = 0;
        #pragma unroll
        for (int i = 0; i < 16; ++i) {
            p0[i] = __expf(p0[i] - m0); s0 += p0[i];
            p1[i] = __expf(p1[i] - m1); s1 += p1[i];
        }
        s0 += __shfl_xor_sync(0xffffffffu, s0, 1); s0 += __shfl_xor_sync(0xffffffffu, s0, 2);
        s1 += __shfl_xor_sync(0xffffffffu, s1, 1); s1 += __shfl_xor_sync(0xffffffffu, s1, 2);
        float i0 = __frcp_rn(s0), i1 = __frcp_rn(s1);
        #pragma unroll
        for (int nt = 0; nt < 8; ++nt) {
            int c = nt * 8 + qc;
            stA(aHp, aLp, wid * 16 + qr, c, p0[2 * nt] * i0, p0[2 * nt + 1] * i0);
            stA(aHp, aLp, wid * 16 + qr + 8, c, p1[2 * nt] * i1, p1[2 * nt + 1] * i1);
        }
    }
    __syncthreads();

    // ---- G6: attended = P @ V ----
    ZACC();
    gemm_sm<2, 4, 4>(aH, aL, vH, vL, wm * 32, wn * 32, PV, acc, lane);
    __syncthreads();
    #pragma unroll
    for (int mt = 0; mt < 2; ++mt)
        #pragma unroll
        for (int nt = 0; nt < 4; ++nt) {
            int r = wm * 32 + mt * 16 + qr, c = wn * 32 + nt * 8 + qc;
            float* d = acc[mt * 4 + nt];
            stA(aHp, aLp, r, c, d[0], d[1]);
            stA(aHp, aLp, r + 8, c, d[2], d[3]);
        }
    CP_WAIT();   // o_w landed
    __syncthreads();

    // ---- G7: o_w; hidden = d + o_b + qss*query; rmsnorm -> A ----
    ZACC();
    gemm_sm<2, 4, 8>(aH, aL, wH, wL, wm * 32, wn * 32, PA, acc, lane);
    __syncthreads();
    cpa(wH, wt + 5 * 69632, 4352, tid, 512);
    {
        const float qs = *query_skip_scale;
        float ss[2][2] = {};
        #pragma unroll
        for (int mt = 0; mt < 2; ++mt)
            #pragma unroll
            for (int nt = 0; nt < 4; ++nt) {
                int c = wn * 32 + nt * 8 + qc;
                float b0 = o_b[c], b1 = o_b[c + 1];
                float* d = acc[mt * 4 + nt]; float* h = hidden[mt * 4 + nt];
                float* qv = query[mt * 4 + nt];
                h[0] = d[0] + b0 + qs * qv[0]; h[1] = d[1] + b1 + qs * qv[1];
                h[2] = d[2] + b0 + qs * qv[2]; h[3] = d[3] + b1 + qs * qv[3];
                ss[mt][0] += h[0] * h[0] + h[1] * h[1];
                ss[mt][1] += h[2] * h[2] + h[3] * h[3];
            }
        #pragma unroll
        for (int mt = 0; mt < 2; ++mt)
            #pragma unroll
            for (int rw = 0; rw < 2; ++rw) {
                float v = ss[mt][rw];
                v += __shfl_xor_sync(0xffffffffu, v, 1);
                v += __shfl_xor_sync(0xffffffffu, v, 2);
                if ((lane & 3) == 0)
                    red[(wm * 32 + mt * 16 + qr + rw * 8) * 4 + wn] = v;
            }
        __syncthreads();
        float rs_[2][2];
        #pragma unroll
        for (int mt = 0; mt < 2; ++mt)
            #pragma unroll
            for (int rw = 0; rw < 2; ++rw) {
                int r = wm * 32 + mt * 16 + qr + rw * 8;
                float s = red[r * 4] + red[r * 4 + 1] + red[r * 4 + 2] + red[r * 4 + 3];
                rs_[mt][rw] = rsqrtf(s * (1.0f / 128.0f) + 1e-6f);
            }
        #pragma unroll
        for (int mt = 0; mt < 2; ++mt)
            #pragma unroll
            for (int nt = 0; nt < 4; ++nt) {
                int r = wm * 32 + mt * 16 + qr, c = wn * 32 + nt * 8 + qc;
                float g0 = ffn_gamma[c], g1 = ffn_gamma[c + 1];
                float* h = hidden[mt * 4 + nt];
                stA(aHp, aLp, r, c, h[0] * rs_[mt][0] * g0, h[1] * rs_[mt][0] * g1);
                stA(aHp, aLp, r + 8, c, h[2] * rs_[mt][1] * g0, h[3] * rs_[mt][1] * g1);
            }
    }
    CP_WAIT();
    __syncthreads();

    // ---- G8: ffn gate -> park (K/V region dead) ----
    ZACC();
    gemm_sm<2, 4, 8>(aH, aL, wH, wL, wm * 32, wn * 32, PA, acc, lane);
    __syncthreads();
    cpa(wH, wt + 6 * 69632, 4352, tid, 512);
    #pragma unroll
    for (int mt = 0; mt < 2; ++mt)
        #pragma unroll
        for (int nt = 0; nt < 4; ++nt) {
            int r = wm * 32 + mt * 16 + qr, c = wn * 32 + nt * 8 + qc;
            float b0 = ffn_in_b[128 + c], b1 = ffn_in_b[129 + c];
            float* d = acc[mt * 4 + nt];
            *reinterpret_cast<float2*>(park + r * 132 + c) =
                make_float2(silu_f(d[0] + b0), silu_f(d[1] + b1));
            *reinterpret_cast<float2*>(park + (r + 8) * 132 + c) =
                make_float2(silu_f(d[2] + b0), silu_f(d[3] + b1));
        }
    CP_WAIT();
    __syncthreads();

    // ---- G9: ffn a; m2 = (a+b)*g -> A ----
    ZACC();
    gemm_sm<2, 4, 8>(aH, aL, wH, wL, wm * 32, wn * 32, PA, acc, lane);
    __syncthreads();
    cpa(wH, wt + 7 * 69632, 4352, tid, 512);
    #pragma unroll
    for (int mt = 0; mt < 2; ++mt)
        #pragma unroll
        for (int nt = 0; nt < 4; ++nt) {
            int r = wm * 32 + mt * 16 + qr, c = wn * 32 + nt * 8 + qc;
            float b0 = ffn_in_b[c], b1 = ffn_in_b[c + 1];
            float* d = acc[mt * 4 + nt];
            float2 ga = *reinterpret_cast<float2*>(park + r * 132 + c);
            float2 gb = *reinterpret_cast<float2*>(park + (r + 8) * 132 + c);
            stA(aHp, aLp, r, c, (d[0] + b0) * ga.x, (d[1] + b1) * ga.y);
            stA(aHp, aLp, r + 8, c, (d[2] + b0) * gb.x, (d[3] + b1) * gb.y);
        }
    CP_WAIT();
    __syncthreads();

    // ---- G10: ffn_out; out = d + b + hidden -> global ----
    ZACC();
    gemm_sm<2, 4, 8>(aH, aL, wH, wL, wm * 32, wn * 32, PA, acc, lane);
    {
        float* ob = out + ((size_t)b * C * T + t) * F + f0;
        #pragma unroll
        for (int mt = 0; mt < 2; ++mt)
            #pragma unroll
            for (int nt = 0; nt < 4; ++nt) {
                int r = wm * 32 + mt * 16 + qr, c = wn * 32 + nt * 8 + qc;
                float b0 = ffn_out_b[c], b1 = ffn_out_b[c + 1];
                float* d = acc[mt * 4 + nt]; float* h = hidden[mt * 4 + nt];
                ob[(size_t)c * (T * F) + r]           = d[0] + b0 + h[0];
                ob[(size_t)(c + 1) * (T * F) + r]     = d[1] + b1 + h[1];
                ob[(size_t)c * (T * F) + r + 8]       = d[2] + b0 + h[2];
                ob[(size_t)(c + 1) * (T * F) + r + 8] = d[3] + b1 + h[3];
            }
    }
    #undef ZACC
}

// ---------------------------------------------------------------------------
extern "C" void kernel_launch(void* const* d_in, const int* in_sizes, int n_in,
                              void* d_out, int out_size)
{
    const float* latent      = (const float*)d_in[0];
    const float* side        = (const float*)d_in[1];
    const float* basis       = (const float*)d_in[2];
    const float* lp_gamma    = (const float*)d_in[3];
    const float* lp_w        = (const float*)d_in[4];
    const float* lp_b        = (const float*)d_in[5];
    const float* qn_gamma    = (const float*)d_in[6];
    const float* qmlp_in_w   = (const float*)d_in[7];
    const float* qmlp_in_b   = (const float*)d_in[8];
    const float* qmlp_out_w  = (const float*)d_in[9];
    const float* qmlp_out_b  = (const float*)d_in[10];
    const float* q_w         = (const float*)d_in[11];
    const float* q_b         = (const float*)d_in[12];
    const float* k_w         = (const float*)d_in[13];
    const float* k_b         = (const float*)d_in[14];
    const float* v_w         = (const float*)d_in[15];
    const float* v_b         = (const float*)d_in[16];
    const float* o_w         = (const float*)d_in[17];
    const float* o_b         = (const float*)d_in[18];
    const float* ffn_gamma   = (const float*)d_in[19];
    const float* ffn_in_w    = (const float*)d_in[20];
    const float* ffn_in_b    = (const float*)d_in[21];
    const float* ffn_out_w   = (const float*)d_in[22];
    const float* ffn_out_b   = (const float*)d_in[23];
    const float* score_scale = (const float*)d_in[24];
    const float* prior_scale = (const float*)d_in[25];
    const float* qss         = (const float*)d_in[26];
    float* out = (float*)d_out;

    cudaFuncSetAttribute(latent_kernel, cudaFuncAttributeMaxDynamicSharedMemorySize, K1_SMEM_BYTES);
    cudaFuncSetAttribute(main_kernel,   cudaFuncAttributeMaxDynamicSharedMemorySize, K2_SMEM_BYTES);

    prep_kernel<<<11, 256>>>(qmlp_in_w, qmlp_out_w, q_w, o_w, ffn_in_w, ffn_out_w,
                             lp_w, k_w, v_w);

    latent_kernel<<<B * T, 256, K1_SMEM_BYTES>>>(
        latent, lp_gamma, lp_b, k_b, v_b);

    main_kernel<<<dim3(F / 128, T, B), 512, K2_SMEM_BYTES>>>(
        side, basis, qn_gamma,
        qmlp_in_b, qmlp_out_b, q_b, o_b,
        ffn_gamma, ffn_in_b, ffn_out_b,
        score_scale, prior_scale, qss, out);
}

// round 15
// speedup vs baseline: 3.4671x; 1.0107x over previous
#include <cuda_runtime.h>
#include <cuda_bf16.h>
#include <cstdint>
#include <math.h>

typedef unsigned long long ull;

static constexpr int B = 8, C = 128, T = 128, F = 512, K = 64;

// pre-converted bf16 hi/lo tiles (smem-identical layout)
// weights: 11 tiles x [hi 128x136][lo 128x136]
__device__ uint4 g_wt4[11 * 69632 / 16];
// K tiles: per frame [hi 64x136][lo 64x136] (rows = kidx, cols = c)
__device__ uint4 g_kt4[(size_t)1024 * 2176];
// V tiles: per frame [hi 128x72][lo 128x72] (rows = c, cols = kidx)
__device__ uint4 g_vt4[(size_t)1024 * 2304];

__device__ __forceinline__ float silu_f(float g) {
    float e = __expf(-g);
    return __fdividef(g, 1.0f + e);
}
__device__ __forceinline__ uint32_t smem_to_u32(const void* p) {
    uint32_t a;
    asm("{ .reg .u64 t; cvta.to.shared.u64 t, %1; cvt.u32.u64 %0, t; }" : "=r"(a) : "l"(p));
    return a;
}
__device__ __forceinline__ void ldsm4(uint32_t* r, uint32_t addr) {
    asm volatile("ldmatrix.sync.aligned.m8n8.x4.shared.b16 {%0,%1,%2,%3}, [%4];"
        : "=r"(r[0]), "=r"(r[1]), "=r"(r[2]), "=r"(r[3]) : "r"(addr));
}
__device__ __forceinline__ void mma16816(float* d, const uint32_t* a, const uint32_t* b) {
    asm volatile("mma.sync.aligned.m16n8k16.row.col.f32.bf16.bf16.f32 "
        "{%0,%1,%2,%3},{%4,%5,%6,%7},{%8,%9},{%0,%1,%2,%3};"
        : "+f"(d[0]), "+f"(d[1]), "+f"(d[2]), "+f"(d[3])
        : "r"(a[0]), "r"(a[1]), "r"(a[2]), "r"(a[3]), "r"(b[0]), "r"(b[1]));
}
__device__ __forceinline__ float bfh_f(float x) { return __bfloat162float(__float2bfloat16(x)); }
__device__ __forceinline__ uint32_t bf2(float lo, float hi) {
    uint32_t r;
    asm("cvt.rn.satfinite.bf16x2.f32 %0, %1, %2;" : "=r"(r) : "f"(hi), "f"(lo));
    return r;
}
// cp.async: nchunks 16B copies from global to smem, one commit group
__device__ __forceinline__ void cpa(uint32_t sdst, const void* gsrc, int nchunks,
                                    int start, int stride) {
    const char* gp = (const char*)gsrc;
    for (int i = start; i < nchunks; i += stride)
        asm volatile("cp.async.cg.shared.global [%0], [%1], 16;"
                     :: "r"(sdst + 16u * i), "l"(gp + 16 * i));
    asm volatile("cp.async.commit_group;" ::: "memory");
}
#define CP_WAIT() asm volatile("cp.async.wait_group 0;" ::: "memory")

static constexpr int PA = 272;   // bytes, 136 bf16
static constexpr int PV = 144;   // bytes, 72 bf16

__device__ __forceinline__ void stA(char* aHp, char* aLp, int r, int c, float x0, float x1) {
    float h0 = bfh_f(x0), h1 = bfh_f(x1);
    *reinterpret_cast<uint32_t*>(aHp + r * PA + c * 2) = bf2(h0, h1);
    *reinterpret_cast<uint32_t*>(aLp + r * PA + c * 2) = bf2(x0 - h0, x1 - h1);
}

// smem-A x smem-B bf16-split GEMM (3 passes), row.col, acc fp32
template <int MT, int NT, int KT>
__device__ __forceinline__ void gemm_sm(uint32_t aH, uint32_t aL, uint32_t bH, uint32_t bL,
                                        int mbase, int nbase, int pitchB,
                                        float (*acc)[4], int lane) {
    #pragma unroll
    for (int kt = 0; kt < KT; ++kt) {
        uint32_t ah[MT][4], al[MT][4];
        int q = lane >> 3;
        #pragma unroll
        for (int mt = 0; mt < MT; ++mt) {
            int row = mbase + mt * 16 + ((q & 1) << 3) + (lane & 7);
            uint32_t ad = (uint32_t)(row * PA + kt * 32 + ((q >> 1) << 4));
            ldsm4(ah[mt], aH + ad);
            ldsm4(al[mt], aL + ad);
        }
        uint32_t bh[NT / 2][4], bl[NT / 2][4];
        #pragma unroll
        for (int p = 0; p < NT / 2; ++p) {
            int row = nbase + p * 16 + ((lane >> 4) << 3) + (lane & 7);
            uint32_t bd = (uint32_t)(row * pitchB + kt * 32 + (((lane >> 3) & 1) << 4));
            ldsm4(bh[p], bH + bd);
            ldsm4(bl[p], bL + bd);
        }
        #pragma unroll
        for (int mt = 0; mt < MT; ++mt)
            #pragma unroll
            for (int nt = 0; nt < NT; ++nt) {
                float* d = acc[mt * NT + nt];
                uint32_t fh[2] = { bh[nt >> 1][(nt & 1) * 2], bh[nt >> 1][(nt & 1) * 2 + 1] };
                uint32_t fl[2] = { bl[nt >> 1][(nt & 1) * 2], bl[nt >> 1][(nt & 1) * 2 + 1] };
                mma16816(d, ah[mt], fh);
                mma16816(d, ah[mt], fl);
                mma16816(d, al[mt], fh);
            }
    }
}

// ===========================================================================
// Prep kernel — convert 11 weight tiles to bf16 hi/lo tile layout (once)
// ===========================================================================
__global__ void prep_kernel(
    const float* __restrict__ qmlp_in_w, const float* __restrict__ qmlp_out_w,
    const float* __restrict__ q_w,       const float* __restrict__ o_w,
    const float* __restrict__ ffn_in_w,  const float* __restrict__ ffn_out_w,
    const float* __restrict__ lp_w,      const float* __restrict__ k_w,
    const float* __restrict__ v_w)
{
    const int bid = blockIdx.x, tid = threadIdx.x;
    const float* src;
    switch (bid) {
        case 0: src = qmlp_in_w + 16384; break;
        case 1: src = qmlp_in_w; break;
        case 2: src = qmlp_out_w; break;
        case 3: src = q_w; break;
        case 4: src = o_w; break;
        case 5: src = ffn_in_w + 16384; break;
        case 6: src = ffn_in_w; break;
        case 7: src = ffn_out_w; break;
        case 8: src = lp_w; break;
        case 9: src = k_w; break;
        default: src = v_w; break;
    }
    __nv_bfloat16* dh = reinterpret_cast<__nv_bfloat16*>(g_wt4) + (size_t)bid * 34816;
    __nv_bfloat16* dl = dh + 17408;
    for (int i = tid; i < 128 * 32; i += 256) {
        int r = i >> 5, c4 = (i & 31) << 2;
        float4 w = *reinterpret_cast<const float4*>(src + r * 128 + c4);
        float h0 = bfh_f(w.x), h1 = bfh_f(w.y), h2 = bfh_f(w.z), h3 = bfh_f(w.w);
        *reinterpret_cast<uint32_t*>(dh + r * 136 + c4)     = bf2(h0, h1);
        *reinterpret_cast<uint32_t*>(dh + r * 136 + c4 + 2) = bf2(h2, h3);
        *reinterpret_cast<uint32_t*>(dl + r * 136 + c4)     = bf2(w.x - h0, w.y - h1);
        *reinterpret_cast<uint32_t*>(dl + r * 136 + c4 + 2) = bf2(w.z - h2, w.w - h3);
    }
}

// ===========================================================================
// Latent kernel — HMMA bf16-split, 256 threads (8 warps), 2 CTAs/SM.
// ===========================================================================
static constexpr int L_RED = 0;               // 1024 B
static constexpr int L_AH = 1024;
static constexpr int L_AL = L_AH + 17408;     // 18432
static constexpr int L_WH = L_AL + 17408;     // 35840
static constexpr int K1_SMEM_BYTES = L_WH + 69632;   // 105472

__global__ void __launch_bounds__(256, 2) latent_kernel(
    const float* __restrict__ latent, const float* __restrict__ lp_gamma,
    const float* __restrict__ lp_b,   const float* __restrict__ k_b,
    const float* __restrict__ v_b)
{
    extern __shared__ char smc[];
    float* red = reinterpret_cast<float*>(smc + L_RED);
    char *aHp = smc + L_AH, *aLp = smc + L_AL, *wHp = smc + L_WH;
    const uint32_t aH = smem_to_u32(aHp), aL = smem_to_u32(aLp);
    const uint32_t wH = smem_to_u32(wHp), wL = wH + 34816;

    const int tid = threadIdx.x, wid = tid >> 5, lane = tid & 31;
    const int wm = wid & 3, wn = wid >> 2;
    const int qr = lane >> 2, qc = (lane & 3) << 1;
    const int frame = blockIdx.x;
    const int b = frame / T, t = frame % T;
    const char* wt = reinterpret_cast<const char*>(g_wt4);

    cpa(wH, wt + 8 * 69632, 4352, tid, 256);   // lp_w

    // stage A = rmsnorm(latent)^T : row kp (0..63), cols c
    {
        const int kp = tid & 63, grp = tid >> 6, cb = grp * 32;
        float x[32];
        const float* sp = latent + ((size_t)(b * C + cb) * T + t) * K + kp;
        #pragma unroll 8
        for (int j = 0; j < 32; ++j) x[j] = sp[(size_t)j * (T * K)];
        float ss = 0;
        #pragma unroll
        for (int j = 0; j < 32; ++j) ss += x[j] * x[j];
        red[grp * 64 + kp] = ss;
        __syncthreads();
        float rs = rsqrtf((red[kp] + red[64 + kp] + red[128 + kp] + red[192 + kp]) * (1.0f / 128.0f) + 1e-6f);
        __syncthreads();
        #pragma unroll
        for (int j = 0; j < 32; j += 2)
            stA(aHp, aLp, kp, cb + j, x[j] * rs * lp_gamma[cb + j],
                x[j + 1] * rs * lp_gamma[cb + j + 1]);
    }
    CP_WAIT();
    __syncthreads();

    float acc[8][4];
    #define ZAC() do { _Pragma("unroll") for (int _i = 0; _i < 8; ++_i) { acc[_i][0]=0;acc[_i][1]=0;acc[_i][2]=0;acc[_i][3]=0; } } while(0)

    // G_lp
    ZAC();
    gemm_sm<1, 8, 8>(aH, aL, wH, wL, wm * 16, wn * 64, PA, acc, lane);
    __syncthreads();
    cpa(wH, wt + 9 * 69632, 4352, tid, 256);   // k_w
    #pragma unroll
    for (int nt = 0; nt < 8; ++nt) {
        int r = wm * 16 + qr, c = wn * 64 + nt * 8 + qc;
        float b0 = lp_b[c], b1 = lp_b[c + 1];
        float* d = acc[nt];
        stA(aHp, aLp, r, c, silu_f(d[0] + b0), silu_f(d[1] + b1));
        stA(aHp, aLp, r + 8, c, silu_f(d[2] + b0), silu_f(d[3] + b1));
    }
    CP_WAIT();
    __syncthreads();

    // G_k -> global K tile
    ZAC();
    gemm_sm<1, 8, 8>(aH, aL, wH, wL, wm * 16, wn * 64, PA, acc, lane);
    __syncthreads();
    cpa(wH, wt + 10 * 69632, 4352, tid, 256);  // v_w
    {
        __nv_bfloat16* ktg = reinterpret_cast<__nv_bfloat16*>(g_kt4) + (size_t)frame * 17408;
        #pragma unroll
        for (int nt = 0; nt < 8; ++nt) {
            int c = wn * 64 + nt * 8 + qc;
            float b0 = k_b[c], b1 = k_b[c + 1];
            float* d = acc[nt];
            #pragma unroll
            for (int rw = 0; rw < 2; ++rw) {
                int r = wm * 16 + qr + rw * 8;
                float v0 = d[2 * rw] + b0, v1 = d[2 * rw + 1] + b1;
                float h0 = bfh_f(v0), h1 = bfh_f(v1);
                *reinterpret_cast<uint32_t*>(ktg + (size_t)r * 136 + c) = bf2(h0, h1);
                *reinterpret_cast<uint32_t*>(ktg + 8704 + (size_t)r * 136 + c) = bf2(v0 - h0, v1 - h1);
            }
        }
    }
    CP_WAIT();
    __syncthreads();

    // G_v -> global V tile transposed [c][kidx]
    ZAC();
    gemm_sm<1, 8, 8>(aH, aL, wH, wL, wm * 16, wn * 64, PA, acc, lane);
    {
        __nv_bfloat16* vtg = reinterpret_cast<__nv_bfloat16*>(g_vt4) + (size_t)frame * 18432;
        #pragma unroll
        for (int nt = 0; nt < 8; ++nt) {
            int c = wn * 64 + nt * 8 + qc;
            float b0 = v_b[c], b1 = v_b[c + 1];
            float* d = acc[nt];
            #pragma unroll
            for (int rw = 0; rw < 2; ++rw) {
                int r = wm * 16 + qr + rw * 8;
                float v0 = d[2 * rw] + b0, v1 = d[2 * rw + 1] + b1;
                float h0 = bfh_f(v0), h1 = bfh_f(v1);
                vtg[(size_t)c * 72 + r]       = __float2bfloat16(h0);
                vtg[(size_t)(c + 1) * 72 + r] = __float2bfloat16(h1);
                vtg[9216 + (size_t)c * 72 + r]       = __float2bfloat16(v0 - h0);
                vtg[9216 + (size_t)(c + 1) * 72 + r] = __float2bfloat16(v1 - h1);
            }
        }
    }
    #undef ZAC
}

// ===========================================================================
// Main kernel — HMMA bf16-split, 512 threads, cp.async staging.
// ===========================================================================
static constexpr int SRED = 0;                 // 2048 B
static constexpr int SA_H = 2048;
static constexpr int SA_L = SA_H + 34816;
static constexpr int SW_H = SA_L + 34816;
static constexpr int SK_H = SW_H + 69632;      // K hi then lo
static constexpr int SV_H = SK_H + 34816;      // V hi then lo
static constexpr int K2_SMEM_BYTES = SV_H + 36864;   // 212992

__global__ void __launch_bounds__(512, 1) main_kernel(
    const float* __restrict__ side,      const float* __restrict__ basis,
    const float* __restrict__ qn_gamma,
    const float* __restrict__ qmlp_in_b, const float* __restrict__ qmlp_out_b,
    const float* __restrict__ q_b,       const float* __restrict__ o_b,
    const float* __restrict__ ffn_gamma, const float* __restrict__ ffn_in_b,
    const float* __restrict__ ffn_out_b,
    const float* __restrict__ score_scale, const float* __restrict__ prior_scale,
    const float* __restrict__ query_skip_scale,
    float* __restrict__ out)
{
    extern __shared__ char smc[];
    float* red = reinterpret_cast<float*>(smc + SRED);
    char *aHp = smc + SA_H, *aLp = smc + SA_L, *wHp = smc + SW_H;
    char *kHp = smc + SK_H, *vHp = smc + SV_H;
    const uint32_t aH = smem_to_u32(aHp), aL = smem_to_u32(aLp);
    const uint32_t wH = smem_to_u32(wHp), wL = wH + 34816;
    const uint32_t kH = smem_to_u32(kHp), kL = kH + 17408;
    const uint32_t vH = smem_to_u32(vHp), vL = vH + 18432;

    const int tid = threadIdx.x, wid = tid >> 5, lane = tid & 31;
    const int wm = wid & 3, wn = wid >> 2;
    const int qr = lane >> 2, qc = (lane & 3) << 1;
    const int fc = blockIdx.x, t = blockIdx.y, b = blockIdx.z;
    const int f0 = fc * 128;
    const int frame = b * T + t;
    const char* wt = reinterpret_cast<const char*>(g_wt4);

    cpa(kH, reinterpret_cast<const char*>(g_kt4) + (size_t)frame * 34816, 2176, tid, 512);
    cpa(vH, reinterpret_cast<const char*>(g_vt4) + (size_t)frame * 36864, 2304, tid, 512);
    cpa(wH, wt, 4352, tid, 512);

    // initial A: side chunk rmsnorm
    {
        const int wg = tid >> 7, f = tid & 127, cb = wg * 32;
        float x[32];
        const float* sp = side + ((size_t)b * C * T + t) * F + f0 + f;
        #pragma unroll 8
        for (int j = 0; j < 32; ++j) x[j] = sp[(size_t)(cb + j) * (T * F)];
        float ss = 0;
        #pragma unroll
        for (int j = 0; j < 32; ++j) ss += x[j] * x[j];
        red[wg * 128 + f] = ss;
        __syncthreads();
        float rs = rsqrtf((red[f] + red[128 + f] + red[256 + f] + red[384 + f]) * (1.0f / 128.0f) + 1e-6f);
        __syncthreads();
        #pragma unroll
        for (int j = 0; j < 32; j += 2)
            stA(aHp, aLp, f, cb + j, x[j] * rs * qn_gamma[cb + j],
                x[j + 1] * rs * qn_gamma[cb + j + 1]);
    }
    CP_WAIT();
    __syncthreads();

    float query[8][4], hidden[8][4];
    float acc[8][4];
    #define ZACC() do { _Pragma("unroll") for (int _i = 0; _i < 8; ++_i) { acc[_i][0]=0;acc[_i][1]=0;acc[_i][2]=0;acc[_i][3]=0; } } while(0)

    // ---- G1: qmlp gate (kept in regs g1) ----
    ZACC();
    gemm_sm<2, 4, 8>(aH, aL, wH, wL, wm * 32, wn * 32, PA, acc, lane);
    __syncthreads();
    cpa(wH, wt + 1 * 69632, 4352, tid, 512);
    float g1[8][4];
    #pragma unroll
    for (int mt = 0; mt < 2; ++mt)
        #pragma unroll
        for (int nt = 0; nt < 4; ++nt) {
            int c = wn * 32 + nt * 8 + qc;
            float b0 = qmlp_in_b[128 + c], b1 = qmlp_in_b[129 + c];
            float* d = acc[mt * 4 + nt]; float* g = g1[mt * 4 + nt];
            g[0] = silu_f(d[0] + b0); g[1] = silu_f(d[1] + b1);
            g[2] = silu_f(d[2] + b0); g[3] = silu_f(d[3] + b1);
        }
    CP_WAIT();
    __syncthreads();

    // ---- G2: qmlp a; m -> A ----
    ZACC();
    gemm_sm<2, 4, 8>(aH, aL, wH, wL, wm * 32, wn * 32, PA, acc, lane);
    __syncthreads();
    cpa(wH, wt + 2 * 69632, 4352, tid, 512);
    #pragma unroll
    for (int mt = 0; mt < 2; ++mt)
        #pragma unroll
        for (int nt = 0; nt < 4; ++nt) {
            int r = wm * 32 + mt * 16 + qr, c = wn * 32 + nt * 8 + qc;
            float b0 = qmlp_in_b[c], b1 = qmlp_in_b[c + 1];
            float* d = acc[mt * 4 + nt]; float* g = g1[mt * 4 + nt];
            stA(aHp, aLp, r, c, (d[0] + b0) * g[0], (d[1] + b1) * g[1]);
            stA(aHp, aLp, r + 8, c, (d[2] + b0) * g[2], (d[3] + b1) * g[3]);
        }
    CP_WAIT();
    __syncthreads();

    // ---- G3: qmlp_out -> query_h (regs + A) ----
    ZACC();
    gemm_sm<2, 4, 8>(aH, aL, wH, wL, wm * 32, wn * 32, PA, acc, lane);
    __syncthreads();
    cpa(wH, wt + 3 * 69632, 4352, tid, 512);
    #pragma unroll
    for (int mt = 0; mt < 2; ++mt)
        #pragma unroll
        for (int nt = 0; nt < 4; ++nt) {
            int r = wm * 32 + mt * 16 + qr, c = wn * 32 + nt * 8 + qc;
            float b0 = qmlp_out_b[c], b1 = qmlp_out_b[c + 1];
            float* d = acc[mt * 4 + nt]; float* qv = query[mt * 4 + nt];
            qv[0] = d[0] + b0; qv[1] = d[1] + b1; qv[2] = d[2] + b0; qv[3] = d[3] + b1;
            stA(aHp, aLp, r, c, qv[0], qv[1]);
            stA(aHp, aLp, r + 8, c, qv[2], qv[3]);
        }
    CP_WAIT();
    __syncthreads();

    // ---- G4: q projection -> A ----
    ZACC();
    gemm_sm<2, 4, 8>(aH, aL, wH, wL, wm * 32, wn * 32, PA, acc, lane);
    __syncthreads();
    cpa(wH, wt + 4 * 69632, 4352, tid, 512);   // o_w, awaited after G6
    #pragma unroll
    for (int mt = 0; mt < 2; ++mt)
        #pragma unroll
        for (int nt = 0; nt < 4; ++nt) {
            int r = wm * 32 + mt * 16 + qr, c = wn * 32 + nt * 8 + qc;
            float b0 = q_b[c], b1 = q_b[c + 1];
            float* d = acc[mt * 4 + nt];
            stA(aHp, aLp, r, c, d[0] + b0, d[1] + b1);
            stA(aHp, aLp, r + 8, c, d[2] + b0, d[3] + b1);
        }
    __syncthreads();

    // ---- G5: scores + softmax, ALL 16 warps ----
    // warp w: rows 16*(w&7), k-half 32*(w>>3)  (MT=1, NT=4)
    {
        const int rw8 = wid & 7, kh = wid >> 3;
        float sacc[4][4];
        #pragma unroll
        for (int i = 0; i < 4; ++i) { sacc[i][0]=0;sacc[i][1]=0;sacc[i][2]=0;sacc[i][3]=0; }
        gemm_sm<1, 4, 8>(aH, aL, kH, kL, rw8 * 16, kh * 32, PA, sacc, lane);
        const float ssc = *score_scale, psc = *prior_scale;
        const int rA = rw8 * 16 + qr, rB = rA + 8;
        const int fgA = f0 + rA, fgB = f0 + rB;
        float p0[8], p1[8];
        #pragma unroll
        for (int nt = 0; nt < 4; ++nt) {
            int k0 = kh * 32 + nt * 8 + qc;
            p0[nt * 2 + 0] = sacc[nt][0] * ssc + basis[(size_t)k0 * F + fgA] * psc;
            p0[nt * 2 + 1] = sacc[nt][1] * ssc + basis[(size_t)(k0 + 1) * F + fgA] * psc;
            p1[nt * 2 + 0] = sacc[nt][2] * ssc + basis[(size_t)k0 * F + fgB] * psc;
            p1[nt * 2 + 1] = sacc[nt][3] * ssc + basis[(size_t)(k0 + 1) * F + fgB] * psc;
        }
        float m0 = p0[0], m1 = p1[0];
        #pragma unroll
        for (int i = 1; i < 8; ++i) { m0 = fmaxf(m0, p0[i]); m1 = fmaxf(m1, p1[i]); }
        m0 = fmaxf(m0, __shfl_xor_sync(0xffffffffu, m0, 1));
        m0 = fmaxf(m0, __shfl_xor_sync(0xffffffffu, m0, 2));
        m1 = fmaxf(m1, __shfl_xor_sync(0xffffffffu, m1, 1));
        m1 = fmaxf(m1, __shfl_xor_sync(0xffffffffu, m1, 2));
        if ((lane & 3) == 0) { red[rA * 2 + kh] = m0; red[rB * 2 + kh] = m1; }
        __syncthreads();
        m0 = fmaxf(red[rA * 2], red[rA * 2 + 1]);
        m1 = fmaxf(red[rB * 2], red[rB * 2 + 1]);
        float s0 = 0, s1 = 0;
        #pragma unroll
        for (int i = 0; i < 8; ++i) {
            p0[i] = __expf(p0[i] - m0); s0 += p0[i];
            p1[i] = __expf(p1[i] - m1); s1 += p1[i];
        }
        s0 += __shfl_xor_sync(0xffffffffu, s0, 1); s0 += __shfl_xor_sync(0xffffffffu, s0, 2);
        s1 += __shfl_xor_sync(0xffffffffu, s1, 1); s1 += __shfl_xor_sync(0xffffffffu, s1, 2);
        if ((lane & 3) == 0) { red[256 + rA * 2 + kh] = s0; red[256 + rB * 2 + kh] = s1; }
        __syncthreads();
        float i0 = __frcp_rn(red[256 + rA * 2] + red[256 + rA * 2 + 1]);
        float i1 = __frcp_rn(red[256 + rB * 2] + red[256 + rB * 2 + 1]);
        #pragma unroll
        for (int nt = 0; nt < 4; ++nt) {
            int c = kh * 32 + nt * 8 + qc;
            stA(aHp, aLp, rA, c, p0[2 * nt] * i0, p0[2 * nt + 1] * i0);
            stA(aHp, aLp, rB, c, p1[2 * nt] * i1, p1[2 * nt + 1] * i1);
        }
    }
    __syncthreads();

    // ---- G6: attended = P @ V ----
    ZACC();
    gemm_sm<2, 4, 4>(aH, aL, vH, vL, wm * 32, wn * 32, PV, acc, lane);
    __syncthreads();
    #pragma unroll
    for (int mt = 0; mt < 2; ++mt)
        #pragma unroll
        for (int nt = 0; nt < 4; ++nt) {
            int r = wm * 32 + mt * 16 + qr, c = wn * 32 + nt * 8 + qc;
            float* d = acc[mt * 4 + nt];
            stA(aHp, aLp, r, c, d[0], d[1]);
            stA(aHp, aLp, r + 8, c, d[2], d[3]);
        }
    CP_WAIT();   // o_w landed
    __syncthreads();

    // ---- G7: o_w; hidden = d + o_b + qss*query; rmsnorm -> A ----
    ZACC();
    gemm_sm<2, 4, 8>(aH, aL, wH, wL, wm * 32, wn * 32, PA, acc, lane);
    __syncthreads();
    cpa(wH, wt + 5 * 69632, 4352, tid, 512);
    {
        const float qs = *query_skip_scale;
        float ss[2][2] = {};
        #pragma unroll
        for (int mt = 0; mt < 2; ++mt)
            #pragma unroll
            for (int nt = 0; nt < 4; ++nt) {
                int c = wn * 32 + nt * 8 + qc;
                float b0 = o_b[c], b1 = o_b[c + 1];
                float* d = acc[mt * 4 + nt]; float* h = hidden[mt * 4 + nt];
                float* qv = query[mt * 4 + nt];
                h[0] = d[0] + b0 + qs * qv[0]; h[1] = d[1] + b1 + qs * qv[1];
                h[2] = d[2] + b0 + qs * qv[2]; h[3] = d[3] + b1 + qs * qv[3];
                ss[mt][0] += h[0] * h[0] + h[1] * h[1];
                ss[mt][1] += h[2] * h[2] + h[3] * h[3];
            }
        #pragma unroll
        for (int mt = 0; mt < 2; ++mt)
            #pragma unroll
            for (int rw = 0; rw < 2; ++rw) {
                float v = ss[mt][rw];
                v += __shfl_xor_sync(0xffffffffu, v, 1);
                v += __shfl_xor_sync(0xffffffffu, v, 2);
                if ((lane & 3) == 0)
                    red[(wm * 32 + mt * 16 + qr + rw * 8) * 4 + wn] = v;
            }
        __syncthreads();
        float rs_[2][2];
        #pragma unroll
        for (int mt = 0; mt < 2; ++mt)
            #pragma unroll
            for (int rw = 0; rw < 2; ++rw) {
                int r = wm * 32 + mt * 16 + qr + rw * 8;
                float s = red[r * 4] + red[r * 4 + 1] + red[r * 4 + 2] + red[r * 4 + 3];
                rs_[mt][rw] = rsqrtf(s * (1.0f / 128.0f) + 1e-6f);
            }
        #pragma unroll
        for (int mt = 0; mt < 2; ++mt)
            #pragma unroll
            for (int nt = 0; nt < 4; ++nt) {
                int r = wm * 32 + mt * 16 + qr, c = wn * 32 + nt * 8 + qc;
                float g0 = ffn_gamma[c], g1 = ffn_gamma[c + 1];
                float* h = hidden[mt * 4 + nt];
                stA(aHp, aLp, r, c, h[0] * rs_[mt][0] * g0, h[1] * rs_[mt][0] * g1);
                stA(aHp, aLp, r + 8, c, h[2] * rs_[mt][1] * g0, h[3] * rs_[mt][1] * g1);
            }
    }
    CP_WAIT();
    __syncthreads();

    // ---- G8: ffn gate -> regs (g1 reused) ----
    ZACC();
    gemm_sm<2, 4, 8>(aH, aL, wH, wL, wm * 32, wn * 32, PA, acc, lane);
    __syncthreads();
    cpa(wH, wt + 6 * 69632, 4352, tid, 512);
    #pragma unroll
    for (int mt = 0; mt < 2; ++mt)
        #pragma unroll
        for (int nt = 0; nt < 4; ++nt) {
            int c = wn * 32 + nt * 8 + qc;
            float b0 = ffn_in_b[128 + c], b1 = ffn_in_b[129 + c];
            float* d = acc[mt * 4 + nt]; float* g = g1[mt * 4 + nt];
            g[0] = silu_f(d[0] + b0); g[1] = silu_f(d[1] + b1);
            g[2] = silu_f(d[2] + b0); g[3] = silu_f(d[3] + b1);
        }
    CP_WAIT();
    __syncthreads();

    // ---- G9: ffn a; m2 = (a+b)*g -> A ----
    ZACC();
    gemm_sm<2, 4, 8>(aH, aL, wH, wL, wm * 32, wn * 32, PA, acc, lane);
    __syncthreads();
    cpa(wH, wt + 7 * 69632, 4352, tid, 512);
    #pragma unroll
    for (int mt = 0; mt < 2; ++mt)
        #pragma unroll
        for (int nt = 0; nt < 4; ++nt) {
            int r = wm * 32 + mt * 16 + qr, c = wn * 32 + nt * 8 + qc;
            float b0 = ffn_in_b[c], b1 = ffn_in_b[c + 1];
            float* d = acc[mt * 4 + nt]; float* g = g1[mt * 4 + nt];
            stA(aHp, aLp, r, c, (d[0] + b0) * g[0], (d[1] + b1) * g[1]);
            stA(aHp, aLp, r + 8, c, (d[2] + b0) * g[2], (d[3] + b1) * g[3]);
        }
    CP_WAIT();
    __syncthreads();

    // ---- G10: ffn_out; out = d + b + hidden -> global ----
    ZACC();
    gemm_sm<2, 4, 8>(aH, aL, wH, wL, wm * 32, wn * 32, PA, acc, lane);
    {
        float* ob = out + ((size_t)b * C * T + t) * F + f0;
        #pragma unroll
        for (int mt = 0; mt < 2; ++mt)
            #pragma unroll
            for (int nt = 0; nt < 4; ++nt) {
                int r = wm * 32 + mt * 16 + qr, c = wn * 32 + nt * 8 + qc;
                float b0 = ffn_out_b[c], b1 = ffn_out_b[c + 1];
                float* d = acc[mt * 4 + nt]; float* h = hidden[mt * 4 + nt];
                ob[(size_t)c * (T * F) + r]           = d[0] + b0 + h[0];
                ob[(size_t)(c + 1) * (T * F) + r]     = d[1] + b1 + h[1];
                ob[(size_t)c * (T * F) + r + 8]       = d[2] + b0 + h[2];
                ob[(size_t)(c + 1) * (T * F) + r + 8] = d[3] + b1 + h[3];
            }
    }
    #undef ZACC
}

// ---------------------------------------------------------------------------
extern "C" void kernel_launch(void* const* d_in, const int* in_sizes, int n_in,
                              void* d_out, int out_size)
{
    const float* latent      = (const float*)d_in[0];
    const float* side        = (const float*)d_in[1];
    const float* basis       = (const float*)d_in[2];
    const float* lp_gamma    = (const float*)d_in[3];
    const float* lp_w        = (const float*)d_in[4];
    const float* lp_b        = (const float*)d_in[5];
    const float* qn_gamma    = (const float*)d_in[6];
    const float* qmlp_in_w   = (const float*)d_in[7];
    const float* qmlp_in_b   = (const float*)d_in[8];
    const float* qmlp_out_w  = (const float*)d_in[9];
    const float* qmlp_out_b  = (const float*)d_in[10];
    const float* q_w         = (const float*)d_in[11];
    const float* q_b         = (const float*)d_in[12];
    const float* k_w         = (const float*)d_in[13];
    const float* k_b         = (const float*)d_in[14];
    const float* v_w         = (const float*)d_in[15];
    const float* v_b         = (const float*)d_in[16];
    const float* o_w         = (const float*)d_in[17];
    const float* o_b         = (const float*)d_in[18];
    const float* ffn_gamma   = (const float*)d_in[19];
    const float* ffn_in_w    = (const float*)d_in[20];
    const float* ffn_in_b    = (const float*)d_in[21];
    const float* ffn_out_w   = (const float*)d_in[22];
    const float* ffn_out_b   = (const float*)d_in[23];
    const float* score_scale = (const float*)d_in[24];
    const float* prior_scale = (const float*)d_in[25];
    const float* qss         = (const float*)d_in[26];
    float* out = (float*)d_out;

    cudaFuncSetAttribute(latent_kernel, cudaFuncAttributeMaxDynamicSharedMemorySize, K1_SMEM_BYTES);
    cudaFuncSetAttribute(main_kernel,   cudaFuncAttributeMaxDynamicSharedMemorySize, K2_SMEM_BYTES);

    prep_kernel<<<11, 256>>>(qmlp_in_w, qmlp_out_w, q_w, o_w, ffn_in_w, ffn_out_w,
                             lp_w, k_w, v_w);

    latent_kernel<<<B * T, 256, K1_SMEM_BYTES>>>(
        latent, lp_gamma, lp_b, k_b, v_b);

    main_kernel<<<dim3(F / 128, T, B), 512, K2_SMEM_BYTES>>>(
        side, basis, qn_gamma,
        qmlp_in_b, qmlp_out_b, q_b, o_b,
        ffn_gamma, ffn_in_b, ffn_out_b,
        score_scale, prior_scale, qss, out);
}